// round 6
// baseline (speedup 1.0000x reference)
#include <cuda_runtime.h>
#include <cuda_bf16.h>
#include <math.h>

// ---------------- problem constants ----------------
#define BB   16
#define NN   2048
#define DD   1024
#define HH   8
#define DHD  64
#define II   512           // H*DH
#define LQ   64
#define SSQ  2112          // N + L
#define NDEPTH 6
#define FFD  4096

typedef __nv_bfloat16 bf16;

// ---------------- scratch ----------------
__device__ bf16 g_xh[(size_t)BB * NN * DD];
__device__ bf16 g_xl[(size_t)BB * NN * DD];
__device__ bf16 g_lnlh[BB * LQ * DD],  g_lnll[BB * LQ * DD];
__device__ bf16 g_lnfh[BB * LQ * DD],  g_lnfl[BB * LQ * DD];
__device__ bf16 g_atth[BB * LQ * II],  g_attl[BB * LQ * II];
__device__ bf16 g_hfh [BB * LQ * FFD], g_hfl [BB * LQ * FFD];
__device__ bf16 g_wqh [DD * II],       g_wql [DD * II];
__device__ bf16 g_wkvh[DD * 2 * II],   g_wkvl[DD * 2 * II];
__device__ bf16 g_wkvph[DD * 2 * II],  g_wkvpl[DD * 2 * II];
__device__ bf16 g_woh [II * DD],       g_wol [II * DD];
__device__ bf16 g_w1h [DD * FFD],      g_w1l [DD * FFD];
__device__ bf16 g_w2h [FFD * DD],      g_w2l [FFD * DD];
__device__ float g_lat[BB * LQ * DD];
__device__ float g_q  [BB * LQ * II];
__device__ float g_k  [(size_t)BB * HH * SSQ * DHD];
__device__ float g_v  [(size_t)BB * HH * SSQ * DHD];
__device__ float g_biaskv[2 * II];

// ---------------- helpers ----------------
__device__ __forceinline__ unsigned pack2(float x, float y)
{
    bf16 hx = __float2bfloat16_rn(x);
    bf16 hy = __float2bfloat16_rn(y);
    return (unsigned)__bfloat16_as_ushort(hx) | ((unsigned)__bfloat16_as_ushort(hy) << 16);
}
__device__ __forceinline__ void split4(float4 v, uint2& hi, uint2& lo)
{
    float hx = __bfloat162float(__float2bfloat16_rn(v.x));
    float hy = __bfloat162float(__float2bfloat16_rn(v.y));
    float hz = __bfloat162float(__float2bfloat16_rn(v.z));
    float hw = __bfloat162float(__float2bfloat16_rn(v.w));
    hi = make_uint2(pack2(v.x, v.y), pack2(v.z, v.w));
    lo = make_uint2(pack2(v.x - hx, v.y - hy), pack2(v.z - hz, v.w - hw));
}

// ---------------- LayerNorm (fp32 out, final layer) ----------------
__global__ __launch_bounds__(256) void ln_kernel(const float* __restrict__ in,
                                                 float* __restrict__ out,
                                                 const float* __restrict__ w,
                                                 const float* __restrict__ b)
{
    int row = blockIdx.x;
    int tid = threadIdx.x;
    const float4 xv = *(const float4*)(in + (size_t)row * DD + tid * 4);
    float s  = xv.x + xv.y + xv.z + xv.w;
    float ss = xv.x * xv.x + xv.y * xv.y + xv.z * xv.z + xv.w * xv.w;
    #pragma unroll
    for (int o = 16; o; o >>= 1) {
        s  += __shfl_xor_sync(0xffffffffu, s,  o);
        ss += __shfl_xor_sync(0xffffffffu, ss, o);
    }
    __shared__ float red[16];
    int wid = tid >> 5;
    if ((tid & 31) == 0) { red[wid] = s; red[wid + 8] = ss; }
    __syncthreads();
    s = 0.f; ss = 0.f;
    #pragma unroll
    for (int i = 0; i < 8; i++) { s += red[i]; ss += red[i + 8]; }
    float mu   = s * (1.f / DD);
    float var  = ss * (1.f / DD) - mu * mu;
    float rstd = rsqrtf(var + 1e-5f);
    float4 o4;
    o4.x = (xv.x - mu) * rstd; o4.y = (xv.y - mu) * rstd;
    o4.z = (xv.z - mu) * rstd; o4.w = (xv.w - mu) * rstd;
    const float4 wv = *(const float4*)(w + tid * 4);
    const float4 bv = *(const float4*)(b + tid * 4);
    o4.x = o4.x * wv.x + bv.x; o4.y = o4.y * wv.y + bv.y;
    o4.z = o4.z * wv.z + bv.z; o4.w = o4.w * wv.w + bv.w;
    *(float4*)(out + (size_t)row * DD + tid * 4) = o4;
}

// ---------------- LayerNorm -> split bf16 hi/lo ----------------
__global__ __launch_bounds__(256) void ln_split_kernel(const float* __restrict__ in,
                                                       bf16* __restrict__ hi,
                                                       bf16* __restrict__ lo,
                                                       const float* __restrict__ w,
                                                       const float* __restrict__ b)
{
    int row = blockIdx.x;
    int tid = threadIdx.x;
    const float4 xv = *(const float4*)(in + (size_t)row * DD + tid * 4);
    float s  = xv.x + xv.y + xv.z + xv.w;
    float ss = xv.x * xv.x + xv.y * xv.y + xv.z * xv.z + xv.w * xv.w;
    #pragma unroll
    for (int o = 16; o; o >>= 1) {
        s  += __shfl_xor_sync(0xffffffffu, s,  o);
        ss += __shfl_xor_sync(0xffffffffu, ss, o);
    }
    __shared__ float red[16];
    int wid = tid >> 5;
    if ((tid & 31) == 0) { red[wid] = s; red[wid + 8] = ss; }
    __syncthreads();
    s = 0.f; ss = 0.f;
    #pragma unroll
    for (int i = 0; i < 8; i++) { s += red[i]; ss += red[i + 8]; }
    float mu   = s * (1.f / DD);
    float var  = ss * (1.f / DD) - mu * mu;
    float rstd = rsqrtf(var + 1e-5f);
    float4 o4;
    o4.x = (xv.x - mu) * rstd; o4.y = (xv.y - mu) * rstd;
    o4.z = (xv.z - mu) * rstd; o4.w = (xv.w - mu) * rstd;
    if (w) {
        const float4 wv = *(const float4*)(w + tid * 4);
        const float4 bv = *(const float4*)(b + tid * 4);
        o4.x = o4.x * wv.x + bv.x; o4.y = o4.y * wv.y + bv.y;
        o4.z = o4.z * wv.z + bv.z; o4.w = o4.w * wv.w + bv.w;
    }
    uint2 h, l;
    split4(o4, h, l);
    *(uint2*)(hi + (size_t)row * DD + tid * 4) = h;
    *(uint2*)(lo + (size_t)row * DD + tid * 4) = l;
}

// ---------------- generic split (weights), optional per-row(1024) scale ------
__global__ __launch_bounds__(256) void split_kernel(const float* __restrict__ in,
                                                    const float* __restrict__ rowscale,
                                                    bf16* __restrict__ hi,
                                                    bf16* __restrict__ lo)
{
    int idx = (blockIdx.x * 256 + threadIdx.x) * 4;
    float4 v = *(const float4*)(in + idx);
    if (rowscale) {
        float sc = rowscale[idx >> 10];
        v.x *= sc; v.y *= sc; v.z *= sc; v.w *= sc;
    }
    uint2 h, l;
    split4(v, h, l);
    *(uint2*)(hi + idx) = h;
    *(uint2*)(lo + idx) = l;
}

// ---------------- lat init ----------------
__global__ void init_lat_kernel(const float* __restrict__ latents, float* __restrict__ lat)
{
    int idx = blockIdx.x * 256 + threadIdx.x;
    lat[idx] = latents[idx & (LQ * DD - 1)];
}

// ---------------- biaskv[j] = sum_d ln_m_b[d] * Wkv[d][j] ----------------
__global__ void bias_kv_kernel(const float* __restrict__ Wkv, const float* __restrict__ lnb,
                               float* __restrict__ bias)
{
    int j  = blockIdx.x * 32 + (threadIdx.x & 31);
    int dc = threadIdx.x >> 5;
    float a = 0.f;
    int d0 = dc * 128;
    #pragma unroll 8
    for (int d = d0; d < d0 + 128; d++) a += lnb[d] * Wkv[(size_t)d * 1024 + j];
    __shared__ float red[8][32];
    red[dc][threadIdx.x & 31] = a;
    __syncthreads();
    if (dc == 0) {
        float s = 0.f;
        #pragma unroll
        for (int i = 0; i < 8; i++) s += red[i][threadIdx.x & 31];
        bias[j] = s;
    }
}

// ================= bf16x3 split-precision tensor-core GEMM =================
enum { EPI_NONE = 0, EPI_ADD = 1, EPI_GELU = 2, EPI_KV = 3 };

#define GBK 32
#define AST 40
#define BST 136

__device__ __forceinline__ void mma16816(float* d, const unsigned* a, const unsigned* b)
{
    asm volatile(
        "mma.sync.aligned.m16n8k16.row.col.f32.bf16.bf16.f32 "
        "{%0,%1,%2,%3}, {%4,%5,%6,%7}, {%8,%9}, {%0,%1,%2,%3};\n"
        : "+f"(d[0]), "+f"(d[1]), "+f"(d[2]), "+f"(d[3])
        : "r"(a[0]), "r"(a[1]), "r"(a[2]), "r"(a[3]), "r"(b[0]), "r"(b[1]));
}
__device__ __forceinline__ void ldsm4(unsigned* r, unsigned addr)
{
    asm volatile("ldmatrix.sync.aligned.m8n8.x4.shared.b16 {%0,%1,%2,%3}, [%4];\n"
                 : "=r"(r[0]), "=r"(r[1]), "=r"(r[2]), "=r"(r[3]) : "r"(addr));
}
__device__ __forceinline__ void ldsm4t(unsigned* r, unsigned addr)
{
    asm volatile("ldmatrix.sync.aligned.m8n8.x4.trans.shared.b16 {%0,%1,%2,%3}, [%4];\n"
                 : "=r"(r[0]), "=r"(r[1]), "=r"(r[2]), "=r"(r[3]) : "r"(addr));
}
__device__ __forceinline__ void cpasync16(unsigned s, const void* g)
{
    asm volatile("cp.async.cg.shared.global [%0], [%1], 16;\n" :: "r"(s), "l"(g));
}
#define CP_COMMIT() asm volatile("cp.async.commit_group;\n")
#define CP_WAIT1()  asm volatile("cp.async.wait_group 1;\n")

template<int TM>
__global__ __launch_bounds__(256) void gemm_bf16(
    const bf16* __restrict__ Ahi, const bf16* __restrict__ Alo,
    const bf16* __restrict__ Bhi, const bf16* __restrict__ Blo,
    float* __restrict__ C, int M, int N, int K, int epi,
    const float* __restrict__ bias,
    float* __restrict__ Kout, float* __restrict__ Vout, int rowsPerB, int sBase,
    bf16* __restrict__ OutHi, bf16* __restrict__ OutLo)
{
    constexpr int WM16   = TM / 32;
    constexpr int A_EL   = TM * AST;
    constexpr int B_EL   = GBK * BST;
    constexpr int STAGE  = 2 * A_EL + 2 * B_EL;      // elements per stage
    extern __shared__ __align__(16) bf16 smg[];
    unsigned base = (unsigned)__cvta_generic_to_shared(smg);

    int tid  = threadIdx.x;
    int lane = tid & 31;
    int warp = tid >> 5;
    int wm = warp & 1, wn = warp >> 1;
    int row0 = blockIdx.y * TM;
    int col0 = blockIdx.x << 7;
    int lr = (lane & 7) + (((lane >> 3) & 1) << 3);
    int lc = (lane >> 4) << 3;

    float acc[WM16][4][4];
    #pragma unroll
    for (int i = 0; i < WM16; i++)
        #pragma unroll
        for (int j = 0; j < 4; j++)
            #pragma unroll
            for (int t = 0; t < 4; t++) acc[i][j][t] = 0.f;

    auto load_stage = [&](int kt, int buf) {
        unsigned sb = base + (unsigned)buf * STAGE * 2;
        constexpr int ACH = (TM * 4) / 256;
        #pragma unroll
        for (int p = 0; p < 2; p++) {
            const bf16* Ap = p ? Alo : Ahi;
            unsigned so = sb + (unsigned)p * A_EL * 2;
            #pragma unroll
            for (int i = 0; i < ACH; i++) {
                int chunk = tid + i * 256;
                int r = chunk >> 2, c16 = chunk & 3;
                cpasync16(so + (unsigned)(r * AST + c16 * 8) * 2,
                          Ap + (size_t)(row0 + r) * K + kt + c16 * 8);
            }
        }
        #pragma unroll
        for (int p = 0; p < 2; p++) {
            const bf16* Bp = p ? Blo : Bhi;
            unsigned so = sb + (unsigned)(2 * A_EL + p * B_EL) * 2;
            #pragma unroll
            for (int i = 0; i < 2; i++) {
                int chunk = tid + i * 256;
                int r = chunk >> 4, cc = (chunk & 15) * 8;
                cpasync16(so + (unsigned)(r * BST + cc) * 2,
                          Bp + (size_t)(kt + r) * N + col0 + cc);
            }
        }
    };

    int NK = K / GBK;
    load_stage(0, 0);   CP_COMMIT();
    load_stage(GBK, 1); CP_COMMIT();

    for (int it = 0; it < NK; it++) {
        CP_WAIT1();
        __syncthreads();
        unsigned sb  = base + (unsigned)(it & 1) * STAGE * 2;
        unsigned aHi = sb;
        unsigned aLo = sb + A_EL * 2;
        unsigned bHi = sb + 2 * A_EL * 2;
        unsigned bLo = bHi + B_EL * 2;

        #pragma unroll
        for (int k16 = 0; k16 < GBK; k16 += 16) {
            unsigned ah[WM16][4], al[WM16][4], bh[2][4], bl[2][4];
            #pragma unroll
            for (int mi = 0; mi < WM16; mi++) {
                unsigned off = (unsigned)((wm * (TM / 2) + mi * 16 + lr) * AST + k16 + lc) * 2;
                ldsm4(ah[mi], aHi + off);
                ldsm4(al[mi], aLo + off);
            }
            #pragma unroll
            for (int ni = 0; ni < 2; ni++) {
                unsigned off = (unsigned)((k16 + lr) * BST + wn * 32 + ni * 16 + lc) * 2;
                ldsm4t(bh[ni], bHi + off);
                ldsm4t(bl[ni], bLo + off);
            }
            #pragma unroll
            for (int mi = 0; mi < WM16; mi++) {
                #pragma unroll
                for (int nj = 0; nj < 4; nj++) {
                    int ni = nj >> 1, p = nj & 1;
                    mma16816(acc[mi][nj], ah[mi], &bh[ni][2 * p]);
                    mma16816(acc[mi][nj], ah[mi], &bl[ni][2 * p]);
                    mma16816(acc[mi][nj], al[mi], &bh[ni][2 * p]);
                }
            }
        }
        __syncthreads();
        if (it + 2 < NK) load_stage((it + 2) * GBK, it & 1);
        CP_COMMIT();
    }

    // ---------------- epilogue ----------------
    int rbase = row0 + wm * (TM / 2) + (lane >> 2);
    int cbase = col0 + wn * 32 + (lane & 3) * 2;
    #pragma unroll
    for (int mi = 0; mi < WM16; mi++) {
        #pragma unroll
        for (int nj = 0; nj < 4; nj++) {
            #pragma unroll
            for (int half = 0; half < 2; half++) {
                int r = rbase + mi * 16 + half * 8;
                int c = cbase + nj * 8;
                float v0 = acc[mi][nj][half * 2 + 0];
                float v1 = acc[mi][nj][half * 2 + 1];
                if (epi == EPI_KV) {
                    if (bias) { v0 += bias[c]; v1 += bias[c + 1]; }
                    int bb = r / rowsPerB;
                    int s  = sBase + (r - bb * rowsPerB);
                    float* dst;
                    if (c < II)
                        dst = Kout + (((size_t)bb * HH + (c >> 6)) * SSQ + s) * DHD + (c & 63);
                    else
                        dst = Vout + (((size_t)bb * HH + ((c - II) >> 6)) * SSQ + s) * DHD + ((c - II) & 63);
                    dst[0] = v0; dst[1] = v1;
                } else if (epi == EPI_GELU) {
                    float h0 = 0.5f * v0 * (1.f + erff(v0 * 0.70710678118654752f));
                    float h1 = 0.5f * v1 * (1.f + erff(v1 * 0.70710678118654752f));
                    float t0 = __bfloat162float(__float2bfloat16_rn(h0));
                    float t1 = __bfloat162float(__float2bfloat16_rn(h1));
                    *(unsigned*)(OutHi + (size_t)r * N + c) = pack2(h0, h1);
                    *(unsigned*)(OutLo + (size_t)r * N + c) = pack2(h0 - t0, h1 - t1);
                } else {
                    float* dst = C + (size_t)r * N + c;
                    if (epi == EPI_ADD) { v0 += dst[0]; v1 += dst[1]; }
                    dst[0] = v0; dst[1] = v1;
                }
            }
        }
    }
}

// ---------------- fused flash attention v2 ----------------
// 2 CTAs per (b,h): each handles 32 q rows, all S. K stored d-major in smem.
#define AT2  68
#define ATTN_SMEM (((size_t)(32 + 64 + 64 + 32) * AT2 + 64) * 4)

__global__ __launch_bounds__(256) void attn_kernel(
    const float* __restrict__ q, const float* __restrict__ kg, const float* __restrict__ vg,
    const int* __restrict__ mask, bf16* __restrict__ attHi, bf16* __restrict__ attLo)
{
    extern __shared__ float sm[];
    float* qs  = sm;                              // [32][AT2] : q rows, d cols
    float* kT  = sm + 32 * AT2;                   // [64][AT2] : kT[d][s]
    float* vs  = sm + (32 + 64) * AT2;            // [64][AT2] : v rows s, d cols
    float* ps  = sm + (32 + 128) * AT2;           // [32][AT2]
    float* msk = sm + (32 + 160) * AT2;           // [64]

    int blk = blockIdx.x;
    int bh = blk >> 1, half = blk & 1;
    int b = bh >> 3, h = bh & 7;
    int tid = threadIdx.x;
    int qr = tid >> 3;                 // 0..31
    int j0 = (tid & 7) * 8;            // this thread's 8 score cols / 8 dh cols

    const float* qbase = q + ((size_t)(b * LQ) + half * 32) * II + h * DHD;
    for (int idx = tid; idx < 32 * 16; idx += 256) {
        int r = idx >> 4, d4 = (idx & 15) << 2;
        *(float4*)&qs[r * AT2 + d4] = *(const float4*)&qbase[(size_t)r * II + d4];
    }

    float acc[8];
    #pragma unroll
    for (int i = 0; i < 8; i++) acc[i] = 0.f;
    float m = -1e30f, l = 0.f;

    const float* kb = kg + ((size_t)b * HH + h) * SSQ * DHD;
    const float* vb = vg + ((size_t)b * HH + h) * SSQ * DHD;
    const int* mrow = mask + b * NN;

    for (int t = 0; t < SSQ / 64; t++) {
        int s0 = t * 64;
        __syncthreads();
        for (int idx = tid; idx < 64 * 16; idx += 256) {
            int r = idx >> 4, d4 = (idx & 15) << 2;
            float4 k4 = *(const float4*)&kb[(size_t)(s0 + r) * DHD + d4];
            kT[(d4 + 0) * AT2 + r] = k4.x;
            kT[(d4 + 1) * AT2 + r] = k4.y;
            kT[(d4 + 2) * AT2 + r] = k4.z;
            kT[(d4 + 3) * AT2 + r] = k4.w;
            *(float4*)&vs[r * AT2 + d4] = *(const float4*)&vb[(size_t)(s0 + r) * DHD + d4];
        }
        if (tid < 64) {
            int s = s0 + tid;
            msk[tid] = (s < NN && mrow[s] == 1) ? 1.f : 0.f;
        }
        __syncthreads();

        float sc[8];
        #pragma unroll
        for (int j = 0; j < 8; j++) sc[j] = 0.f;
        const float* qrow = &qs[qr * AT2];
        #pragma unroll 8
        for (int d = 0; d < 64; d++) {
            float qv = qrow[d];
            float4 kA = *(const float4*)&kT[d * AT2 + j0];
            float4 kB = *(const float4*)&kT[d * AT2 + j0 + 4];
            sc[0] += qv * kA.x; sc[1] += qv * kA.y; sc[2] += qv * kA.z; sc[3] += qv * kA.w;
            sc[4] += qv * kB.x; sc[5] += qv * kB.y; sc[6] += qv * kB.z; sc[7] += qv * kB.w;
        }
        float tmax = -1e30f;
        #pragma unroll
        for (int j = 0; j < 8; j++) {
            float s = sc[j] * 0.125f;
            if (msk[j0 + j] != 0.f) s = -1e30f;
            sc[j] = s;
            tmax = fmaxf(tmax, s);
        }
        tmax = fmaxf(tmax, __shfl_xor_sync(0xffffffffu, tmax, 1));
        tmax = fmaxf(tmax, __shfl_xor_sync(0xffffffffu, tmax, 2));
        tmax = fmaxf(tmax, __shfl_xor_sync(0xffffffffu, tmax, 4));
        float mnew = fmaxf(m, tmax);
        float corr = __expf(m - mnew);
        float psum = 0.f;
        #pragma unroll
        for (int j = 0; j < 8; j++) {
            float p = __expf(sc[j] - mnew);
            ps[qr * AT2 + j0 + j] = p;
            psum += p;
        }
        psum += __shfl_xor_sync(0xffffffffu, psum, 1);
        psum += __shfl_xor_sync(0xffffffffu, psum, 2);
        psum += __shfl_xor_sync(0xffffffffu, psum, 4);
        l = l * corr + psum;
        m = mnew;
        #pragma unroll
        for (int i = 0; i < 8; i++) acc[i] *= corr;
        __syncwarp();

        #pragma unroll 4
        for (int j = 0; j < 64; j++) {
            float p = ps[qr * AT2 + j];
            float4 v0 = *(const float4*)&vs[j * AT2 + j0];
            float4 v1 = *(const float4*)&vs[j * AT2 + j0 + 4];
            acc[0] += p * v0.x; acc[1] += p * v0.y; acc[2] += p * v0.z; acc[3] += p * v0.w;
            acc[4] += p * v1.x; acc[5] += p * v1.y; acc[6] += p * v1.z; acc[7] += p * v1.w;
        }
    }

    float invl = 1.f / l;
    size_t obase = ((size_t)(b * LQ) + half * 32 + qr) * II + h * DHD + j0;
    float o[8];
    #pragma unroll
    for (int i = 0; i < 8; i++) o[i] = acc[i] * invl;
    float th[8];
    #pragma unroll
    for (int i = 0; i < 8; i++) th[i] = __bfloat162float(__float2bfloat16_rn(o[i]));
    *(uint2*)(attHi + obase)     = make_uint2(pack2(o[0], o[1]), pack2(o[2], o[3]));
    *(uint2*)(attHi + obase + 4) = make_uint2(pack2(o[4], o[5]), pack2(o[6], o[7]));
    *(uint2*)(attLo + obase)     = make_uint2(pack2(o[0]-th[0], o[1]-th[1]), pack2(o[2]-th[2], o[3]-th[3]));
    *(uint2*)(attLo + obase + 4) = make_uint2(pack2(o[4]-th[4], o[5]-th[5]), pack2(o[6]-th[6], o[7]-th[7]));
}

// ---------------- host orchestration ----------------
#define SMEM128 ((2 * (2 * 128 * AST + 2 * GBK * BST)) * 2)
#define SMEM64  ((2 * (2 * 64  * AST + 2 * GBK * BST)) * 2)

extern "C" void kernel_launch(void* const* d_in, const int* in_sizes, int n_in,
                              void* d_out, int out_size)
{
    (void)in_sizes; (void)n_in; (void)out_size;
    const float* x        = (const float*)d_in[0];
    const int*   mask     = (const int*)  d_in[1];
    const float* latents  = (const float*)d_in[2];
    const float* ln_m_w   = (const float*)d_in[3];
    const float* ln_m_b   = (const float*)d_in[4];
    const float* ln_l_w   = (const float*)d_in[5];
    const float* ln_l_b   = (const float*)d_in[6];
    const float* Wq       = (const float*)d_in[7];
    const float* Wkv      = (const float*)d_in[8];
    const float* Wo       = (const float*)d_in[9];
    const float* ff_ln_w  = (const float*)d_in[10];
    const float* ff_ln_b  = (const float*)d_in[11];
    const float* W1       = (const float*)d_in[12];
    const float* W2       = (const float*)d_in[13];
    const float* norm_w   = (const float*)d_in[14];
    const float* norm_b   = (const float*)d_in[15];
    float* out = (float*)d_out;

    bf16 *xh, *xl, *lnlh, *lnll, *lnfh, *lnfl, *atth, *attl, *hfh, *hfl;
    bf16 *wqh, *wql, *wkvh, *wkvl, *wkvph, *wkvpl, *woh, *wol, *w1h, *w1l, *w2h, *w2l;
    float *lat, *qb, *kb, *vb, *biaskv;
    cudaGetSymbolAddress((void**)&xh, g_xh);     cudaGetSymbolAddress((void**)&xl, g_xl);
    cudaGetSymbolAddress((void**)&lnlh, g_lnlh); cudaGetSymbolAddress((void**)&lnll, g_lnll);
    cudaGetSymbolAddress((void**)&lnfh, g_lnfh); cudaGetSymbolAddress((void**)&lnfl, g_lnfl);
    cudaGetSymbolAddress((void**)&atth, g_atth); cudaGetSymbolAddress((void**)&attl, g_attl);
    cudaGetSymbolAddress((void**)&hfh, g_hfh);   cudaGetSymbolAddress((void**)&hfl, g_hfl);
    cudaGetSymbolAddress((void**)&wqh, g_wqh);   cudaGetSymbolAddress((void**)&wql, g_wql);
    cudaGetSymbolAddress((void**)&wkvh, g_wkvh); cudaGetSymbolAddress((void**)&wkvl, g_wkvl);
    cudaGetSymbolAddress((void**)&wkvph, g_wkvph); cudaGetSymbolAddress((void**)&wkvpl, g_wkvpl);
    cudaGetSymbolAddress((void**)&woh, g_woh);   cudaGetSymbolAddress((void**)&wol, g_wol);
    cudaGetSymbolAddress((void**)&w1h, g_w1h);   cudaGetSymbolAddress((void**)&w1l, g_w1l);
    cudaGetSymbolAddress((void**)&w2h, g_w2h);   cudaGetSymbolAddress((void**)&w2l, g_w2l);
    cudaGetSymbolAddress((void**)&lat, g_lat);
    cudaGetSymbolAddress((void**)&qb, g_q);
    cudaGetSymbolAddress((void**)&kb, g_k);
    cudaGetSymbolAddress((void**)&vb, g_v);
    cudaGetSymbolAddress((void**)&biaskv, g_biaskv);

    cudaFuncSetAttribute(gemm_bf16<128>, cudaFuncAttributeMaxDynamicSharedMemorySize, SMEM128);
    cudaFuncSetAttribute(gemm_bf16<64>,  cudaFuncAttributeMaxDynamicSharedMemorySize, SMEM64);
    cudaFuncSetAttribute(attn_kernel,    cudaFuncAttributeMaxDynamicSharedMemorySize, (int)ATTN_SMEM);

    // layer-invariant
    ln_split_kernel<<<BB * NN, 256>>>(x, xh, xl, nullptr, nullptr);
    init_lat_kernel<<<BB * LQ * DD / 256, 256>>>(latents, lat);

    for (int i = 0; i < NDEPTH; i++) {
        const float* Wkv_i = Wkv + (size_t)i * DD * 2 * II;
        const float* Wq_i  = Wq  + (size_t)i * DD * II;
        const float* Wo_i  = Wo  + (size_t)i * II * DD;
        const float* W1_i  = W1  + (size_t)i * DD * FFD;
        const float* W2_i  = W2  + (size_t)i * FFD * DD;

        // weight conversions
        split_kernel<<<DD * 2 * II / 1024, 256>>>(Wkv_i, ln_m_w + i * DD, wkvph, wkvpl);
        split_kernel<<<DD * 2 * II / 1024, 256>>>(Wkv_i, nullptr, wkvh, wkvl);
        split_kernel<<<DD * II / 1024, 256>>>(Wq_i, nullptr, wqh, wql);
        split_kernel<<<II * DD / 1024, 256>>>(Wo_i, nullptr, woh, wol);
        split_kernel<<<DD * FFD / 1024, 256>>>(W1_i, nullptr, w1h, w1l);
        split_kernel<<<FFD * DD / 1024, 256>>>(W2_i, nullptr, w2h, w2l);
        bias_kv_kernel<<<32, 256>>>(Wkv_i, ln_m_b + i * DD, biaskv);

        ln_split_kernel<<<BB * LQ, 256>>>(lat, lnlh, lnll, ln_l_w + i * DD, ln_l_b + i * DD);

        // q = lnl @ Wq  (fp32 out)
        gemm_bf16<64><<<dim3(II / 128, BB * LQ / 64), 256, SMEM64>>>(
            lnlh, lnll, wqh, wql, qb, BB * LQ, II, DD, EPI_NONE,
            nullptr, nullptr, nullptr, 0, 0, nullptr, nullptr);

        // kv (x part)
        gemm_bf16<128><<<dim3(2 * II / 128, BB * NN / 128), 256, SMEM128>>>(
            xh, xl, wkvph, wkvpl, nullptr, BB * NN, 2 * II, DD, EPI_KV,
            biaskv, kb, vb, NN, 0, nullptr, nullptr);

        // kv (latent part)
        gemm_bf16<64><<<dim3(2 * II / 128, BB * LQ / 64), 256, SMEM64>>>(
            lnlh, lnll, wkvh, wkvl, nullptr, BB * LQ, 2 * II, DD, EPI_KV,
            nullptr, kb, vb, LQ, NN, nullptr, nullptr);

        // attention -> split bf16
        attn_kernel<<<BB * HH * 2, 256, ATTN_SMEM>>>(qb, kb, vb, mask, atth, attl);

        // lat += att @ Wo
        gemm_bf16<64><<<dim3(DD / 128, BB * LQ / 64), 256, SMEM64>>>(
            atth, attl, woh, wol, lat, BB * LQ, DD, II, EPI_ADD,
            nullptr, nullptr, nullptr, 0, 0, nullptr, nullptr);

        // FF
        ln_split_kernel<<<BB * LQ, 256>>>(lat, lnfh, lnfl, ff_ln_w + i * DD, ff_ln_b + i * DD);
        gemm_bf16<64><<<dim3(FFD / 128, BB * LQ / 64), 256, SMEM64>>>(
            lnfh, lnfl, w1h, w1l, nullptr, BB * LQ, FFD, DD, EPI_GELU,
            nullptr, nullptr, nullptr, 0, 0, hfh, hfl);
        gemm_bf16<64><<<dim3(DD / 128, BB * LQ / 64), 256, SMEM64>>>(
            hfh, hfl, w2h, w2l, lat, BB * LQ, DD, FFD, EPI_ADD,
            nullptr, nullptr, nullptr, 0, 0, nullptr, nullptr);
    }

    ln_kernel<<<BB * LQ, 256>>>(lat, out, norm_w, norm_b);
}

// round 7
// speedup vs baseline: 1.0200x; 1.0200x over previous
#include <cuda_runtime.h>
#include <cuda_bf16.h>
#include <math.h>

// ---------------- problem constants ----------------
#define BB   16
#define NN   2048
#define DD   1024
#define HH   8
#define DHD  64
#define II   512           // H*DH
#define LQ   64
#define SSQ  2112          // N + L
#define NDEPTH 6
#define FFD  4096
#define NQKV 1536          // II + 2*II

typedef __nv_bfloat16 bf16;

// ---------------- scratch ----------------
__device__ bf16 g_xh[(size_t)BB * NN * DD];
__device__ bf16 g_xl[(size_t)BB * NN * DD];
__device__ bf16 g_lnlh[BB * LQ * DD],  g_lnll[BB * LQ * DD];
__device__ bf16 g_lnfh[BB * LQ * DD],  g_lnfl[BB * LQ * DD];
__device__ bf16 g_atth[BB * LQ * II],  g_attl[BB * LQ * II];
__device__ bf16 g_hfh [BB * LQ * FFD], g_hfl [BB * LQ * FFD];
__device__ bf16 g_cmbh[DD * NQKV],     g_cmbl[DD * NQKV];   // [Wq | Wkv] per layer
__device__ bf16 g_wkvph[DD * 2 * II],  g_wkvpl[DD * 2 * II]; // ln_m_w-folded Wkv
__device__ bf16 g_woh [II * DD],       g_wol [II * DD];
__device__ bf16 g_w1h [DD * FFD],      g_w1l [DD * FFD];
__device__ bf16 g_w2h [FFD * DD],      g_w2l [FFD * DD];
__device__ float g_lat[BB * LQ * DD];
__device__ float g_q  [BB * LQ * II];
__device__ float g_k  [(size_t)BB * HH * SSQ * DHD];
__device__ float g_v  [(size_t)BB * HH * SSQ * DHD];
__device__ float g_biaskv[2 * II];

// ---------------- helpers ----------------
__device__ __forceinline__ unsigned pack2(float x, float y)
{
    bf16 hx = __float2bfloat16_rn(x);
    bf16 hy = __float2bfloat16_rn(y);
    return (unsigned)__bfloat16_as_ushort(hx) | ((unsigned)__bfloat16_as_ushort(hy) << 16);
}
__device__ __forceinline__ void split4(float4 v, uint2& hi, uint2& lo)
{
    float hx = __bfloat162float(__float2bfloat16_rn(v.x));
    float hy = __bfloat162float(__float2bfloat16_rn(v.y));
    float hz = __bfloat162float(__float2bfloat16_rn(v.z));
    float hw = __bfloat162float(__float2bfloat16_rn(v.w));
    hi = make_uint2(pack2(v.x, v.y), pack2(v.z, v.w));
    lo = make_uint2(pack2(v.x - hx, v.y - hy), pack2(v.z - hz, v.w - hw));
}

// ---------------- LayerNorm (fp32 out, final layer) ----------------
__global__ __launch_bounds__(256) void ln_kernel(const float* __restrict__ in,
                                                 float* __restrict__ out,
                                                 const float* __restrict__ w,
                                                 const float* __restrict__ b)
{
    int row = blockIdx.x;
    int tid = threadIdx.x;
    const float4 xv = *(const float4*)(in + (size_t)row * DD + tid * 4);
    float s  = xv.x + xv.y + xv.z + xv.w;
    float ss = xv.x * xv.x + xv.y * xv.y + xv.z * xv.z + xv.w * xv.w;
    #pragma unroll
    for (int o = 16; o; o >>= 1) {
        s  += __shfl_xor_sync(0xffffffffu, s,  o);
        ss += __shfl_xor_sync(0xffffffffu, ss, o);
    }
    __shared__ float red[16];
    int wid = tid >> 5;
    if ((tid & 31) == 0) { red[wid] = s; red[wid + 8] = ss; }
    __syncthreads();
    s = 0.f; ss = 0.f;
    #pragma unroll
    for (int i = 0; i < 8; i++) { s += red[i]; ss += red[i + 8]; }
    float mu   = s * (1.f / DD);
    float var  = ss * (1.f / DD) - mu * mu;
    float rstd = rsqrtf(var + 1e-5f);
    float4 o4;
    o4.x = (xv.x - mu) * rstd; o4.y = (xv.y - mu) * rstd;
    o4.z = (xv.z - mu) * rstd; o4.w = (xv.w - mu) * rstd;
    const float4 wv = *(const float4*)(w + tid * 4);
    const float4 bv = *(const float4*)(b + tid * 4);
    o4.x = o4.x * wv.x + bv.x; o4.y = o4.y * wv.y + bv.y;
    o4.z = o4.z * wv.z + bv.z; o4.w = o4.w * wv.w + bv.w;
    *(float4*)(out + (size_t)row * DD + tid * 4) = o4;
}

// ---------------- LayerNorm -> split bf16 hi/lo ----------------
__global__ __launch_bounds__(256) void ln_split_kernel(const float* __restrict__ in,
                                                       bf16* __restrict__ hi,
                                                       bf16* __restrict__ lo,
                                                       const float* __restrict__ w,
                                                       const float* __restrict__ b)
{
    int row = blockIdx.x;
    int tid = threadIdx.x;
    const float4 xv = *(const float4*)(in + (size_t)row * DD + tid * 4);
    float s  = xv.x + xv.y + xv.z + xv.w;
    float ss = xv.x * xv.x + xv.y * xv.y + xv.z * xv.z + xv.w * xv.w;
    #pragma unroll
    for (int o = 16; o; o >>= 1) {
        s  += __shfl_xor_sync(0xffffffffu, s,  o);
        ss += __shfl_xor_sync(0xffffffffu, ss, o);
    }
    __shared__ float red[16];
    int wid = tid >> 5;
    if ((tid & 31) == 0) { red[wid] = s; red[wid + 8] = ss; }
    __syncthreads();
    s = 0.f; ss = 0.f;
    #pragma unroll
    for (int i = 0; i < 8; i++) { s += red[i]; ss += red[i + 8]; }
    float mu   = s * (1.f / DD);
    float var  = ss * (1.f / DD) - mu * mu;
    float rstd = rsqrtf(var + 1e-5f);
    float4 o4;
    o4.x = (xv.x - mu) * rstd; o4.y = (xv.y - mu) * rstd;
    o4.z = (xv.z - mu) * rstd; o4.w = (xv.w - mu) * rstd;
    if (w) {
        const float4 wv = *(const float4*)(w + tid * 4);
        const float4 bv = *(const float4*)(b + tid * 4);
        o4.x = o4.x * wv.x + bv.x; o4.y = o4.y * wv.y + bv.y;
        o4.z = o4.z * wv.z + bv.z; o4.w = o4.w * wv.w + bv.w;
    }
    uint2 h, l;
    split4(o4, h, l);
    *(uint2*)(hi + (size_t)row * DD + tid * 4) = h;
    *(uint2*)(lo + (size_t)row * DD + tid * 4) = l;
}

// ---------------- generic split with src/dst geometry ----------------
// idx over src elements; row = idx / srcCols; col = idx % srcCols;
// dst offset = row * dstStride + dstOff + col
__global__ __launch_bounds__(256) void split_kernel(const float* __restrict__ in,
                                                    bf16* __restrict__ hi,
                                                    bf16* __restrict__ lo,
                                                    int srcColsLog2, int dstStride, int dstOff)
{
    int idx = (blockIdx.x * 256 + threadIdx.x) * 4;
    float4 v = *(const float4*)(in + idx);
    int row = idx >> srcColsLog2;
    int col = idx & ((1 << srcColsLog2) - 1);
    size_t d = (size_t)row * dstStride + dstOff + col;
    uint2 h, l;
    split4(v, h, l);
    *(uint2*)(hi + d) = h;
    *(uint2*)(lo + d) = l;
}

// ---------------- Wkv split: folded (hi/lo) + unfolded into combined ----------
__global__ __launch_bounds__(256) void split_wkv_kernel(const float* __restrict__ Wkv,
                                                        const float* __restrict__ lw,
                                                        bf16* __restrict__ fh, bf16* __restrict__ fl,
                                                        bf16* __restrict__ ch, bf16* __restrict__ cl)
{
    int idx = (blockIdx.x * 256 + threadIdx.x) * 4;      // over D*1024
    float4 v = *(const float4*)(Wkv + idx);
    int row = idx >> 10;
    int col = idx & 1023;
    uint2 h, l;
    split4(v, h, l);                                     // unfolded -> combined at off 512
    size_t d = (size_t)row * NQKV + II + col;
    *(uint2*)(ch + d) = h;
    *(uint2*)(cl + d) = l;
    float sc = lw[row];
    v.x *= sc; v.y *= sc; v.z *= sc; v.w *= sc;
    split4(v, h, l);                                     // folded
    *(uint2*)(fh + idx) = h;
    *(uint2*)(fl + idx) = l;
}

// ---------------- lat init ----------------
__global__ void init_lat_kernel(const float* __restrict__ latents, float* __restrict__ lat)
{
    int idx = blockIdx.x * 256 + threadIdx.x;
    lat[idx] = latents[idx & (LQ * DD - 1)];
}

// ---------------- biaskv[j] = sum_d ln_m_b[d] * Wkv[d][j] ----------------
__global__ __launch_bounds__(256) void bias_kv_kernel(const float* __restrict__ Wkv,
                                                      const float* __restrict__ lnb,
                                                      float* __restrict__ bias)
{
    // 128 blocks, 8 columns each; 32 d-chunks of 32
    int j  = blockIdx.x * 8 + (threadIdx.x & 7);
    int dc = threadIdx.x >> 3;                 // 0..31
    float a = 0.f;
    int d0 = dc * 32;
    #pragma unroll 8
    for (int d = d0; d < d0 + 32; d++) a += lnb[d] * Wkv[(size_t)d * 1024 + j];
    __shared__ float red[32][8];
    red[dc][threadIdx.x & 7] = a;
    __syncthreads();
    if (threadIdx.x < 8) {
        float s = 0.f;
        #pragma unroll
        for (int i = 0; i < 32; i++) s += red[i][threadIdx.x];
        bias[blockIdx.x * 8 + threadIdx.x] = s;
    }
}

// ================= bf16x3 split-precision tensor-core GEMM =================
enum { EPI_NONE = 0, EPI_ADD = 1, EPI_GELU = 2, EPI_KV = 3, EPI_QKV = 4 };

#define GBK 32
#define AST 40
#define BST 136

__device__ __forceinline__ void mma16816(float* d, const unsigned* a, const unsigned* b)
{
    asm volatile(
        "mma.sync.aligned.m16n8k16.row.col.f32.bf16.bf16.f32 "
        "{%0,%1,%2,%3}, {%4,%5,%6,%7}, {%8,%9}, {%0,%1,%2,%3};\n"
        : "+f"(d[0]), "+f"(d[1]), "+f"(d[2]), "+f"(d[3])
        : "r"(a[0]), "r"(a[1]), "r"(a[2]), "r"(a[3]), "r"(b[0]), "r"(b[1]));
}
__device__ __forceinline__ void ldsm4(unsigned* r, unsigned addr)
{
    asm volatile("ldmatrix.sync.aligned.m8n8.x4.shared.b16 {%0,%1,%2,%3}, [%4];\n"
                 : "=r"(r[0]), "=r"(r[1]), "=r"(r[2]), "=r"(r[3]) : "r"(addr));
}
__device__ __forceinline__ void ldsm4t(unsigned* r, unsigned addr)
{
    asm volatile("ldmatrix.sync.aligned.m8n8.x4.trans.shared.b16 {%0,%1,%2,%3}, [%4];\n"
                 : "=r"(r[0]), "=r"(r[1]), "=r"(r[2]), "=r"(r[3]) : "r"(addr));
}
__device__ __forceinline__ void cpasync16(unsigned s, const void* g)
{
    asm volatile("cp.async.cg.shared.global [%0], [%1], 16;\n" :: "r"(s), "l"(g));
}
#define CP_COMMIT() asm volatile("cp.async.commit_group;\n")
#define CP_WAIT1()  asm volatile("cp.async.wait_group 1;\n")

template<int TM, int NSTAGE>
__global__ __launch_bounds__(256, 2) void gemm_bf16(
    const bf16* __restrict__ Ahi, const bf16* __restrict__ Alo,
    const bf16* __restrict__ Bhi, const bf16* __restrict__ Blo,
    float* __restrict__ C, int M, int N, int K, int epi,
    const float* __restrict__ bias,
    float* __restrict__ Kout, float* __restrict__ Vout, int rowsPerB, int sBase,
    bf16* __restrict__ OutHi, bf16* __restrict__ OutLo)
{
    constexpr int WM16   = TM / 32;
    constexpr int A_EL   = TM * AST;
    constexpr int B_EL   = GBK * BST;
    constexpr int STAGE  = 2 * A_EL + 2 * B_EL;
    extern __shared__ __align__(16) bf16 smg[];
    unsigned base = (unsigned)__cvta_generic_to_shared(smg);

    int tid  = threadIdx.x;
    int lane = tid & 31;
    int warp = tid >> 5;
    int wm = warp & 1, wn = warp >> 1;
    int row0 = blockIdx.y * TM;
    int col0 = blockIdx.x << 7;
    int lr = (lane & 7) + (((lane >> 3) & 1) << 3);
    int lc = (lane >> 4) << 3;

    float acc[WM16][4][4];
    #pragma unroll
    for (int i = 0; i < WM16; i++)
        #pragma unroll
        for (int j = 0; j < 4; j++)
            #pragma unroll
            for (int t = 0; t < 4; t++) acc[i][j][t] = 0.f;

    auto load_stage = [&](int kt, int buf) {
        unsigned sb = base + (unsigned)buf * STAGE * 2;
        constexpr int ACH = (TM * 4) / 256;
        #pragma unroll
        for (int p = 0; p < 2; p++) {
            const bf16* Ap = p ? Alo : Ahi;
            unsigned so = sb + (unsigned)p * A_EL * 2;
            #pragma unroll
            for (int i = 0; i < ACH; i++) {
                int chunk = tid + i * 256;
                int r = chunk >> 2, c16 = chunk & 3;
                cpasync16(so + (unsigned)(r * AST + c16 * 8) * 2,
                          Ap + (size_t)(row0 + r) * K + kt + c16 * 8);
            }
        }
        #pragma unroll
        for (int p = 0; p < 2; p++) {
            const bf16* Bp = p ? Blo : Bhi;
            unsigned so = sb + (unsigned)(2 * A_EL + p * B_EL) * 2;
            #pragma unroll
            for (int i = 0; i < 2; i++) {
                int chunk = tid + i * 256;
                int r = chunk >> 4, cc = (chunk & 15) * 8;
                cpasync16(so + (unsigned)(r * BST + cc) * 2,
                          Bp + (size_t)(kt + r) * N + col0 + cc);
            }
        }
    };

    int NK = K / GBK;
    load_stage(0, 0);   CP_COMMIT();
    load_stage(GBK, 1); CP_COMMIT();

    for (int it = 0; it < NK; it++) {
        CP_WAIT1();
        __syncthreads();
        int buf = (NSTAGE == 2) ? (it & 1) : (it % 3);
        unsigned sb  = base + (unsigned)buf * STAGE * 2;
        unsigned aHi = sb;
        unsigned aLo = sb + A_EL * 2;
        unsigned bHi = sb + 2 * A_EL * 2;
        unsigned bLo = bHi + B_EL * 2;

        if (NSTAGE == 3) {
            // prefetch into buffer computed last iteration (safe past the barrier)
            if (it + 2 < NK) load_stage((it + 2) * GBK, (it + 2) % 3);
            CP_COMMIT();
        }

        #pragma unroll
        for (int k16 = 0; k16 < GBK; k16 += 16) {
            unsigned bh[2][4], bl[2][4];
            #pragma unroll
            for (int ni = 0; ni < 2; ni++) {
                unsigned off = (unsigned)((k16 + lr) * BST + wn * 32 + ni * 16 + lc) * 2;
                ldsm4t(bh[ni], bHi + off);
                ldsm4t(bl[ni], bLo + off);
            }
            #pragma unroll
            for (int mi = 0; mi < WM16; mi++) {
                unsigned ah[4], al[4];
                unsigned off = (unsigned)((wm * (TM / 2) + mi * 16 + lr) * AST + k16 + lc) * 2;
                ldsm4(ah, aHi + off);
                ldsm4(al, aLo + off);
                #pragma unroll
                for (int nj = 0; nj < 4; nj++) {
                    int ni = nj >> 1, p = nj & 1;
                    mma16816(acc[mi][nj], ah, &bh[ni][2 * p]);
                    mma16816(acc[mi][nj], ah, &bl[ni][2 * p]);
                    mma16816(acc[mi][nj], al, &bh[ni][2 * p]);
                }
            }
        }

        if (NSTAGE == 2) {
            __syncthreads();
            if (it + 2 < NK) load_stage((it + 2) * GBK, it & 1);
            CP_COMMIT();
        }
    }

    // ---------------- epilogue ----------------
    int rbase = row0 + wm * (TM / 2) + (lane >> 2);
    int cbase = col0 + wn * 32 + (lane & 3) * 2;
    #pragma unroll
    for (int mi = 0; mi < WM16; mi++) {
        #pragma unroll
        for (int nj = 0; nj < 4; nj++) {
            #pragma unroll
            for (int half = 0; half < 2; half++) {
                int r = rbase + mi * 16 + half * 8;
                int c = cbase + nj * 8;
                float v0 = acc[mi][nj][half * 2 + 0];
                float v1 = acc[mi][nj][half * 2 + 1];
                if (epi == EPI_KV) {
                    if (bias) { v0 += bias[c]; v1 += bias[c + 1]; }
                    int bb = r / rowsPerB;
                    int s  = sBase + (r - bb * rowsPerB);
                    float* dst;
                    if (c < II)
                        dst = Kout + (((size_t)bb * HH + (c >> 6)) * SSQ + s) * DHD + (c & 63);
                    else
                        dst = Vout + (((size_t)bb * HH + ((c - II) >> 6)) * SSQ + s) * DHD + ((c - II) & 63);
                    dst[0] = v0; dst[1] = v1;
                } else if (epi == EPI_QKV) {
                    if (c < II) {
                        float* dst = C + (size_t)r * II + c;
                        dst[0] = v0; dst[1] = v1;
                    } else {
                        int c2 = c - II;                   // 0..1023
                        int bb = r / rowsPerB;
                        int s  = sBase + (r - bb * rowsPerB);
                        float* dst;
                        if (c2 < II)
                            dst = Kout + (((size_t)bb * HH + (c2 >> 6)) * SSQ + s) * DHD + (c2 & 63);
                        else
                            dst = Vout + (((size_t)bb * HH + ((c2 - II) >> 6)) * SSQ + s) * DHD + ((c2 - II) & 63);
                        dst[0] = v0; dst[1] = v1;
                    }
                } else if (epi == EPI_GELU) {
                    float h0 = 0.5f * v0 * (1.f + erff(v0 * 0.70710678118654752f));
                    float h1 = 0.5f * v1 * (1.f + erff(v1 * 0.70710678118654752f));
                    float t0 = __bfloat162float(__float2bfloat16_rn(h0));
                    float t1 = __bfloat162float(__float2bfloat16_rn(h1));
                    *(unsigned*)(OutHi + (size_t)r * N + c) = pack2(h0, h1);
                    *(unsigned*)(OutLo + (size_t)r * N + c) = pack2(h0 - t0, h1 - t1);
                } else {
                    float* dst = C + (size_t)r * N + c;
                    if (epi == EPI_ADD) { v0 += dst[0]; v1 += dst[1]; }
                    dst[0] = v0; dst[1] = v1;
                }
            }
        }
    }
}

// ---------------- fused flash attention ----------------
#define AT2  68
#define ATTN_SMEM (((size_t)(32 + 64 + 64 + 32) * AT2 + 64) * 4)

__global__ __launch_bounds__(256) void attn_kernel(
    const float* __restrict__ q, const float* __restrict__ kg, const float* __restrict__ vg,
    const int* __restrict__ mask, bf16* __restrict__ attHi, bf16* __restrict__ attLo)
{
    extern __shared__ float sm[];
    float* qs  = sm;
    float* kT  = sm + 32 * AT2;
    float* vs  = sm + (32 + 64) * AT2;
    float* ps  = sm + (32 + 128) * AT2;
    float* msk = sm + (32 + 160) * AT2;

    int blk = blockIdx.x;
    int bh = blk >> 1, half = blk & 1;
    int b = bh >> 3, h = bh & 7;
    int tid = threadIdx.x;
    int qr = tid >> 3;
    int j0 = (tid & 7) * 8;

    const float* qbase = q + ((size_t)(b * LQ) + half * 32) * II + h * DHD;
    for (int idx = tid; idx < 32 * 16; idx += 256) {
        int r = idx >> 4, d4 = (idx & 15) << 2;
        *(float4*)&qs[r * AT2 + d4] = *(const float4*)&qbase[(size_t)r * II + d4];
    }

    float acc[8];
    #pragma unroll
    for (int i = 0; i < 8; i++) acc[i] = 0.f;
    float m = -1e30f, l = 0.f;

    const float* kb = kg + ((size_t)b * HH + h) * SSQ * DHD;
    const float* vb = vg + ((size_t)b * HH + h) * SSQ * DHD;
    const int* mrow = mask + b * NN;

    for (int t = 0; t < SSQ / 64; t++) {
        int s0 = t * 64;
        __syncthreads();
        for (int idx = tid; idx < 64 * 16; idx += 256) {
            int r = idx >> 4, d4 = (idx & 15) << 2;
            float4 k4 = *(const float4*)&kb[(size_t)(s0 + r) * DHD + d4];
            kT[(d4 + 0) * AT2 + r] = k4.x;
            kT[(d4 + 1) * AT2 + r] = k4.y;
            kT[(d4 + 2) * AT2 + r] = k4.z;
            kT[(d4 + 3) * AT2 + r] = k4.w;
            *(float4*)&vs[r * AT2 + d4] = *(const float4*)&vb[(size_t)(s0 + r) * DHD + d4];
        }
        if (tid < 64) {
            int s = s0 + tid;
            msk[tid] = (s < NN && mrow[s] == 1) ? 1.f : 0.f;
        }
        __syncthreads();

        float sc[8];
        #pragma unroll
        for (int j = 0; j < 8; j++) sc[j] = 0.f;
        const float* qrow = &qs[qr * AT2];
        #pragma unroll 8
        for (int d = 0; d < 64; d++) {
            float qv = qrow[d];
            float4 kA = *(const float4*)&kT[d * AT2 + j0];
            float4 kB = *(const float4*)&kT[d * AT2 + j0 + 4];
            sc[0] += qv * kA.x; sc[1] += qv * kA.y; sc[2] += qv * kA.z; sc[3] += qv * kA.w;
            sc[4] += qv * kB.x; sc[5] += qv * kB.y; sc[6] += qv * kB.z; sc[7] += qv * kB.w;
        }
        float tmax = -1e30f;
        #pragma unroll
        for (int j = 0; j < 8; j++) {
            float s = sc[j] * 0.125f;
            if (msk[j0 + j] != 0.f) s = -1e30f;
            sc[j] = s;
            tmax = fmaxf(tmax, s);
        }
        tmax = fmaxf(tmax, __shfl_xor_sync(0xffffffffu, tmax, 1));
        tmax = fmaxf(tmax, __shfl_xor_sync(0xffffffffu, tmax, 2));
        tmax = fmaxf(tmax, __shfl_xor_sync(0xffffffffu, tmax, 4));
        float mnew = fmaxf(m, tmax);
        float corr = __expf(m - mnew);
        float psum = 0.f;
        #pragma unroll
        for (int j = 0; j < 8; j++) {
            float p = __expf(sc[j] - mnew);
            ps[qr * AT2 + j0 + j] = p;
            psum += p;
        }
        psum += __shfl_xor_sync(0xffffffffu, psum, 1);
        psum += __shfl_xor_sync(0xffffffffu, psum, 2);
        psum += __shfl_xor_sync(0xffffffffu, psum, 4);
        l = l * corr + psum;
        m = mnew;
        #pragma unroll
        for (int i = 0; i < 8; i++) acc[i] *= corr;
        __syncwarp();

        #pragma unroll 4
        for (int j = 0; j < 64; j++) {
            float p = ps[qr * AT2 + j];
            float4 v0 = *(const float4*)&vs[j * AT2 + j0];
            float4 v1 = *(const float4*)&vs[j * AT2 + j0 + 4];
            acc[0] += p * v0.x; acc[1] += p * v0.y; acc[2] += p * v0.z; acc[3] += p * v0.w;
            acc[4] += p * v1.x; acc[5] += p * v1.y; acc[6] += p * v1.z; acc[7] += p * v1.w;
        }
    }

    float invl = 1.f / l;
    size_t obase = ((size_t)(b * LQ) + half * 32 + qr) * II + h * DHD + j0;
    float o[8];
    #pragma unroll
    for (int i = 0; i < 8; i++) o[i] = acc[i] * invl;
    float th[8];
    #pragma unroll
    for (int i = 0; i < 8; i++) th[i] = __bfloat162float(__float2bfloat16_rn(o[i]));
    *(uint2*)(attHi + obase)     = make_uint2(pack2(o[0], o[1]), pack2(o[2], o[3]));
    *(uint2*)(attHi + obase + 4) = make_uint2(pack2(o[4], o[5]), pack2(o[6], o[7]));
    *(uint2*)(attLo + obase)     = make_uint2(pack2(o[0]-th[0], o[1]-th[1]), pack2(o[2]-th[2], o[3]-th[3]));
    *(uint2*)(attLo + obase + 4) = make_uint2(pack2(o[4]-th[4], o[5]-th[5]), pack2(o[6]-th[6], o[7]-th[7]));
}

// ---------------- host orchestration ----------------
#define SMEM128 ((2 * (2 * 128 * AST + 2 * GBK * BST)) * 2)
#define SMEM64  ((3 * (2 * 64  * AST + 2 * GBK * BST)) * 2)

extern "C" void kernel_launch(void* const* d_in, const int* in_sizes, int n_in,
                              void* d_out, int out_size)
{
    (void)in_sizes; (void)n_in; (void)out_size;
    const float* x        = (const float*)d_in[0];
    const int*   mask     = (const int*)  d_in[1];
    const float* latents  = (const float*)d_in[2];
    const float* ln_m_w   = (const float*)d_in[3];
    const float* ln_m_b   = (const float*)d_in[4];
    const float* ln_l_w   = (const float*)d_in[5];
    const float* ln_l_b   = (const float*)d_in[6];
    const float* Wq       = (const float*)d_in[7];
    const float* Wkv      = (const float*)d_in[8];
    const float* Wo       = (const float*)d_in[9];
    const float* ff_ln_w  = (const float*)d_in[10];
    const float* ff_ln_b  = (const float*)d_in[11];
    const float* W1       = (const float*)d_in[12];
    const float* W2       = (const float*)d_in[13];
    const float* norm_w   = (const float*)d_in[14];
    const float* norm_b   = (const float*)d_in[15];
    float* out = (float*)d_out;

    bf16 *xh, *xl, *lnlh, *lnll, *lnfh, *lnfl, *atth, *attl, *hfh, *hfl;
    bf16 *cmbh, *cmbl, *wkvph, *wkvpl, *woh, *wol, *w1h, *w1l, *w2h, *w2l;
    float *lat, *qb, *kb, *vb, *biaskv;
    cudaGetSymbolAddress((void**)&xh, g_xh);     cudaGetSymbolAddress((void**)&xl, g_xl);
    cudaGetSymbolAddress((void**)&lnlh, g_lnlh); cudaGetSymbolAddress((void**)&lnll, g_lnll);
    cudaGetSymbolAddress((void**)&lnfh, g_lnfh); cudaGetSymbolAddress((void**)&lnfl, g_lnfl);
    cudaGetSymbolAddress((void**)&atth, g_atth); cudaGetSymbolAddress((void**)&attl, g_attl);
    cudaGetSymbolAddress((void**)&hfh, g_hfh);   cudaGetSymbolAddress((void**)&hfl, g_hfl);
    cudaGetSymbolAddress((void**)&cmbh, g_cmbh); cudaGetSymbolAddress((void**)&cmbl, g_cmbl);
    cudaGetSymbolAddress((void**)&wkvph, g_wkvph); cudaGetSymbolAddress((void**)&wkvpl, g_wkvpl);
    cudaGetSymbolAddress((void**)&woh, g_woh);   cudaGetSymbolAddress((void**)&wol, g_wol);
    cudaGetSymbolAddress((void**)&w1h, g_w1h);   cudaGetSymbolAddress((void**)&w1l, g_w1l);
    cudaGetSymbolAddress((void**)&w2h, g_w2h);   cudaGetSymbolAddress((void**)&w2l, g_w2l);
    cudaGetSymbolAddress((void**)&lat, g_lat);
    cudaGetSymbolAddress((void**)&qb, g_q);
    cudaGetSymbolAddress((void**)&kb, g_k);
    cudaGetSymbolAddress((void**)&vb, g_v);
    cudaGetSymbolAddress((void**)&biaskv, g_biaskv);

    cudaFuncSetAttribute((const void*)gemm_bf16<128,2>, cudaFuncAttributeMaxDynamicSharedMemorySize, SMEM128);
    cudaFuncSetAttribute((const void*)gemm_bf16<64,3>,  cudaFuncAttributeMaxDynamicSharedMemorySize, SMEM64);
    cudaFuncSetAttribute((const void*)attn_kernel,      cudaFuncAttributeMaxDynamicSharedMemorySize, (int)ATTN_SMEM);

    // layer-invariant
    ln_split_kernel<<<BB * NN, 256>>>(x, xh, xl, nullptr, nullptr);
    init_lat_kernel<<<BB * LQ * DD / 256, 256>>>(latents, lat);

    for (int i = 0; i < NDEPTH; i++) {
        const float* Wkv_i = Wkv + (size_t)i * DD * 2 * II;
        const float* Wq_i  = Wq  + (size_t)i * DD * II;
        const float* Wo_i  = Wo  + (size_t)i * II * DD;
        const float* W1_i  = W1  + (size_t)i * DD * FFD;
        const float* W2_i  = W2  + (size_t)i * FFD * DD;

        // weight conversions
        split_wkv_kernel<<<DD * 2 * II / 1024, 256>>>(Wkv_i, ln_m_w + i * DD,
                                                      wkvph, wkvpl, cmbh, cmbl);
        split_kernel<<<DD * II / 1024, 256>>>(Wq_i, cmbh, cmbl, 9, NQKV, 0);
        split_kernel<<<II * DD / 1024, 256>>>(Wo_i, woh, wol, 10, DD, 0);
        split_kernel<<<DD * FFD / 1024, 256>>>(W1_i, w1h, w1l, 12, FFD, 0);
        split_kernel<<<FFD * DD / 1024, 256>>>(W2_i, w2h, w2l, 10, DD, 0);
        bias_kv_kernel<<<128, 256>>>(Wkv_i, ln_m_b + i * DD, biaskv);

        ln_split_kernel<<<BB * LQ, 256>>>(lat, lnlh, lnll, ln_l_w + i * DD, ln_l_b + i * DD);

        // merged: [q | k | v]_latent = lnl @ [Wq | Wkv]
        gemm_bf16<64,3><<<dim3(NQKV / 128, BB * LQ / 64), 256, SMEM64>>>(
            lnlh, lnll, cmbh, cmbl, qb, BB * LQ, NQKV, DD, EPI_QKV,
            nullptr, kb, vb, LQ, NN, nullptr, nullptr);

        // kv (x part)
        gemm_bf16<128,2><<<dim3(2 * II / 128, BB * NN / 128), 256, SMEM128>>>(
            xh, xl, wkvph, wkvpl, nullptr, BB * NN, 2 * II, DD, EPI_KV,
            biaskv, kb, vb, NN, 0, nullptr, nullptr);

        // attention -> split bf16
        attn_kernel<<<BB * HH * 2, 256, ATTN_SMEM>>>(qb, kb, vb, mask, atth, attl);

        // lat += att @ Wo
        gemm_bf16<64,3><<<dim3(DD / 128, BB * LQ / 64), 256, SMEM64>>>(
            atth, attl, woh, wol, lat, BB * LQ, DD, II, EPI_ADD,
            nullptr, nullptr, nullptr, 0, 0, nullptr, nullptr);

        // FF
        ln_split_kernel<<<BB * LQ, 256>>>(lat, lnfh, lnfl, ff_ln_w + i * DD, ff_ln_b + i * DD);
        gemm_bf16<64,3><<<dim3(FFD / 128, BB * LQ / 64), 256, SMEM64>>>(
            lnfh, lnfl, w1h, w1l, nullptr, BB * LQ, FFD, DD, EPI_GELU,
            nullptr, nullptr, nullptr, 0, 0, hfh, hfl);
        gemm_bf16<64,3><<<dim3(DD / 128, BB * LQ / 64), 256, SMEM64>>>(
            hfh, hfl, w2h, w2l, lat, BB * LQ, DD, FFD, EPI_ADD,
            nullptr, nullptr, nullptr, 0, 0, nullptr, nullptr);
    }

    ln_kernel<<<BB * LQ, 256>>>(lat, out, norm_w, norm_b);
}

// round 10
// speedup vs baseline: 1.6114x; 1.5799x over previous
#include <cuda_runtime.h>
#include <cuda_bf16.h>
#include <stdint.h>
#include <math.h>

// ---------------- problem constants ----------------
#define BB   16
#define NN   2048
#define DD   1024
#define HH   8
#define DHD  64
#define II   512           // H*DH
#define LQ   64
#define SSQ  2112          // N + L
#define NDEPTH 6
#define FFD  4096
#define NQKV 1536          // II + 2*II

typedef __nv_bfloat16 bf16;

// ---------------- scratch ----------------
__device__ bf16 g_xh[(size_t)BB * NN * DD];     // compacted xhat hi (pad rows stay 0)
__device__ bf16 g_xl[(size_t)BB * NN * DD];     // compacted xhat lo
__device__ bf16 g_lnlh[BB * LQ * DD],  g_lnll[BB * LQ * DD];
__device__ bf16 g_lnfh[BB * LQ * DD],  g_lnfl[BB * LQ * DD];
__device__ bf16 g_atth[BB * LQ * II],  g_attl[BB * LQ * II];
__device__ bf16 g_hfh [BB * LQ * FFD], g_hfl [BB * LQ * FFD];
__device__ bf16 g_cmbh[DD * NQKV],     g_cmbl[DD * NQKV];     // [Wq | Wkv] per layer
__device__ bf16 g_wkvph[DD * 2 * II],  g_wkvpl[DD * 2 * II];  // ln_m_w-folded Wkv
__device__ bf16 g_woh [II * DD],       g_wol [II * DD];
__device__ bf16 g_w1h [DD * FFD],      g_w1l [DD * FFD];
__device__ bf16 g_w2h [FFD * DD],      g_w2l [FFD * DD];
__device__ float g_lat[BB * LQ * DD];
__device__ float g_q  [BB * LQ * II];
__device__ float g_k  [(size_t)BB * HH * SSQ * DHD];
__device__ float g_v  [(size_t)BB * HH * SSQ * DHD];
__device__ float g_biaskv[2 * II];
__device__ int   g_idxmap[BB * NN];    // per-batch compacted source indices
__device__ int   g_counts[BB];         // per-batch unmasked count

// ---------------- helpers ----------------
__device__ __forceinline__ unsigned pack2(float x, float y)
{
    bf16 hx = __float2bfloat16_rn(x);
    bf16 hy = __float2bfloat16_rn(y);
    return (unsigned)__bfloat16_as_ushort(hx) | ((unsigned)__bfloat16_as_ushort(hy) << 16);
}
__device__ __forceinline__ void split4(float4 v, uint2& hi, uint2& lo)
{
    float hx = __bfloat162float(__float2bfloat16_rn(v.x));
    float hy = __bfloat162float(__float2bfloat16_rn(v.y));
    float hz = __bfloat162float(__float2bfloat16_rn(v.z));
    float hw = __bfloat162float(__float2bfloat16_rn(v.w));
    hi = make_uint2(pack2(v.x, v.y), pack2(v.z, v.w));
    lo = make_uint2(pack2(v.x - hx, v.y - hy), pack2(v.z - hz, v.w - hw));
}

// ---------------- mask compaction: per-batch scan ----------------
__global__ __launch_bounds__(1024) void scan_mask_kernel(const int* __restrict__ mask,
                                                         int* __restrict__ idxmap,
                                                         int* __restrict__ counts)
{
    __shared__ int sh[1024];
    int b = blockIdx.x;
    int t = threadIdx.x;
    int v0 = (mask[b * NN + 2 * t]     == 0) ? 1 : 0;
    int v1 = (mask[b * NN + 2 * t + 1] == 0) ? 1 : 0;
    sh[t] = v0 + v1;
    __syncthreads();
    for (int off = 1; off < 1024; off <<= 1) {
        int x = 0;
        if (t >= off) x = sh[t - off];
        __syncthreads();
        if (t >= off) sh[t] += x;
        __syncthreads();
    }
    int incl = sh[t];
    int excl = incl - v0 - v1;
    if (v0) idxmap[b * NN + excl] = 2 * t;
    if (v1) idxmap[b * NN + excl + v0] = 2 * t + 1;
    if (t == 1023) counts[b] = incl;
}

// ---------------- LayerNorm (fp32 out, final layer) ----------------
__global__ __launch_bounds__(256) void ln_kernel(const float* __restrict__ in,
                                                 float* __restrict__ out,
                                                 const float* __restrict__ w,
                                                 const float* __restrict__ b)
{
    int row = blockIdx.x;
    int tid = threadIdx.x;
    const float4 xv = *(const float4*)(in + (size_t)row * DD + tid * 4);
    float s  = xv.x + xv.y + xv.z + xv.w;
    float ss = xv.x * xv.x + xv.y * xv.y + xv.z * xv.z + xv.w * xv.w;
    #pragma unroll
    for (int o = 16; o; o >>= 1) {
        s  += __shfl_xor_sync(0xffffffffu, s,  o);
        ss += __shfl_xor_sync(0xffffffffu, ss, o);
    }
    __shared__ float red[16];
    int wid = tid >> 5;
    if ((tid & 31) == 0) { red[wid] = s; red[wid + 8] = ss; }
    __syncthreads();
    s = 0.f; ss = 0.f;
    #pragma unroll
    for (int i = 0; i < 8; i++) { s += red[i]; ss += red[i + 8]; }
    float mu   = s * (1.f / DD);
    float var  = ss * (1.f / DD) - mu * mu;
    float rstd = rsqrtf(var + 1e-5f);
    float4 o4;
    o4.x = (xv.x - mu) * rstd; o4.y = (xv.y - mu) * rstd;
    o4.z = (xv.z - mu) * rstd; o4.w = (xv.w - mu) * rstd;
    const float4 wv = *(const float4*)(w + tid * 4);
    const float4 bv = *(const float4*)(b + tid * 4);
    o4.x = o4.x * wv.x + bv.x; o4.y = o4.y * wv.y + bv.y;
    o4.z = o4.z * wv.z + bv.z; o4.w = o4.w * wv.w + bv.w;
    *(float4*)(out + (size_t)row * DD + tid * 4) = o4;
}

// ---------------- LayerNorm -> split bf16 hi/lo ----------------
__global__ __launch_bounds__(256) void ln_split_kernel(const float* __restrict__ in,
                                                       bf16* __restrict__ hi,
                                                       bf16* __restrict__ lo,
                                                       const float* __restrict__ w,
                                                       const float* __restrict__ b)
{
    int row = blockIdx.x;
    int tid = threadIdx.x;
    const float4 xv = *(const float4*)(in + (size_t)row * DD + tid * 4);
    float s  = xv.x + xv.y + xv.z + xv.w;
    float ss = xv.x * xv.x + xv.y * xv.y + xv.z * xv.z + xv.w * xv.w;
    #pragma unroll
    for (int o = 16; o; o >>= 1) {
        s  += __shfl_xor_sync(0xffffffffu, s,  o);
        ss += __shfl_xor_sync(0xffffffffu, ss, o);
    }
    __shared__ float red[16];
    int wid = tid >> 5;
    if ((tid & 31) == 0) { red[wid] = s; red[wid + 8] = ss; }
    __syncthreads();
    s = 0.f; ss = 0.f;
    #pragma unroll
    for (int i = 0; i < 8; i++) { s += red[i]; ss += red[i + 8]; }
    float mu   = s * (1.f / DD);
    float var  = ss * (1.f / DD) - mu * mu;
    float rstd = rsqrtf(var + 1e-5f);
    float4 o4;
    o4.x = (xv.x - mu) * rstd; o4.y = (xv.y - mu) * rstd;
    o4.z = (xv.z - mu) * rstd; o4.w = (xv.w - mu) * rstd;
    if (w) {
        const float4 wv = *(const float4*)(w + tid * 4);
        const float4 bv = *(const float4*)(b + tid * 4);
        o4.x = o4.x * wv.x + bv.x; o4.y = o4.y * wv.y + bv.y;
        o4.z = o4.z * wv.z + bv.z; o4.w = o4.w * wv.w + bv.w;
    }
    uint2 h, l;
    split4(o4, h, l);
    *(uint2*)(hi + (size_t)row * DD + tid * 4) = h;
    *(uint2*)(lo + (size_t)row * DD + tid * 4) = l;
}

// ---------------- compacted LN-split of x: out row (b,j) <- x row (b, idxmap) ----
__global__ __launch_bounds__(256) void ln_split_gather_kernel(const float* __restrict__ in,
                                                              const int* __restrict__ idxmap,
                                                              const int* __restrict__ counts,
                                                              bf16* __restrict__ hi,
                                                              bf16* __restrict__ lo)
{
    int row = blockIdx.x;                  // 0 .. BB*NN-1 (compacted dst row)
    int b   = row >> 11;
    int j   = row & (NN - 1);
    if (j >= counts[b]) return;
    int src = idxmap[row];
    int tid = threadIdx.x;
    const float4 xv = *(const float4*)(in + ((size_t)b * NN + src) * DD + tid * 4);
    float s  = xv.x + xv.y + xv.z + xv.w;
    float ss = xv.x * xv.x + xv.y * xv.y + xv.z * xv.z + xv.w * xv.w;
    #pragma unroll
    for (int o = 16; o; o >>= 1) {
        s  += __shfl_xor_sync(0xffffffffu, s,  o);
        ss += __shfl_xor_sync(0xffffffffu, ss, o);
    }
    __shared__ float red[16];
    int wid = tid >> 5;
    if ((tid & 31) == 0) { red[wid] = s; red[wid + 8] = ss; }
    __syncthreads();
    s = 0.f; ss = 0.f;
    #pragma unroll
    for (int i = 0; i < 8; i++) { s += red[i]; ss += red[i + 8]; }
    float mu   = s * (1.f / DD);
    float var  = ss * (1.f / DD) - mu * mu;
    float rstd = rsqrtf(var + 1e-5f);
    float4 o4;
    o4.x = (xv.x - mu) * rstd; o4.y = (xv.y - mu) * rstd;
    o4.z = (xv.z - mu) * rstd; o4.w = (xv.w - mu) * rstd;
    uint2 h, l;
    split4(o4, h, l);
    *(uint2*)(hi + (size_t)row * DD + tid * 4) = h;
    *(uint2*)(lo + (size_t)row * DD + tid * 4) = l;
}

// ---------------- generic split with src/dst geometry ----------------
__global__ __launch_bounds__(256) void split_kernel(const float* __restrict__ in,
                                                    bf16* __restrict__ hi,
                                                    bf16* __restrict__ lo,
                                                    int srcColsLog2, int dstStride, int dstOff)
{
    int idx = (blockIdx.x * 256 + threadIdx.x) * 4;
    float4 v = *(const float4*)(in + idx);
    int row = idx >> srcColsLog2;
    int col = idx & ((1 << srcColsLog2) - 1);
    size_t d = (size_t)row * dstStride + dstOff + col;
    uint2 h, l;
    split4(v, h, l);
    *(uint2*)(hi + d) = h;
    *(uint2*)(lo + d) = l;
}

// ---------------- Wkv split: folded (hi/lo) + unfolded into combined ----------
__global__ __launch_bounds__(256) void split_wkv_kernel(const float* __restrict__ Wkv,
                                                        const float* __restrict__ lw,
                                                        bf16* __restrict__ fh, bf16* __restrict__ fl,
                                                        bf16* __restrict__ ch, bf16* __restrict__ cl)
{
    int idx = (blockIdx.x * 256 + threadIdx.x) * 4;      // over D*1024
    float4 v = *(const float4*)(Wkv + idx);
    int row = idx >> 10;
    int col = idx & 1023;
    uint2 h, l;
    split4(v, h, l);                                     // unfolded -> combined at off 512
    size_t d = (size_t)row * NQKV + II + col;
    *(uint2*)(ch + d) = h;
    *(uint2*)(cl + d) = l;
    float sc = lw[row];
    v.x *= sc; v.y *= sc; v.z *= sc; v.w *= sc;
    split4(v, h, l);                                     // folded
    *(uint2*)(fh + idx) = h;
    *(uint2*)(fl + idx) = l;
}

// ---------------- lat init ----------------
__global__ void init_lat_kernel(const float* __restrict__ latents, float* __restrict__ lat)
{
    int idx = blockIdx.x * 256 + threadIdx.x;
    lat[idx] = latents[idx & (LQ * DD - 1)];
}

// ---------------- biaskv[j] = sum_d ln_m_b[d] * Wkv[d][j] ----------------
__global__ __launch_bounds__(256) void bias_kv_kernel(const float* __restrict__ Wkv,
                                                      const float* __restrict__ lnb,
                                                      float* __restrict__ bias)
{
    int j  = blockIdx.x * 8 + (threadIdx.x & 7);
    int dc = threadIdx.x >> 3;                 // 0..31
    float a = 0.f;
    int d0 = dc * 32;
    #pragma unroll 8
    for (int d = d0; d < d0 + 32; d++) a += lnb[d] * Wkv[(size_t)d * 1024 + j];
    __shared__ float red[32][8];
    red[dc][threadIdx.x & 7] = a;
    __syncthreads();
    if (threadIdx.x < 8) {
        float s = 0.f;
        #pragma unroll
        for (int i = 0; i < 32; i++) s += red[i][threadIdx.x];
        bias[blockIdx.x * 8 + threadIdx.x] = s;
    }
}

// ================= bf16x3 split-precision mma.sync GEMM =================
enum { EPI_NONE = 0, EPI_ADD = 1, EPI_GELU = 2, EPI_KV = 3, EPI_QKV = 4 };

#define GBK 32
#define AST 40
#define BST 136

__device__ __forceinline__ void mma16816(float* d, const unsigned* a, const unsigned* b)
{
    asm volatile(
        "mma.sync.aligned.m16n8k16.row.col.f32.bf16.bf16.f32 "
        "{%0,%1,%2,%3}, {%4,%5,%6,%7}, {%8,%9}, {%0,%1,%2,%3};\n"
        : "+f"(d[0]), "+f"(d[1]), "+f"(d[2]), "+f"(d[3])
        : "r"(a[0]), "r"(a[1]), "r"(a[2]), "r"(a[3]), "r"(b[0]), "r"(b[1]));
}
__device__ __forceinline__ void ldsm4(unsigned* r, unsigned addr)
{
    asm volatile("ldmatrix.sync.aligned.m8n8.x4.shared.b16 {%0,%1,%2,%3}, [%4];\n"
                 : "=r"(r[0]), "=r"(r[1]), "=r"(r[2]), "=r"(r[3]) : "r"(addr));
}
__device__ __forceinline__ void ldsm4t(unsigned* r, unsigned addr)
{
    asm volatile("ldmatrix.sync.aligned.m8n8.x4.trans.shared.b16 {%0,%1,%2,%3}, [%4];\n"
                 : "=r"(r[0]), "=r"(r[1]), "=r"(r[2]), "=r"(r[3]) : "r"(addr));
}
__device__ __forceinline__ void cpasync16(unsigned s, const void* g)
{
    asm volatile("cp.async.cg.shared.global [%0], [%1], 16;\n" :: "r"(s), "l"(g));
}
#define CP_COMMIT() asm volatile("cp.async.commit_group;\n")
#define CP_WAIT1()  asm volatile("cp.async.wait_group 1;\n")

template<int TM, int NSTAGE>
__global__ __launch_bounds__(256, 2) void gemm_bf16(
    const bf16* __restrict__ Ahi, const bf16* __restrict__ Alo,
    const bf16* __restrict__ Bhi, const bf16* __restrict__ Blo,
    float* __restrict__ C, int M, int N, int K, int epi,
    const float* __restrict__ bias,
    float* __restrict__ Kout, float* __restrict__ Vout, int rowsPerB,
    const int* __restrict__ cnts,
    bf16* __restrict__ OutHi, bf16* __restrict__ OutLo)
{
    constexpr int WM16   = TM / 32;
    constexpr int A_EL   = TM * AST;
    constexpr int B_EL   = GBK * BST;
    constexpr int STAGE  = 2 * A_EL + 2 * B_EL;
    extern __shared__ __align__(16) bf16 smg[];
    unsigned base = (unsigned)__cvta_generic_to_shared(smg);

    int row0 = blockIdx.y * TM;
    int col0 = blockIdx.x << 7;

    // skip fully-padded kv-x tiles (compacted rows)
    if (epi == EPI_KV) {
        int bb = row0 >> 11;
        if ((row0 & (NN - 1)) >= cnts[bb]) return;
    }

    int tid  = threadIdx.x;
    int lane = tid & 31;
    int warp = tid >> 5;
    int wm = warp & 1, wn = warp >> 1;
    int lr = (lane & 7) + (((lane >> 3) & 1) << 3);
    int lc = (lane >> 4) << 3;

    float acc[WM16][4][4];
    #pragma unroll
    for (int i = 0; i < WM16; i++)
        #pragma unroll
        for (int j = 0; j < 4; j++)
            #pragma unroll
            for (int t = 0; t < 4; t++) acc[i][j][t] = 0.f;

    auto load_stage = [&](int kt, int buf) {
        unsigned sb = base + (unsigned)buf * STAGE * 2;
        constexpr int ACH = (TM * 4) / 256;
        #pragma unroll
        for (int p = 0; p < 2; p++) {
            const bf16* Ap = p ? Alo : Ahi;
            unsigned so = sb + (unsigned)p * A_EL * 2;
            #pragma unroll
            for (int i = 0; i < ACH; i++) {
                int chunk = tid + i * 256;
                int r = chunk >> 2, c16 = chunk & 3;
                cpasync16(so + (unsigned)(r * AST + c16 * 8) * 2,
                          Ap + (size_t)(row0 + r) * K + kt + c16 * 8);
            }
        }
        #pragma unroll
        for (int p = 0; p < 2; p++) {
            const bf16* Bp = p ? Blo : Bhi;
            unsigned so = sb + (unsigned)(2 * A_EL + p * B_EL) * 2;
            #pragma unroll
            for (int i = 0; i < 2; i++) {
                int chunk = tid + i * 256;
                int r = chunk >> 4, cc = (chunk & 15) * 8;
                cpasync16(so + (unsigned)(r * BST + cc) * 2,
                          Bp + (size_t)(kt + r) * N + col0 + cc);
            }
        }
    };

    int NK = K / GBK;
    load_stage(0, 0);   CP_COMMIT();
    load_stage(GBK, 1); CP_COMMIT();

    for (int it = 0; it < NK; it++) {
        CP_WAIT1();
        __syncthreads();
        int buf = (NSTAGE == 2) ? (it & 1) : (it % 3);
        unsigned sb  = base + (unsigned)buf * STAGE * 2;
        unsigned aHi = sb;
        unsigned aLo = sb + A_EL * 2;
        unsigned bHi = sb + 2 * A_EL * 2;
        unsigned bLo = bHi + B_EL * 2;

        if (NSTAGE == 3) {
            if (it + 2 < NK) load_stage((it + 2) * GBK, (it + 2) % 3);
            CP_COMMIT();
        }

        #pragma unroll
        for (int k16 = 0; k16 < GBK; k16 += 16) {
            unsigned bh[2][4], bl[2][4];
            #pragma unroll
            for (int ni = 0; ni < 2; ni++) {
                unsigned off = (unsigned)((k16 + lr) * BST + wn * 32 + ni * 16 + lc) * 2;
                ldsm4t(bh[ni], bHi + off);
                ldsm4t(bl[ni], bLo + off);
            }
            #pragma unroll
            for (int mi = 0; mi < WM16; mi++) {
                unsigned ah[4], al[4];
                unsigned off = (unsigned)((wm * (TM / 2) + mi * 16 + lr) * AST + k16 + lc) * 2;
                ldsm4(ah, aHi + off);
                ldsm4(al, aLo + off);
                #pragma unroll
                for (int nj = 0; nj < 4; nj++) {
                    int ni = nj >> 1, p = nj & 1;
                    mma16816(acc[mi][nj], ah, &bh[ni][2 * p]);
                    mma16816(acc[mi][nj], ah, &bl[ni][2 * p]);
                    mma16816(acc[mi][nj], al, &bh[ni][2 * p]);
                }
            }
        }

        if (NSTAGE == 2) {
            __syncthreads();
            if (it + 2 < NK) load_stage((it + 2) * GBK, it & 1);
            CP_COMMIT();
        }
    }

    // ---------------- epilogue ----------------
    int rbase = row0 + wm * (TM / 2) + (lane >> 2);
    int cbase = col0 + wn * 32 + (lane & 3) * 2;
    int cnt0 = (epi == EPI_KV) ? cnts[row0 >> 11] : 0;
    #pragma unroll
    for (int mi = 0; mi < WM16; mi++) {
        #pragma unroll
        for (int nj = 0; nj < 4; nj++) {
            #pragma unroll
            for (int half = 0; half < 2; half++) {
                int r = rbase + mi * 16 + half * 8;
                int c = cbase + nj * 8;
                float v0 = acc[mi][nj][half * 2 + 0];
                float v1 = acc[mi][nj][half * 2 + 1];
                if (epi == EPI_KV) {
                    int s = r & (NN - 1);
                    if (s < cnt0) {
                        int bb = r >> 11;
                        v0 += bias[c]; v1 += bias[c + 1];
                        float* dst;
                        if (c < II)
                            dst = Kout + (((size_t)bb * HH + (c >> 6)) * SSQ + s) * DHD + (c & 63);
                        else
                            dst = Vout + (((size_t)bb * HH + ((c - II) >> 6)) * SSQ + s) * DHD + ((c - II) & 63);
                        dst[0] = v0; dst[1] = v1;
                    }
                } else if (epi == EPI_QKV) {
                    if (c < II) {
                        float* dst = C + (size_t)r * II + c;
                        dst[0] = v0; dst[1] = v1;
                    } else {
                        int c2 = c - II;
                        int bb = r / rowsPerB;
                        int s  = cnts[bb] + (r - bb * rowsPerB);   // latents appended after real keys
                        float* dst;
                        if (c2 < II)
                            dst = Kout + (((size_t)bb * HH + (c2 >> 6)) * SSQ + s) * DHD + (c2 & 63);
                        else
                            dst = Vout + (((size_t)bb * HH + ((c2 - II) >> 6)) * SSQ + s) * DHD + ((c2 - II) & 63);
                        dst[0] = v0; dst[1] = v1;
                    }
                } else if (epi == EPI_GELU) {
                    float h0 = 0.5f * v0 * (1.f + erff(v0 * 0.70710678118654752f));
                    float h1 = 0.5f * v1 * (1.f + erff(v1 * 0.70710678118654752f));
                    float t0 = __bfloat162float(__float2bfloat16_rn(h0));
                    float t1 = __bfloat162float(__float2bfloat16_rn(h1));
                    *(unsigned*)(OutHi + (size_t)r * N + c) = pack2(h0, h1);
                    *(unsigned*)(OutLo + (size_t)r * N + c) = pack2(h0 - t0, h1 - t1);
                } else {
                    float* dst = C + (size_t)r * N + c;
                    if (epi == EPI_ADD) { v0 += dst[0]; v1 += dst[1]; }
                    dst[0] = v0; dst[1] = v1;
                }
            }
        }
    }
}

// ---------------- fused flash attention over compacted keys ----------------
#define AT2  68
#define ATTN_SMEM (((size_t)(32 + 64 + 64 + 32) * AT2) * 4)

__global__ __launch_bounds__(256) void attn_kernel(
    const float* __restrict__ q, const float* __restrict__ kg, const float* __restrict__ vg,
    const int* __restrict__ counts, bf16* __restrict__ attHi, bf16* __restrict__ attLo)
{
    extern __shared__ float sm[];
    float* qs  = sm;
    float* kT  = sm + 32 * AT2;
    float* vs  = sm + (32 + 64) * AT2;
    float* ps  = sm + (32 + 128) * AT2;

    int blk = blockIdx.x;
    int bh = blk >> 1, half = blk & 1;
    int b = bh >> 3, h = bh & 7;
    int tid = threadIdx.x;
    int qr = tid >> 3;
    int j0 = (tid & 7) * 8;

    int Sv = counts[b] + LQ;              // valid keys: compacted x + latents
    int nT = (Sv + 63) >> 6;

    const float* qbase = q + ((size_t)(b * LQ) + half * 32) * II + h * DHD;
    for (int idx = tid; idx < 32 * 16; idx += 256) {
        int r = idx >> 4, d4 = (idx & 15) << 2;
        *(float4*)&qs[r * AT2 + d4] = *(const float4*)&qbase[(size_t)r * II + d4];
    }

    float acc[8];
    #pragma unroll
    for (int i = 0; i < 8; i++) acc[i] = 0.f;
    float m = -1e30f, l = 0.f;

    const float* kb = kg + ((size_t)b * HH + h) * SSQ * DHD;
    const float* vb = vg + ((size_t)b * HH + h) * SSQ * DHD;

    for (int t = 0; t < nT; t++) {
        int s0 = t * 64;
        __syncthreads();
        for (int idx = tid; idx < 64 * 16; idx += 256) {
            int r = idx >> 4, d4 = (idx & 15) << 2;
            float4 k4 = *(const float4*)&kb[(size_t)(s0 + r) * DHD + d4];
            kT[(d4 + 0) * AT2 + r] = k4.x;
            kT[(d4 + 1) * AT2 + r] = k4.y;
            kT[(d4 + 2) * AT2 + r] = k4.z;
            kT[(d4 + 3) * AT2 + r] = k4.w;
            *(float4*)&vs[r * AT2 + d4] = *(const float4*)&vb[(size_t)(s0 + r) * DHD + d4];
        }
        __syncthreads();

        float sc[8];
        #pragma unroll
        for (int j = 0; j < 8; j++) sc[j] = 0.f;
        const float* qrow = &qs[qr * AT2];
        #pragma unroll 8
        for (int d = 0; d < 64; d++) {
            float qv = qrow[d];
            float4 kA = *(const float4*)&kT[d * AT2 + j0];
            float4 kB = *(const float4*)&kT[d * AT2 + j0 + 4];
            sc[0] += qv * kA.x; sc[1] += qv * kA.y; sc[2] += qv * kA.z; sc[3] += qv * kA.w;
            sc[4] += qv * kB.x; sc[5] += qv * kB.y; sc[6] += qv * kB.z; sc[7] += qv * kB.w;
        }
        float tmax = -1e30f;
        #pragma unroll
        for (int j = 0; j < 8; j++) {
            float s = sc[j] * 0.125f;
            if (s0 + j0 + j >= Sv) s = -1e30f;
            sc[j] = s;
            tmax = fmaxf(tmax, s);
        }
        tmax = fmaxf(tmax, __shfl_xor_sync(0xffffffffu, tmax, 1));
        tmax = fmaxf(tmax, __shfl_xor_sync(0xffffffffu, tmax, 2));
        tmax = fmaxf(tmax, __shfl_xor_sync(0xffffffffu, tmax, 4));
        float mnew = fmaxf(m, tmax);
        float corr = __expf(m - mnew);
        float psum = 0.f;
        #pragma unroll
        for (int j = 0; j < 8; j++) {
            float p = __expf(sc[j] - mnew);
            ps[qr * AT2 + j0 + j] = p;
            psum += p;
        }
        psum += __shfl_xor_sync(0xffffffffu, psum, 1);
        psum += __shfl_xor_sync(0xffffffffu, psum, 2);
        psum += __shfl_xor_sync(0xffffffffu, psum, 4);
        l = l * corr + psum;
        m = mnew;
        #pragma unroll
        for (int i = 0; i < 8; i++) acc[i] *= corr;
        __syncwarp();

        #pragma unroll 4
        for (int j = 0; j < 64; j++) {
            float p = ps[qr * AT2 + j];
            float4 v0 = *(const float4*)&vs[j * AT2 + j0];
            float4 v1 = *(const float4*)&vs[j * AT2 + j0 + 4];
            acc[0] += p * v0.x; acc[1] += p * v0.y; acc[2] += p * v0.z; acc[3] += p * v0.w;
            acc[4] += p * v1.x; acc[5] += p * v1.y; acc[6] += p * v1.z; acc[7] += p * v1.w;
        }
    }

    float invl = 1.f / l;
    size_t obase = ((size_t)(b * LQ) + half * 32 + qr) * II + h * DHD + j0;
    float o[8];
    #pragma unroll
    for (int i = 0; i < 8; i++) o[i] = acc[i] * invl;
    float th[8];
    #pragma unroll
    for (int i = 0; i < 8; i++) th[i] = __bfloat162float(__float2bfloat16_rn(o[i]));
    *(uint2*)(attHi + obase)     = make_uint2(pack2(o[0], o[1]), pack2(o[2], o[3]));
    *(uint2*)(attHi + obase + 4) = make_uint2(pack2(o[4], o[5]), pack2(o[6], o[7]));
    *(uint2*)(attLo + obase)     = make_uint2(pack2(o[0]-th[0], o[1]-th[1]), pack2(o[2]-th[2], o[3]-th[3]));
    *(uint2*)(attLo + obase + 4) = make_uint2(pack2(o[4]-th[4], o[5]-th[5]), pack2(o[6]-th[6], o[7]-th[7]));
}

// ---------------- host orchestration ----------------
#define SMEM128 ((2 * (2 * 128 * AST + 2 * GBK * BST)) * 2)
#define SMEM64  ((3 * (2 * 64  * AST + 2 * GBK * BST)) * 2)

extern "C" void kernel_launch(void* const* d_in, const int* in_sizes, int n_in,
                              void* d_out, int out_size)
{
    (void)in_sizes; (void)n_in; (void)out_size;
    const float* x        = (const float*)d_in[0];
    const int*   mask     = (const int*)  d_in[1];
    const float* latents  = (const float*)d_in[2];
    const float* ln_m_w   = (const float*)d_in[3];
    const float* ln_m_b   = (const float*)d_in[4];
    const float* ln_l_w   = (const float*)d_in[5];
    const float* ln_l_b   = (const float*)d_in[6];
    const float* Wq       = (const float*)d_in[7];
    const float* Wkv      = (const float*)d_in[8];
    const float* Wo       = (const float*)d_in[9];
    const float* ff_ln_w  = (const float*)d_in[10];
    const float* ff_ln_b  = (const float*)d_in[11];
    const float* W1       = (const float*)d_in[12];
    const float* W2       = (const float*)d_in[13];
    const float* norm_w   = (const float*)d_in[14];
    const float* norm_b   = (const float*)d_in[15];
    float* out = (float*)d_out;

    bf16 *xh, *xl, *lnlh, *lnll, *lnfh, *lnfl, *atth, *attl, *hfh, *hfl;
    bf16 *cmbh, *cmbl, *wkvph, *wkvpl, *woh, *wol, *w1h, *w1l, *w2h, *w2l;
    float *lat, *qb, *kb, *vb, *biaskv;
    int *idxmap, *counts;
    cudaGetSymbolAddress((void**)&xh, g_xh);     cudaGetSymbolAddress((void**)&xl, g_xl);
    cudaGetSymbolAddress((void**)&lnlh, g_lnlh); cudaGetSymbolAddress((void**)&lnll, g_lnll);
    cudaGetSymbolAddress((void**)&lnfh, g_lnfh); cudaGetSymbolAddress((void**)&lnfl, g_lnfl);
    cudaGetSymbolAddress((void**)&atth, g_atth); cudaGetSymbolAddress((void**)&attl, g_attl);
    cudaGetSymbolAddress((void**)&hfh, g_hfh);   cudaGetSymbolAddress((void**)&hfl, g_hfl);
    cudaGetSymbolAddress((void**)&cmbh, g_cmbh); cudaGetSymbolAddress((void**)&cmbl, g_cmbl);
    cudaGetSymbolAddress((void**)&wkvph, g_wkvph); cudaGetSymbolAddress((void**)&wkvpl, g_wkvpl);
    cudaGetSymbolAddress((void**)&woh, g_woh);   cudaGetSymbolAddress((void**)&wol, g_wol);
    cudaGetSymbolAddress((void**)&w1h, g_w1h);   cudaGetSymbolAddress((void**)&w1l, g_w1l);
    cudaGetSymbolAddress((void**)&w2h, g_w2h);   cudaGetSymbolAddress((void**)&w2l, g_w2l);
    cudaGetSymbolAddress((void**)&lat, g_lat);
    cudaGetSymbolAddress((void**)&qb, g_q);
    cudaGetSymbolAddress((void**)&kb, g_k);
    cudaGetSymbolAddress((void**)&vb, g_v);
    cudaGetSymbolAddress((void**)&biaskv, g_biaskv);
    cudaGetSymbolAddress((void**)&idxmap, g_idxmap);
    cudaGetSymbolAddress((void**)&counts, g_counts);

    cudaFuncSetAttribute((const void*)gemm_bf16<128,2>, cudaFuncAttributeMaxDynamicSharedMemorySize, SMEM128);
    cudaFuncSetAttribute((const void*)gemm_bf16<64,3>,  cudaFuncAttributeMaxDynamicSharedMemorySize, SMEM64);
    cudaFuncSetAttribute((const void*)attn_kernel,      cudaFuncAttributeMaxDynamicSharedMemorySize, (int)ATTN_SMEM);

    // layer-invariant: mask compaction, compacted xhat, lat init
    scan_mask_kernel<<<BB, 1024>>>(mask, idxmap, counts);
    ln_split_gather_kernel<<<BB * NN, 256>>>(x, idxmap, counts, xh, xl);
    init_lat_kernel<<<BB * LQ * DD / 256, 256>>>(latents, lat);

    for (int i = 0; i < NDEPTH; i++) {
        const float* Wkv_i = Wkv + (size_t)i * DD * 2 * II;
        const float* Wq_i  = Wq  + (size_t)i * DD * II;
        const float* Wo_i  = Wo  + (size_t)i * II * DD;
        const float* W1_i  = W1  + (size_t)i * DD * FFD;
        const float* W2_i  = W2  + (size_t)i * FFD * DD;

        // weight conversions
        split_wkv_kernel<<<DD * 2 * II / 1024, 256>>>(Wkv_i, ln_m_w + i * DD,
                                                      wkvph, wkvpl, cmbh, cmbl);
        split_kernel<<<DD * II / 1024, 256>>>(Wq_i, cmbh, cmbl, 9, NQKV, 0);
        split_kernel<<<II * DD / 1024, 256>>>(Wo_i, woh, wol, 10, DD, 0);
        split_kernel<<<DD * FFD / 1024, 256>>>(W1_i, w1h, w1l, 12, FFD, 0);
        split_kernel<<<FFD * DD / 1024, 256>>>(W2_i, w2h, w2l, 10, DD, 0);
        bias_kv_kernel<<<128, 256>>>(Wkv_i, ln_m_b + i * DD, biaskv);

        ln_split_kernel<<<BB * LQ, 256>>>(lat, lnlh, lnll, ln_l_w + i * DD, ln_l_b + i * DD);

        // merged: [q | k | v]_latent = lnl @ [Wq | Wkv]; latents land at s = counts[b]
        gemm_bf16<64,3><<<dim3(NQKV / 128, BB * LQ / 64), 256, SMEM64>>>(
            lnlh, lnll, cmbh, cmbl, qb, BB * LQ, NQKV, DD, EPI_QKV,
            nullptr, kb, vb, LQ, counts, nullptr, nullptr);

        // kv (compacted x part): inactive tiles early-exit
        gemm_bf16<128,2><<<dim3(2 * II / 128, BB * NN / 128), 256, SMEM128>>>(
            xh, xl, wkvph, wkvpl, nullptr, BB * NN, 2 * II, DD, EPI_KV,
            biaskv, kb, vb, NN, counts, nullptr, nullptr);

        // attention over compacted keys -> split bf16
        attn_kernel<<<BB * HH * 2, 256, ATTN_SMEM>>>(qb, kb, vb, counts, atth, attl);

        // lat += att @ Wo
        gemm_bf16<64,3><<<dim3(DD / 128, BB * LQ / 64), 256, SMEM64>>>(
            atth, attl, woh, wol, lat, BB * LQ, DD, II, EPI_ADD,
            nullptr, nullptr, nullptr, 0, counts, nullptr, nullptr);

        // FF
        ln_split_kernel<<<BB * LQ, 256>>>(lat, lnfh, lnfl, ff_ln_w + i * DD, ff_ln_b + i * DD);
        gemm_bf16<64,3><<<dim3(FFD / 128, BB * LQ / 64), 256, SMEM64>>>(
            lnfh, lnfl, w1h, w1l, nullptr, BB * LQ, FFD, DD, EPI_GELU,
            nullptr, nullptr, nullptr, 0, counts, hfh, hfl);
        gemm_bf16<64,3><<<dim3(DD / 128, BB * LQ / 64), 256, SMEM64>>>(
            hfh, hfl, w2h, w2l, lat, BB * LQ, DD, FFD, EPI_ADD,
            nullptr, nullptr, nullptr, 0, counts, nullptr, nullptr);
    }

    ln_kernel<<<BB * LQ, 256>>>(lat, out, norm_w, norm_b);
}

// round 11
// speedup vs baseline: 1.7032x; 1.0570x over previous
#include <cuda_runtime.h>
#include <cuda_bf16.h>
#include <stdint.h>
#include <math.h>

// ---------------- problem constants ----------------
#define BB   16
#define NN   2048
#define DD   1024
#define HH   8
#define DHD  64
#define II   512           // H*DH
#define LQ   64
#define SSQ  2112          // N + L
#define NDEPTH 6
#define FFD  4096
#define NQKV 1536          // II + 2*II

#define KVSZ ((size_t)BB * HH * SSQ * DHD)

typedef __nv_bfloat16 bf16;

// ---------------- scratch ----------------
__device__ bf16 g_xh[(size_t)BB * NN * DD];     // compacted xhat hi (pad rows stay 0)
__device__ bf16 g_xl[(size_t)BB * NN * DD];     // compacted xhat lo
__device__ bf16 g_lnlh[BB * LQ * DD],  g_lnll[BB * LQ * DD];
__device__ bf16 g_lnfh[BB * LQ * DD],  g_lnfl[BB * LQ * DD];
__device__ bf16 g_atth[BB * LQ * II],  g_attl[BB * LQ * II];
__device__ bf16 g_hfh [BB * LQ * FFD], g_hfl [BB * LQ * FFD];
// per-layer weight planes (all 6 layers)
__device__ bf16 g_cmbh[(size_t)NDEPTH * DD * NQKV],   g_cmbl[(size_t)NDEPTH * DD * NQKV];
__device__ bf16 g_wkvph[(size_t)NDEPTH * DD * 2 * II], g_wkvpl[(size_t)NDEPTH * DD * 2 * II];
__device__ bf16 g_woh [(size_t)NDEPTH * II * DD],     g_wol [(size_t)NDEPTH * II * DD];
__device__ bf16 g_w1h [(size_t)NDEPTH * DD * FFD],    g_w1l [(size_t)NDEPTH * DD * FFD];
__device__ bf16 g_w2h [(size_t)NDEPTH * FFD * DD],    g_w2l [(size_t)NDEPTH * FFD * DD];
__device__ float g_biaskv[NDEPTH * 2 * II];
__device__ float g_lat[BB * LQ * DD];
__device__ float g_q  [BB * LQ * II];
__device__ float g_k  [(size_t)NDEPTH * KVSZ];   // per-layer K buffers
__device__ float g_v  [(size_t)NDEPTH * KVSZ];   // per-layer V buffers
__device__ int   g_idxmap[BB * NN];
__device__ int   g_counts[BB];

// ---------------- helpers ----------------
__device__ __forceinline__ unsigned pack2(float x, float y)
{
    bf16 hx = __float2bfloat16_rn(x);
    bf16 hy = __float2bfloat16_rn(y);
    return (unsigned)__bfloat16_as_ushort(hx) | ((unsigned)__bfloat16_as_ushort(hy) << 16);
}
__device__ __forceinline__ void split4(float4 v, uint2& hi, uint2& lo)
{
    float hx = __bfloat162float(__float2bfloat16_rn(v.x));
    float hy = __bfloat162float(__float2bfloat16_rn(v.y));
    float hz = __bfloat162float(__float2bfloat16_rn(v.z));
    float hw = __bfloat162float(__float2bfloat16_rn(v.w));
    hi = make_uint2(pack2(v.x, v.y), pack2(v.z, v.w));
    lo = make_uint2(pack2(v.x - hx, v.y - hy), pack2(v.z - hz, v.w - hw));
}

// ---------------- mask compaction: per-batch scan ----------------
__global__ __launch_bounds__(1024) void scan_mask_kernel(const int* __restrict__ mask,
                                                         int* __restrict__ idxmap,
                                                         int* __restrict__ counts)
{
    __shared__ int sh[1024];
    int b = blockIdx.x;
    int t = threadIdx.x;
    int v0 = (mask[b * NN + 2 * t]     == 0) ? 1 : 0;
    int v1 = (mask[b * NN + 2 * t + 1] == 0) ? 1 : 0;
    sh[t] = v0 + v1;
    __syncthreads();
    for (int off = 1; off < 1024; off <<= 1) {
        int x = 0;
        if (t >= off) x = sh[t - off];
        __syncthreads();
        if (t >= off) sh[t] += x;
        __syncthreads();
    }
    int incl = sh[t];
    int excl = incl - v0 - v1;
    if (v0) idxmap[b * NN + excl] = 2 * t;
    if (v1) idxmap[b * NN + excl + v0] = 2 * t + 1;
    if (t == 1023) counts[b] = incl;
}

// ---------------- LayerNorm (fp32 out, final layer) ----------------
__global__ __launch_bounds__(256) void ln_kernel(const float* __restrict__ in,
                                                 float* __restrict__ out,
                                                 const float* __restrict__ w,
                                                 const float* __restrict__ b)
{
    int row = blockIdx.x;
    int tid = threadIdx.x;
    const float4 xv = *(const float4*)(in + (size_t)row * DD + tid * 4);
    float s  = xv.x + xv.y + xv.z + xv.w;
    float ss = xv.x * xv.x + xv.y * xv.y + xv.z * xv.z + xv.w * xv.w;
    #pragma unroll
    for (int o = 16; o; o >>= 1) {
        s  += __shfl_xor_sync(0xffffffffu, s,  o);
        ss += __shfl_xor_sync(0xffffffffu, ss, o);
    }
    __shared__ float red[16];
    int wid = tid >> 5;
    if ((tid & 31) == 0) { red[wid] = s; red[wid + 8] = ss; }
    __syncthreads();
    s = 0.f; ss = 0.f;
    #pragma unroll
    for (int i = 0; i < 8; i++) { s += red[i]; ss += red[i + 8]; }
    float mu   = s * (1.f / DD);
    float var  = ss * (1.f / DD) - mu * mu;
    float rstd = rsqrtf(var + 1e-5f);
    float4 o4;
    o4.x = (xv.x - mu) * rstd; o4.y = (xv.y - mu) * rstd;
    o4.z = (xv.z - mu) * rstd; o4.w = (xv.w - mu) * rstd;
    const float4 wv = *(const float4*)(w + tid * 4);
    const float4 bv = *(const float4*)(b + tid * 4);
    o4.x = o4.x * wv.x + bv.x; o4.y = o4.y * wv.y + bv.y;
    o4.z = o4.z * wv.z + bv.z; o4.w = o4.w * wv.w + bv.w;
    *(float4*)(out + (size_t)row * DD + tid * 4) = o4;
}

// ---------------- LayerNorm -> split bf16 hi/lo ----------------
__global__ __launch_bounds__(256) void ln_split_kernel(const float* __restrict__ in,
                                                       bf16* __restrict__ hi,
                                                       bf16* __restrict__ lo,
                                                       const float* __restrict__ w,
                                                       const float* __restrict__ b)
{
    int row = blockIdx.x;
    int tid = threadIdx.x;
    const float4 xv = *(const float4*)(in + (size_t)row * DD + tid * 4);
    float s  = xv.x + xv.y + xv.z + xv.w;
    float ss = xv.x * xv.x + xv.y * xv.y + xv.z * xv.z + xv.w * xv.w;
    #pragma unroll
    for (int o = 16; o; o >>= 1) {
        s  += __shfl_xor_sync(0xffffffffu, s,  o);
        ss += __shfl_xor_sync(0xffffffffu, ss, o);
    }
    __shared__ float red[16];
    int wid = tid >> 5;
    if ((tid & 31) == 0) { red[wid] = s; red[wid + 8] = ss; }
    __syncthreads();
    s = 0.f; ss = 0.f;
    #pragma unroll
    for (int i = 0; i < 8; i++) { s += red[i]; ss += red[i + 8]; }
    float mu   = s * (1.f / DD);
    float var  = ss * (1.f / DD) - mu * mu;
    float rstd = rsqrtf(var + 1e-5f);
    float4 o4;
    o4.x = (xv.x - mu) * rstd; o4.y = (xv.y - mu) * rstd;
    o4.z = (xv.z - mu) * rstd; o4.w = (xv.w - mu) * rstd;
    const float4 wv = *(const float4*)(w + tid * 4);
    const float4 bv = *(const float4*)(b + tid * 4);
    o4.x = o4.x * wv.x + bv.x; o4.y = o4.y * wv.y + bv.y;
    o4.z = o4.z * wv.z + bv.z; o4.w = o4.w * wv.w + bv.w;
    uint2 h, l;
    split4(o4, h, l);
    *(uint2*)(hi + (size_t)row * DD + tid * 4) = h;
    *(uint2*)(lo + (size_t)row * DD + tid * 4) = l;
}

// ---------------- compacted LN-split of x ----------------
__global__ __launch_bounds__(256) void ln_split_gather_kernel(const float* __restrict__ in,
                                                              const int* __restrict__ idxmap,
                                                              const int* __restrict__ counts,
                                                              bf16* __restrict__ hi,
                                                              bf16* __restrict__ lo)
{
    int row = blockIdx.x;
    int b   = row >> 11;
    int j   = row & (NN - 1);
    if (j >= counts[b]) return;
    int src = idxmap[row];
    int tid = threadIdx.x;
    const float4 xv = *(const float4*)(in + ((size_t)b * NN + src) * DD + tid * 4);
    float s  = xv.x + xv.y + xv.z + xv.w;
    float ss = xv.x * xv.x + xv.y * xv.y + xv.z * xv.z + xv.w * xv.w;
    #pragma unroll
    for (int o = 16; o; o >>= 1) {
        s  += __shfl_xor_sync(0xffffffffu, s,  o);
        ss += __shfl_xor_sync(0xffffffffu, ss, o);
    }
    __shared__ float red[16];
    int wid = tid >> 5;
    if ((tid & 31) == 0) { red[wid] = s; red[wid + 8] = ss; }
    __syncthreads();
    s = 0.f; ss = 0.f;
    #pragma unroll
    for (int i = 0; i < 8; i++) { s += red[i]; ss += red[i + 8]; }
    float mu   = s * (1.f / DD);
    float var  = ss * (1.f / DD) - mu * mu;
    float rstd = rsqrtf(var + 1e-5f);
    float4 o4;
    o4.x = (xv.x - mu) * rstd; o4.y = (xv.y - mu) * rstd;
    o4.z = (xv.z - mu) * rstd; o4.w = (xv.w - mu) * rstd;
    uint2 h, l;
    split4(o4, h, l);
    *(uint2*)(hi + (size_t)row * DD + tid * 4) = h;
    *(uint2*)(lo + (size_t)row * DD + tid * 4) = l;
}

// ---------------- all-layer generic weight split ----------------
// grid: (elemsPerLayer/1024, NDEPTH)
__global__ __launch_bounds__(256) void split_all_kernel(const float* __restrict__ in,
                                                        bf16* __restrict__ hi,
                                                        bf16* __restrict__ lo,
                                                        int srcColsLog2, int dstStride, int dstOff,
                                                        size_t srcLS, size_t dstLS)
{
    int layer = blockIdx.y;
    int idx = (blockIdx.x * 256 + threadIdx.x) * 4;
    float4 v = *(const float4*)(in + layer * srcLS + idx);
    int row = idx >> srcColsLog2;
    int col = idx & ((1 << srcColsLog2) - 1);
    size_t d = layer * dstLS + (size_t)row * dstStride + dstOff + col;
    uint2 h, l;
    split4(v, h, l);
    *(uint2*)(hi + d) = h;
    *(uint2*)(lo + d) = l;
}

// ---------------- all-layer Wkv split: folded + unfolded-into-combined ------
__global__ __launch_bounds__(256) void split_wkv_all_kernel(const float* __restrict__ Wkv,
                                                            const float* __restrict__ lwAll,
                                                            bf16* __restrict__ fh, bf16* __restrict__ fl,
                                                            bf16* __restrict__ ch, bf16* __restrict__ cl)
{
    int layer = blockIdx.y;
    int idx = (blockIdx.x * 256 + threadIdx.x) * 4;      // over D*1024
    float4 v = *(const float4*)(Wkv + (size_t)layer * DD * 1024 + idx);
    int row = idx >> 10;
    int col = idx & 1023;
    uint2 h, l;
    split4(v, h, l);
    size_t d = (size_t)layer * DD * NQKV + (size_t)row * NQKV + II + col;
    *(uint2*)(ch + d) = h;
    *(uint2*)(cl + d) = l;
    float sc = lwAll[layer * DD + row];
    v.x *= sc; v.y *= sc; v.z *= sc; v.w *= sc;
    split4(v, h, l);
    size_t f = (size_t)layer * DD * 1024 + idx;
    *(uint2*)(fh + f) = h;
    *(uint2*)(fl + f) = l;
}

// ---------------- lat init ----------------
__global__ void init_lat_kernel(const float* __restrict__ latents, float* __restrict__ lat)
{
    int idx = blockIdx.x * 256 + threadIdx.x;
    lat[idx] = latents[idx & (LQ * DD - 1)];
}

// ---------------- all-layer biaskv ----------------
__global__ __launch_bounds__(256) void bias_kv_all_kernel(const float* __restrict__ Wkv,
                                                          const float* __restrict__ lnbAll,
                                                          float* __restrict__ bias)
{
    int layer = blockIdx.y;
    const float* W = Wkv + (size_t)layer * DD * 1024;
    const float* lnb = lnbAll + layer * DD;
    int j  = blockIdx.x * 8 + (threadIdx.x & 7);
    int dc = threadIdx.x >> 3;
    float a = 0.f;
    int d0 = dc * 32;
    #pragma unroll 8
    for (int d = d0; d < d0 + 32; d++) a += lnb[d] * W[(size_t)d * 1024 + j];
    __shared__ float red[32][8];
    red[dc][threadIdx.x & 7] = a;
    __syncthreads();
    if (threadIdx.x < 8) {
        float s = 0.f;
        #pragma unroll
        for (int i = 0; i < 32; i++) s += red[i][threadIdx.x];
        bias[layer * 1024 + blockIdx.x * 8 + threadIdx.x] = s;
    }
}

// ================= bf16x3 split-precision mma.sync GEMM =================
enum { EPI_NONE = 0, EPI_ADD = 1, EPI_GELU = 2, EPI_KV = 3, EPI_QKV = 4 };

#define GBK 32
#define AST 40
#define BST 136

__device__ __forceinline__ void mma16816(float* d, const unsigned* a, const unsigned* b)
{
    asm volatile(
        "mma.sync.aligned.m16n8k16.row.col.f32.bf16.bf16.f32 "
        "{%0,%1,%2,%3}, {%4,%5,%6,%7}, {%8,%9}, {%0,%1,%2,%3};\n"
        : "+f"(d[0]), "+f"(d[1]), "+f"(d[2]), "+f"(d[3])
        : "r"(a[0]), "r"(a[1]), "r"(a[2]), "r"(a[3]), "r"(b[0]), "r"(b[1]));
}
__device__ __forceinline__ void ldsm4(unsigned* r, unsigned addr)
{
    asm volatile("ldmatrix.sync.aligned.m8n8.x4.shared.b16 {%0,%1,%2,%3}, [%4];\n"
                 : "=r"(r[0]), "=r"(r[1]), "=r"(r[2]), "=r"(r[3]) : "r"(addr));
}
__device__ __forceinline__ void ldsm4t(unsigned* r, unsigned addr)
{
    asm volatile("ldmatrix.sync.aligned.m8n8.x4.trans.shared.b16 {%0,%1,%2,%3}, [%4];\n"
                 : "=r"(r[0]), "=r"(r[1]), "=r"(r[2]), "=r"(r[3]) : "r"(addr));
}
__device__ __forceinline__ void cpasync16(unsigned s, const void* g)
{
    asm volatile("cp.async.cg.shared.global [%0], [%1], 16;\n" :: "r"(s), "l"(g));
}
#define CP_COMMIT() asm volatile("cp.async.commit_group;\n")
#define CP_WAIT1()  asm volatile("cp.async.wait_group 1;\n")

template<int TM, int NSTAGE>
__global__ __launch_bounds__(256, 2) void gemm_bf16(
    const bf16* __restrict__ Ahi, const bf16* __restrict__ Alo,
    const bf16* __restrict__ Bhi, const bf16* __restrict__ Blo,
    float* __restrict__ C, int M, int N, int K, int epi,
    const float* __restrict__ bias,
    float* __restrict__ Kout, float* __restrict__ Vout, int rowsPerB,
    const int* __restrict__ cnts,
    bf16* __restrict__ OutHi, bf16* __restrict__ OutLo)
{
    constexpr int WM16   = TM / 32;
    constexpr int A_EL   = TM * AST;
    constexpr int B_EL   = GBK * BST;
    constexpr int STAGE  = 2 * A_EL + 2 * B_EL;
    extern __shared__ __align__(16) bf16 smg[];
    unsigned base = (unsigned)__cvta_generic_to_shared(smg);

    int row0 = blockIdx.y * TM;
    int col0 = blockIdx.x << 7;

    if (epi == EPI_KV) {
        int bb = row0 >> 11;
        if ((row0 & (NN - 1)) >= cnts[bb]) return;
    }

    int tid  = threadIdx.x;
    int lane = tid & 31;
    int warp = tid >> 5;
    int wm = warp & 1, wn = warp >> 1;
    int lr = (lane & 7) + (((lane >> 3) & 1) << 3);
    int lc = (lane >> 4) << 3;

    float acc[WM16][4][4];
    #pragma unroll
    for (int i = 0; i < WM16; i++)
        #pragma unroll
        for (int j = 0; j < 4; j++)
            #pragma unroll
            for (int t = 0; t < 4; t++) acc[i][j][t] = 0.f;

    auto load_stage = [&](int kt, int buf) {
        unsigned sb = base + (unsigned)buf * STAGE * 2;
        constexpr int ACH = (TM * 4) / 256;
        #pragma unroll
        for (int p = 0; p < 2; p++) {
            const bf16* Ap = p ? Alo : Ahi;
            unsigned so = sb + (unsigned)p * A_EL * 2;
            #pragma unroll
            for (int i = 0; i < ACH; i++) {
                int chunk = tid + i * 256;
                int r = chunk >> 2, c16 = chunk & 3;
                cpasync16(so + (unsigned)(r * AST + c16 * 8) * 2,
                          Ap + (size_t)(row0 + r) * K + kt + c16 * 8);
            }
        }
        #pragma unroll
        for (int p = 0; p < 2; p++) {
            const bf16* Bp = p ? Blo : Bhi;
            unsigned so = sb + (unsigned)(2 * A_EL + p * B_EL) * 2;
            #pragma unroll
            for (int i = 0; i < 2; i++) {
                int chunk = tid + i * 256;
                int r = chunk >> 4, cc = (chunk & 15) * 8;
                cpasync16(so + (unsigned)(r * BST + cc) * 2,
                          Bp + (size_t)(kt + r) * N + col0 + cc);
            }
        }
    };

    int NK = K / GBK;
    load_stage(0, 0);   CP_COMMIT();
    load_stage(GBK, 1); CP_COMMIT();

    for (int it = 0; it < NK; it++) {
        CP_WAIT1();
        __syncthreads();
        int buf = (NSTAGE == 2) ? (it & 1) : (it % 3);
        unsigned sb  = base + (unsigned)buf * STAGE * 2;
        unsigned aHi = sb;
        unsigned aLo = sb + A_EL * 2;
        unsigned bHi = sb + 2 * A_EL * 2;
        unsigned bLo = bHi + B_EL * 2;

        if (NSTAGE == 3) {
            if (it + 2 < NK) load_stage((it + 2) * GBK, (it + 2) % 3);
            CP_COMMIT();
        }

        #pragma unroll
        for (int k16 = 0; k16 < GBK; k16 += 16) {
            unsigned bh[2][4], bl[2][4];
            #pragma unroll
            for (int ni = 0; ni < 2; ni++) {
                unsigned off = (unsigned)((k16 + lr) * BST + wn * 32 + ni * 16 + lc) * 2;
                ldsm4t(bh[ni], bHi + off);
                ldsm4t(bl[ni], bLo + off);
            }
            #pragma unroll
            for (int mi = 0; mi < WM16; mi++) {
                unsigned ah[4], al[4];
                unsigned off = (unsigned)((wm * (TM / 2) + mi * 16 + lr) * AST + k16 + lc) * 2;
                ldsm4(ah, aHi + off);
                ldsm4(al, aLo + off);
                #pragma unroll
                for (int nj = 0; nj < 4; nj++) {
                    int ni = nj >> 1, p = nj & 1;
                    mma16816(acc[mi][nj], ah, &bh[ni][2 * p]);
                    mma16816(acc[mi][nj], ah, &bl[ni][2 * p]);
                    mma16816(acc[mi][nj], al, &bh[ni][2 * p]);
                }
            }
        }

        if (NSTAGE == 2) {
            __syncthreads();
            if (it + 2 < NK) load_stage((it + 2) * GBK, it & 1);
            CP_COMMIT();
        }
    }

    // ---------------- epilogue ----------------
    int rbase = row0 + wm * (TM / 2) + (lane >> 2);
    int cbase = col0 + wn * 32 + (lane & 3) * 2;
    int cnt0 = (epi == EPI_KV) ? cnts[row0 >> 11] : 0;
    #pragma unroll
    for (int mi = 0; mi < WM16; mi++) {
        #pragma unroll
        for (int nj = 0; nj < 4; nj++) {
            #pragma unroll
            for (int half = 0; half < 2; half++) {
                int r = rbase + mi * 16 + half * 8;
                int c = cbase + nj * 8;
                float v0 = acc[mi][nj][half * 2 + 0];
                float v1 = acc[mi][nj][half * 2 + 1];
                if (epi == EPI_KV) {
                    int s = r & (NN - 1);
                    if (s < cnt0) {
                        int bb = r >> 11;
                        v0 += bias[c]; v1 += bias[c + 1];
                        float* dst;
                        if (c < II)
                            dst = Kout + (((size_t)bb * HH + (c >> 6)) * SSQ + s) * DHD + (c & 63);
                        else
                            dst = Vout + (((size_t)bb * HH + ((c - II) >> 6)) * SSQ + s) * DHD + ((c - II) & 63);
                        dst[0] = v0; dst[1] = v1;
                    }
                } else if (epi == EPI_QKV) {
                    if (c < II) {
                        float* dst = C + (size_t)r * II + c;
                        dst[0] = v0; dst[1] = v1;
                    } else {
                        int c2 = c - II;
                        int bb = r / rowsPerB;
                        int s  = cnts[bb] + (r - bb * rowsPerB);
                        float* dst;
                        if (c2 < II)
                            dst = Kout + (((size_t)bb * HH + (c2 >> 6)) * SSQ + s) * DHD + (c2 & 63);
                        else
                            dst = Vout + (((size_t)bb * HH + ((c2 - II) >> 6)) * SSQ + s) * DHD + ((c2 - II) & 63);
                        dst[0] = v0; dst[1] = v1;
                    }
                } else if (epi == EPI_GELU) {
                    float h0 = 0.5f * v0 * (1.f + erff(v0 * 0.70710678118654752f));
                    float h1 = 0.5f * v1 * (1.f + erff(v1 * 0.70710678118654752f));
                    float t0 = __bfloat162float(__float2bfloat16_rn(h0));
                    float t1 = __bfloat162float(__float2bfloat16_rn(h1));
                    *(unsigned*)(OutHi + (size_t)r * N + c) = pack2(h0, h1);
                    *(unsigned*)(OutLo + (size_t)r * N + c) = pack2(h0 - t0, h1 - t1);
                } else {
                    float* dst = C + (size_t)r * N + c;
                    if (epi == EPI_ADD) { v0 += dst[0]; v1 += dst[1]; }
                    dst[0] = v0; dst[1] = v1;
                }
            }
        }
    }
}

// ---------------- fused flash attention over compacted keys ----------------
#define AT2  68
#define ATTN_SMEM (((size_t)(32 + 64 + 64 + 32) * AT2) * 4)

__global__ __launch_bounds__(256) void attn_kernel(
    const float* __restrict__ q, const float* __restrict__ kg, const float* __restrict__ vg,
    const int* __restrict__ counts, bf16* __restrict__ attHi, bf16* __restrict__ attLo)
{
    extern __shared__ float sm[];
    float* qs  = sm;
    float* kT  = sm + 32 * AT2;
    float* vs  = sm + (32 + 64) * AT2;
    float* ps  = sm + (32 + 128) * AT2;

    int blk = blockIdx.x;
    int bh = blk >> 1, half = blk & 1;
    int b = bh >> 3, h = bh & 7;
    int tid = threadIdx.x;
    int qr = tid >> 3;
    int j0 = (tid & 7) * 8;

    int Sv = counts[b] + LQ;
    int nT = (Sv + 63) >> 6;

    const float* qbase = q + ((size_t)(b * LQ) + half * 32) * II + h * DHD;
    for (int idx = tid; idx < 32 * 16; idx += 256) {
        int r = idx >> 4, d4 = (idx & 15) << 2;
        *(float4*)&qs[r * AT2 + d4] = *(const float4*)&qbase[(size_t)r * II + d4];
    }

    float acc[8];
    #pragma unroll
    for (int i = 0; i < 8; i++) acc[i] = 0.f;
    float m = -1e30f, l = 0.f;

    const float* kb = kg + ((size_t)b * HH + h) * SSQ * DHD;
    const float* vb = vg + ((size_t)b * HH + h) * SSQ * DHD;

    for (int t = 0; t < nT; t++) {
        int s0 = t * 64;
        __syncthreads();
        for (int idx = tid; idx < 64 * 16; idx += 256) {
            int r = idx >> 4, d4 = (idx & 15) << 2;
            float4 k4 = *(const float4*)&kb[(size_t)(s0 + r) * DHD + d4];
            kT[(d4 + 0) * AT2 + r] = k4.x;
            kT[(d4 + 1) * AT2 + r] = k4.y;
            kT[(d4 + 2) * AT2 + r] = k4.z;
            kT[(d4 + 3) * AT2 + r] = k4.w;
            *(float4*)&vs[r * AT2 + d4] = *(const float4*)&vb[(size_t)(s0 + r) * DHD + d4];
        }
        __syncthreads();

        float sc[8];
        #pragma unroll
        for (int j = 0; j < 8; j++) sc[j] = 0.f;
        const float* qrow = &qs[qr * AT2];
        #pragma unroll 8
        for (int d = 0; d < 64; d++) {
            float qv = qrow[d];
            float4 kA = *(const float4*)&kT[d * AT2 + j0];
            float4 kB = *(const float4*)&kT[d * AT2 + j0 + 4];
            sc[0] += qv * kA.x; sc[1] += qv * kA.y; sc[2] += qv * kA.z; sc[3] += qv * kA.w;
            sc[4] += qv * kB.x; sc[5] += qv * kB.y; sc[6] += qv * kB.z; sc[7] += qv * kB.w;
        }
        float tmax = -1e30f;
        #pragma unroll
        for (int j = 0; j < 8; j++) {
            float s = sc[j] * 0.125f;
            if (s0 + j0 + j >= Sv) s = -1e30f;
            sc[j] = s;
            tmax = fmaxf(tmax, s);
        }
        tmax = fmaxf(tmax, __shfl_xor_sync(0xffffffffu, tmax, 1));
        tmax = fmaxf(tmax, __shfl_xor_sync(0xffffffffu, tmax, 2));
        tmax = fmaxf(tmax, __shfl_xor_sync(0xffffffffu, tmax, 4));
        float mnew = fmaxf(m, tmax);
        float corr = __expf(m - mnew);
        float psum = 0.f;
        #pragma unroll
        for (int j = 0; j < 8; j++) {
            float p = __expf(sc[j] - mnew);
            ps[qr * AT2 + j0 + j] = p;
            psum += p;
        }
        psum += __shfl_xor_sync(0xffffffffu, psum, 1);
        psum += __shfl_xor_sync(0xffffffffu, psum, 2);
        psum += __shfl_xor_sync(0xffffffffu, psum, 4);
        l = l * corr + psum;
        m = mnew;
        #pragma unroll
        for (int i = 0; i < 8; i++) acc[i] *= corr;
        __syncwarp();

        #pragma unroll 4
        for (int j = 0; j < 64; j++) {
            float p = ps[qr * AT2 + j];
            float4 v0 = *(const float4*)&vs[j * AT2 + j0];
            float4 v1 = *(const float4*)&vs[j * AT2 + j0 + 4];
            acc[0] += p * v0.x; acc[1] += p * v0.y; acc[2] += p * v0.z; acc[3] += p * v0.w;
            acc[4] += p * v1.x; acc[5] += p * v1.y; acc[6] += p * v1.z; acc[7] += p * v1.w;
        }
    }

    float invl = 1.f / l;
    size_t obase = ((size_t)(b * LQ) + half * 32 + qr) * II + h * DHD + j0;
    float o[8];
    #pragma unroll
    for (int i = 0; i < 8; i++) o[i] = acc[i] * invl;
    float th[8];
    #pragma unroll
    for (int i = 0; i < 8; i++) th[i] = __bfloat162float(__float2bfloat16_rn(o[i]));
    *(uint2*)(attHi + obase)     = make_uint2(pack2(o[0], o[1]), pack2(o[2], o[3]));
    *(uint2*)(attHi + obase + 4) = make_uint2(pack2(o[4], o[5]), pack2(o[6], o[7]));
    *(uint2*)(attLo + obase)     = make_uint2(pack2(o[0]-th[0], o[1]-th[1]), pack2(o[2]-th[2], o[3]-th[3]));
    *(uint2*)(attLo + obase + 4) = make_uint2(pack2(o[4]-th[4], o[5]-th[5]), pack2(o[6]-th[6], o[7]-th[7]));
}

// ---------------- host orchestration ----------------
#define SMEM128 ((2 * (2 * 128 * AST + 2 * GBK * BST)) * 2)
#define SMEM64  ((3 * (2 * 64  * AST + 2 * GBK * BST)) * 2)

extern "C" void kernel_launch(void* const* d_in, const int* in_sizes, int n_in,
                              void* d_out, int out_size)
{
    (void)in_sizes; (void)n_in; (void)out_size;
    const float* x        = (const float*)d_in[0];
    const int*   mask     = (const int*)  d_in[1];
    const float* latents  = (const float*)d_in[2];
    const float* ln_m_w   = (const float*)d_in[3];
    const float* ln_m_b   = (const float*)d_in[4];
    const float* ln_l_w   = (const float*)d_in[5];
    const float* ln_l_b   = (const float*)d_in[6];
    const float* Wq       = (const float*)d_in[7];
    const float* Wkv      = (const float*)d_in[8];
    const float* Wo       = (const float*)d_in[9];
    const float* ff_ln_w  = (const float*)d_in[10];
    const float* ff_ln_b  = (const float*)d_in[11];
    const float* W1       = (const float*)d_in[12];
    const float* W2       = (const float*)d_in[13];
    const float* norm_w   = (const float*)d_in[14];
    const float* norm_b   = (const float*)d_in[15];
    float* out = (float*)d_out;

    bf16 *xh, *xl, *lnlh, *lnll, *lnfh, *lnfl, *atth, *attl, *hfh, *hfl;
    bf16 *cmbh, *cmbl, *wkvph, *wkvpl, *woh, *wol, *w1h, *w1l, *w2h, *w2l;
    float *lat, *qb, *kb, *vb, *biaskv;
    int *idxmap, *counts;
    cudaGetSymbolAddress((void**)&xh, g_xh);     cudaGetSymbolAddress((void**)&xl, g_xl);
    cudaGetSymbolAddress((void**)&lnlh, g_lnlh); cudaGetSymbolAddress((void**)&lnll, g_lnll);
    cudaGetSymbolAddress((void**)&lnfh, g_lnfh); cudaGetSymbolAddress((void**)&lnfl, g_lnfl);
    cudaGetSymbolAddress((void**)&atth, g_atth); cudaGetSymbolAddress((void**)&attl, g_attl);
    cudaGetSymbolAddress((void**)&hfh, g_hfh);   cudaGetSymbolAddress((void**)&hfl, g_hfl);
    cudaGetSymbolAddress((void**)&cmbh, g_cmbh); cudaGetSymbolAddress((void**)&cmbl, g_cmbl);
    cudaGetSymbolAddress((void**)&wkvph, g_wkvph); cudaGetSymbolAddress((void**)&wkvpl, g_wkvpl);
    cudaGetSymbolAddress((void**)&woh, g_woh);   cudaGetSymbolAddress((void**)&wol, g_wol);
    cudaGetSymbolAddress((void**)&w1h, g_w1h);   cudaGetSymbolAddress((void**)&w1l, g_w1l);
    cudaGetSymbolAddress((void**)&w2h, g_w2h);   cudaGetSymbolAddress((void**)&w2l, g_w2l);
    cudaGetSymbolAddress((void**)&lat, g_lat);
    cudaGetSymbolAddress((void**)&qb, g_q);
    cudaGetSymbolAddress((void**)&kb, g_k);
    cudaGetSymbolAddress((void**)&vb, g_v);
    cudaGetSymbolAddress((void**)&biaskv, g_biaskv);
    cudaGetSymbolAddress((void**)&idxmap, g_idxmap);
    cudaGetSymbolAddress((void**)&counts, g_counts);

    cudaFuncSetAttribute((const void*)gemm_bf16<128,2>, cudaFuncAttributeMaxDynamicSharedMemorySize, SMEM128);
    cudaFuncSetAttribute((const void*)gemm_bf16<64,3>,  cudaFuncAttributeMaxDynamicSharedMemorySize, SMEM64);
    cudaFuncSetAttribute((const void*)attn_kernel,      cudaFuncAttributeMaxDynamicSharedMemorySize, (int)ATTN_SMEM);

    // side stream + events (created fresh each call; kernel_launch only runs
    // a handful of times before graph replay takes over, so no cleanup needed)
    cudaStream_t s2;
    cudaStreamCreateWithFlags(&s2, cudaStreamNonBlocking);
    cudaEvent_t evFork, evKV[NDEPTH];
    cudaEventCreateWithFlags(&evFork, cudaEventDisableTiming);
    for (int i = 0; i < NDEPTH; i++)
        cudaEventCreateWithFlags(&evKV[i], cudaEventDisableTiming);

    // ---- prologue on main stream: compaction, xhat, lat, ALL weight prep ----
    scan_mask_kernel<<<BB, 1024>>>(mask, idxmap, counts);
    ln_split_gather_kernel<<<BB * NN, 256>>>(x, idxmap, counts, xh, xl);
    init_lat_kernel<<<BB * LQ * DD / 256, 256>>>(latents, lat);

    split_wkv_all_kernel<<<dim3(1024, NDEPTH), 256>>>(Wkv, ln_m_w, wkvph, wkvpl, cmbh, cmbl);
    split_all_kernel<<<dim3(512, NDEPTH), 256>>>(Wq, cmbh, cmbl, 9, NQKV, 0,
                                                 (size_t)DD * II, (size_t)DD * NQKV);
    split_all_kernel<<<dim3(512, NDEPTH), 256>>>(Wo, woh, wol, 10, DD, 0,
                                                 (size_t)II * DD, (size_t)II * DD);
    split_all_kernel<<<dim3(4096, NDEPTH), 256>>>(W1, w1h, w1l, 12, FFD, 0,
                                                  (size_t)DD * FFD, (size_t)DD * FFD);
    split_all_kernel<<<dim3(4096, NDEPTH), 256>>>(W2, w2h, w2l, 10, DD, 0,
                                                  (size_t)FFD * DD, (size_t)FFD * DD);
    bias_kv_all_kernel<<<dim3(128, NDEPTH), 256>>>(Wkv, ln_m_b, biaskv);

    // ---- fork: all six kv-x GEMMs on the side stream (independent of lat path) ----
    cudaEventRecord(evFork, 0);
    cudaStreamWaitEvent(s2, evFork, 0);
    for (int i = 0; i < NDEPTH; i++) {
        gemm_bf16<128,2><<<dim3(2 * II / 128, BB * NN / 128), 256, SMEM128, s2>>>(
            xh, xl,
            wkvph + (size_t)i * DD * 2 * II, wkvpl + (size_t)i * DD * 2 * II,
            nullptr, BB * NN, 2 * II, DD, EPI_KV,
            biaskv + i * 2 * II, kb + (size_t)i * KVSZ, vb + (size_t)i * KVSZ, NN, counts,
            nullptr, nullptr);
        cudaEventRecord(evKV[i], s2);
    }

    // ---- main loop: lat path ----
    for (int i = 0; i < NDEPTH; i++) {
        float* kb_i = kb + (size_t)i * KVSZ;
        float* vb_i = vb + (size_t)i * KVSZ;

        ln_split_kernel<<<BB * LQ, 256>>>(lat, lnlh, lnll, ln_l_w + i * DD, ln_l_b + i * DD);

        // merged: [q | k | v]_latent = lnl @ [Wq | Wkv]; latents land at s = counts[b]
        gemm_bf16<64,3><<<dim3(NQKV / 128, BB * LQ / 64), 256, SMEM64>>>(
            lnlh, lnll,
            cmbh + (size_t)i * DD * NQKV, cmbl + (size_t)i * DD * NQKV,
            qb, BB * LQ, NQKV, DD, EPI_QKV,
            nullptr, kb_i, vb_i, LQ, counts, nullptr, nullptr);

        // join: attention needs side-stream kv-x for this layer
        cudaStreamWaitEvent(0, evKV[i], 0);
        attn_kernel<<<BB * HH * 2, 256, ATTN_SMEM>>>(qb, kb_i, vb_i, counts, atth, attl);

        // lat += att @ Wo
        gemm_bf16<64,3><<<dim3(DD / 128, BB * LQ / 64), 256, SMEM64>>>(
            atth, attl,
            woh + (size_t)i * II * DD, wol + (size_t)i * II * DD,
            lat, BB * LQ, DD, II, EPI_ADD,
            nullptr, nullptr, nullptr, 0, counts, nullptr, nullptr);

        // FF
        ln_split_kernel<<<BB * LQ, 256>>>(lat, lnfh, lnfl, ff_ln_w + i * DD, ff_ln_b + i * DD);
        gemm_bf16<64,3><<<dim3(FFD / 128, BB * LQ / 64), 256, SMEM64>>>(
            lnfh, lnfl,
            w1h + (size_t)i * DD * FFD, w1l + (size_t)i * DD * FFD,
            nullptr, BB * LQ, FFD, DD, EPI_GELU,
            nullptr, nullptr, nullptr, 0, counts, hfh, hfl);
        gemm_bf16<64,3><<<dim3(DD / 128, BB * LQ / 64), 256, SMEM64>>>(
            hfh, hfl,
            w2h + (size_t)i * FFD * DD, w2l + (size_t)i * FFD * DD,
            lat, BB * LQ, DD, FFD, EPI_ADD,
            nullptr, nullptr, nullptr, 0, counts, nullptr, nullptr);
    }

    ln_kernel<<<BB * LQ, 256>>>(lat, out, norm_w, norm_b);
}

// round 12
// speedup vs baseline: 2.0036x; 1.1764x over previous
#include <cuda_runtime.h>
#include <cuda_fp16.h>
#include <stdint.h>
#include <math.h>

// ---------------- problem constants ----------------
#define BB   16
#define NN   2048
#define DD   1024
#define HH   8
#define DHD  64
#define II   512           // H*DH
#define LQ   64
#define SSQ  2112          // N + L
#define NDEPTH 6
#define FFD  4096
#define NQKV 1536          // II + 2*II

#define KVSZ ((size_t)BB * HH * SSQ * DHD)

typedef __half fp16;

// ---------------- scratch ----------------
__device__ fp16 g_xh[(size_t)BB * NN * DD];     // compacted xhat hi
__device__ fp16 g_xl[(size_t)BB * NN * DD];     // compacted xhat lo
__device__ fp16 g_lnlh[BB * LQ * DD],  g_lnll[BB * LQ * DD];
__device__ fp16 g_lnfh[BB * LQ * DD],  g_lnfl[BB * LQ * DD];
__device__ fp16 g_atth[BB * LQ * II],  g_attl[BB * LQ * II];
__device__ fp16 g_hfh [BB * LQ * FFD], g_hfl [BB * LQ * FFD];
// per-layer weight planes (hi only — B side of every GEMM)
__device__ fp16 g_cmbh[(size_t)NDEPTH * DD * NQKV];
__device__ fp16 g_wkvph[(size_t)NDEPTH * DD * 2 * II];
__device__ fp16 g_woh [(size_t)NDEPTH * II * DD];
__device__ fp16 g_w1h [(size_t)NDEPTH * DD * FFD];
__device__ fp16 g_w2h [(size_t)NDEPTH * FFD * DD];
__device__ float g_biaskv[NDEPTH * 2 * II];
__device__ float g_lat[BB * LQ * DD];
__device__ float g_q  [BB * LQ * II];
__device__ float g_k  [(size_t)NDEPTH * KVSZ];
__device__ float g_v  [(size_t)NDEPTH * KVSZ];
__device__ int   g_idxmap[BB * NN];
__device__ int   g_counts[BB];

// ---------------- helpers ----------------
__device__ __forceinline__ unsigned pack2h(float x, float y)
{
    return (unsigned)__half_as_ushort(__float2half_rn(x))
         | ((unsigned)__half_as_ushort(__float2half_rn(y)) << 16);
}
__device__ __forceinline__ void split4h(float4 v, uint2& hi, uint2& lo)
{
    float hx = __half2float(__float2half_rn(v.x));
    float hy = __half2float(__float2half_rn(v.y));
    float hz = __half2float(__float2half_rn(v.z));
    float hw = __half2float(__float2half_rn(v.w));
    hi = make_uint2(pack2h(v.x, v.y), pack2h(v.z, v.w));
    lo = make_uint2(pack2h(v.x - hx, v.y - hy), pack2h(v.z - hz, v.w - hw));
}
__device__ __forceinline__ uint2 hi4h(float4 v)
{
    return make_uint2(pack2h(v.x, v.y), pack2h(v.z, v.w));
}

// ---------------- mask compaction: per-batch scan ----------------
__global__ __launch_bounds__(1024) void scan_mask_kernel(const int* __restrict__ mask,
                                                         int* __restrict__ idxmap,
                                                         int* __restrict__ counts)
{
    __shared__ int sh[1024];
    int b = blockIdx.x;
    int t = threadIdx.x;
    int v0 = (mask[b * NN + 2 * t]     == 0) ? 1 : 0;
    int v1 = (mask[b * NN + 2 * t + 1] == 0) ? 1 : 0;
    sh[t] = v0 + v1;
    __syncthreads();
    for (int off = 1; off < 1024; off <<= 1) {
        int x = 0;
        if (t >= off) x = sh[t - off];
        __syncthreads();
        if (t >= off) sh[t] += x;
        __syncthreads();
    }
    int incl = sh[t];
    int excl = incl - v0 - v1;
    if (v0) idxmap[b * NN + excl] = 2 * t;
    if (v1) idxmap[b * NN + excl + v0] = 2 * t + 1;
    if (t == 1023) counts[b] = incl;
}

// ---------------- LayerNorm (fp32 out, final layer) ----------------
__global__ __launch_bounds__(256) void ln_kernel(const float* __restrict__ in,
                                                 float* __restrict__ out,
                                                 const float* __restrict__ w,
                                                 const float* __restrict__ b)
{
    int row = blockIdx.x;
    int tid = threadIdx.x;
    const float4 xv = *(const float4*)(in + (size_t)row * DD + tid * 4);
    float s  = xv.x + xv.y + xv.z + xv.w;
    float ss = xv.x * xv.x + xv.y * xv.y + xv.z * xv.z + xv.w * xv.w;
    #pragma unroll
    for (int o = 16; o; o >>= 1) {
        s  += __shfl_xor_sync(0xffffffffu, s,  o);
        ss += __shfl_xor_sync(0xffffffffu, ss, o);
    }
    __shared__ float red[16];
    int wid = tid >> 5;
    if ((tid & 31) == 0) { red[wid] = s; red[wid + 8] = ss; }
    __syncthreads();
    s = 0.f; ss = 0.f;
    #pragma unroll
    for (int i = 0; i < 8; i++) { s += red[i]; ss += red[i + 8]; }
    float mu   = s * (1.f / DD);
    float var  = ss * (1.f / DD) - mu * mu;
    float rstd = rsqrtf(var + 1e-5f);
    float4 o4;
    o4.x = (xv.x - mu) * rstd; o4.y = (xv.y - mu) * rstd;
    o4.z = (xv.z - mu) * rstd; o4.w = (xv.w - mu) * rstd;
    const float4 wv = *(const float4*)(w + tid * 4);
    const float4 bv = *(const float4*)(b + tid * 4);
    o4.x = o4.x * wv.x + bv.x; o4.y = o4.y * wv.y + bv.y;
    o4.z = o4.z * wv.z + bv.z; o4.w = o4.w * wv.w + bv.w;
    *(float4*)(out + (size_t)row * DD + tid * 4) = o4;
}

// ---------------- LayerNorm -> split fp16 hi/lo ----------------
__global__ __launch_bounds__(256) void ln_split_kernel(const float* __restrict__ in,
                                                       fp16* __restrict__ hi,
                                                       fp16* __restrict__ lo,
                                                       const float* __restrict__ w,
                                                       const float* __restrict__ b)
{
    int row = blockIdx.x;
    int tid = threadIdx.x;
    const float4 xv = *(const float4*)(in + (size_t)row * DD + tid * 4);
    float s  = xv.x + xv.y + xv.z + xv.w;
    float ss = xv.x * xv.x + xv.y * xv.y + xv.z * xv.z + xv.w * xv.w;
    #pragma unroll
    for (int o = 16; o; o >>= 1) {
        s  += __shfl_xor_sync(0xffffffffu, s,  o);
        ss += __shfl_xor_sync(0xffffffffu, ss, o);
    }
    __shared__ float red[16];
    int wid = tid >> 5;
    if ((tid & 31) == 0) { red[wid] = s; red[wid + 8] = ss; }
    __syncthreads();
    s = 0.f; ss = 0.f;
    #pragma unroll
    for (int i = 0; i < 8; i++) { s += red[i]; ss += red[i + 8]; }
    float mu   = s * (1.f / DD);
    float var  = ss * (1.f / DD) - mu * mu;
    float rstd = rsqrtf(var + 1e-5f);
    float4 o4;
    o4.x = (xv.x - mu) * rstd; o4.y = (xv.y - mu) * rstd;
    o4.z = (xv.z - mu) * rstd; o4.w = (xv.w - mu) * rstd;
    const float4 wv = *(const float4*)(w + tid * 4);
    const float4 bv = *(const float4*)(b + tid * 4);
    o4.x = o4.x * wv.x + bv.x; o4.y = o4.y * wv.y + bv.y;
    o4.z = o4.z * wv.z + bv.z; o4.w = o4.w * wv.w + bv.w;
    uint2 h, l;
    split4h(o4, h, l);
    *(uint2*)(hi + (size_t)row * DD + tid * 4) = h;
    *(uint2*)(lo + (size_t)row * DD + tid * 4) = l;
}

// ---------------- compacted LN-split of x ----------------
__global__ __launch_bounds__(256) void ln_split_gather_kernel(const float* __restrict__ in,
                                                              const int* __restrict__ idxmap,
                                                              const int* __restrict__ counts,
                                                              fp16* __restrict__ hi,
                                                              fp16* __restrict__ lo)
{
    int row = blockIdx.x;
    int b   = row >> 11;
    int j   = row & (NN - 1);
    if (j >= counts[b]) return;
    int src = idxmap[row];
    int tid = threadIdx.x;
    const float4 xv = *(const float4*)(in + ((size_t)b * NN + src) * DD + tid * 4);
    float s  = xv.x + xv.y + xv.z + xv.w;
    float ss = xv.x * xv.x + xv.y * xv.y + xv.z * xv.z + xv.w * xv.w;
    #pragma unroll
    for (int o = 16; o; o >>= 1) {
        s  += __shfl_xor_sync(0xffffffffu, s,  o);
        ss += __shfl_xor_sync(0xffffffffu, ss, o);
    }
    __shared__ float red[16];
    int wid = tid >> 5;
    if ((tid & 31) == 0) { red[wid] = s; red[wid + 8] = ss; }
    __syncthreads();
    s = 0.f; ss = 0.f;
    #pragma unroll
    for (int i = 0; i < 8; i++) { s += red[i]; ss += red[i + 8]; }
    float mu   = s * (1.f / DD);
    float var  = ss * (1.f / DD) - mu * mu;
    float rstd = rsqrtf(var + 1e-5f);
    float4 o4;
    o4.x = (xv.x - mu) * rstd; o4.y = (xv.y - mu) * rstd;
    o4.z = (xv.z - mu) * rstd; o4.w = (xv.w - mu) * rstd;
    uint2 h, l;
    split4h(o4, h, l);
    *(uint2*)(hi + (size_t)row * DD + tid * 4) = h;
    *(uint2*)(lo + (size_t)row * DD + tid * 4) = l;
}

// ---------------- all-layer generic weight split (hi plane only) ----------
__global__ __launch_bounds__(256) void split_all_kernel(const float* __restrict__ in,
                                                        fp16* __restrict__ hi,
                                                        int srcColsLog2, int dstStride, int dstOff,
                                                        size_t srcLS, size_t dstLS)
{
    int layer = blockIdx.y;
    int idx = (blockIdx.x * 256 + threadIdx.x) * 4;
    float4 v = *(const float4*)(in + layer * srcLS + idx);
    int row = idx >> srcColsLog2;
    int col = idx & ((1 << srcColsLog2) - 1);
    size_t d = layer * dstLS + (size_t)row * dstStride + dstOff + col;
    *(uint2*)(hi + d) = hi4h(v);
}

// ---------------- all-layer Wkv split: folded + unfolded-into-combined ------
__global__ __launch_bounds__(256) void split_wkv_all_kernel(const float* __restrict__ Wkv,
                                                            const float* __restrict__ lwAll,
                                                            fp16* __restrict__ fh,
                                                            fp16* __restrict__ ch)
{
    int layer = blockIdx.y;
    int idx = (blockIdx.x * 256 + threadIdx.x) * 4;      // over D*1024
    float4 v = *(const float4*)(Wkv + (size_t)layer * DD * 1024 + idx);
    int row = idx >> 10;
    int col = idx & 1023;
    size_t d = (size_t)layer * DD * NQKV + (size_t)row * NQKV + II + col;
    *(uint2*)(ch + d) = hi4h(v);
    float sc = lwAll[layer * DD + row];
    v.x *= sc; v.y *= sc; v.z *= sc; v.w *= sc;
    size_t f = (size_t)layer * DD * 1024 + idx;
    *(uint2*)(fh + f) = hi4h(v);
}

// ---------------- lat init ----------------
__global__ void init_lat_kernel(const float* __restrict__ latents, float* __restrict__ lat)
{
    int idx = blockIdx.x * 256 + threadIdx.x;
    lat[idx] = latents[idx & (LQ * DD - 1)];
}

// ---------------- all-layer biaskv ----------------
__global__ __launch_bounds__(256) void bias_kv_all_kernel(const float* __restrict__ Wkv,
                                                          const float* __restrict__ lnbAll,
                                                          float* __restrict__ bias)
{
    int layer = blockIdx.y;
    const float* W = Wkv + (size_t)layer * DD * 1024;
    const float* lnb = lnbAll + layer * DD;
    int j  = blockIdx.x * 8 + (threadIdx.x & 7);
    int dc = threadIdx.x >> 3;
    float a = 0.f;
    int d0 = dc * 32;
    #pragma unroll 8
    for (int d = d0; d < d0 + 32; d++) a += lnb[d] * W[(size_t)d * 1024 + j];
    __shared__ float red[32][8];
    red[dc][threadIdx.x & 7] = a;
    __syncthreads();
    if (threadIdx.x < 8) {
        float s = 0.f;
        #pragma unroll
        for (int i = 0; i < 32; i++) s += red[i][threadIdx.x];
        bias[layer * 1024 + blockIdx.x * 8 + threadIdx.x] = s;
    }
}

// ================= fp16x2 split-precision mma.sync GEMM =================
// C = (Ahi + Alo) @ Bhi : 2 MMAs per tile, per-GEMM rel err ~2^-11.
enum { EPI_NONE = 0, EPI_ADD = 1, EPI_GELU = 2, EPI_KV = 3, EPI_QKV = 4 };

#define GBK 32
#define AST 40
#define BST 136

__device__ __forceinline__ void mma16816h(float* d, const unsigned* a, const unsigned* b)
{
    asm volatile(
        "mma.sync.aligned.m16n8k16.row.col.f32.f16.f16.f32 "
        "{%0,%1,%2,%3}, {%4,%5,%6,%7}, {%8,%9}, {%0,%1,%2,%3};\n"
        : "+f"(d[0]), "+f"(d[1]), "+f"(d[2]), "+f"(d[3])
        : "r"(a[0]), "r"(a[1]), "r"(a[2]), "r"(a[3]), "r"(b[0]), "r"(b[1]));
}
__device__ __forceinline__ void ldsm4(unsigned* r, unsigned addr)
{
    asm volatile("ldmatrix.sync.aligned.m8n8.x4.shared.b16 {%0,%1,%2,%3}, [%4];\n"
                 : "=r"(r[0]), "=r"(r[1]), "=r"(r[2]), "=r"(r[3]) : "r"(addr));
}
__device__ __forceinline__ void ldsm4t(unsigned* r, unsigned addr)
{
    asm volatile("ldmatrix.sync.aligned.m8n8.x4.trans.shared.b16 {%0,%1,%2,%3}, [%4];\n"
                 : "=r"(r[0]), "=r"(r[1]), "=r"(r[2]), "=r"(r[3]) : "r"(addr));
}
__device__ __forceinline__ void cpasync16(unsigned s, const void* g)
{
    asm volatile("cp.async.cg.shared.global [%0], [%1], 16;\n" :: "r"(s), "l"(g));
}
#define CP_COMMIT() asm volatile("cp.async.commit_group;\n")
#define CP_WAIT1()  asm volatile("cp.async.wait_group 1;\n")

template<int TM>
__global__ __launch_bounds__(256, 2) void gemm_fp16(
    const fp16* __restrict__ Ahi, const fp16* __restrict__ Alo,
    const fp16* __restrict__ Bhi,
    float* __restrict__ C, int M, int N, int K, int epi,
    const float* __restrict__ bias,
    float* __restrict__ Kout, float* __restrict__ Vout, int rowsPerB,
    const int* __restrict__ cnts,
    fp16* __restrict__ OutHi, fp16* __restrict__ OutLo)
{
    constexpr int WM16   = TM / 32;
    constexpr int A_EL   = TM * AST;
    constexpr int B_EL   = GBK * BST;
    constexpr int STAGE  = 2 * A_EL + B_EL;
    extern __shared__ __align__(16) fp16 smg[];
    unsigned base = (unsigned)__cvta_generic_to_shared(smg);

    int row0 = blockIdx.y * TM;
    int col0 = blockIdx.x << 7;

    if (epi == EPI_KV) {
        int bb = row0 >> 11;
        if ((row0 & (NN - 1)) >= cnts[bb]) return;
    }

    int tid  = threadIdx.x;
    int lane = tid & 31;
    int warp = tid >> 5;
    int wm = warp & 1, wn = warp >> 1;
    int lr = (lane & 7) + (((lane >> 3) & 1) << 3);
    int lc = (lane >> 4) << 3;

    float acc[WM16][4][4];
    #pragma unroll
    for (int i = 0; i < WM16; i++)
        #pragma unroll
        for (int j = 0; j < 4; j++)
            #pragma unroll
            for (int t = 0; t < 4; t++) acc[i][j][t] = 0.f;

    auto load_stage = [&](int kt, int buf) {
        unsigned sb = base + (unsigned)buf * STAGE * 2;
        constexpr int ACH = (TM * 4) / 256;
        #pragma unroll
        for (int p = 0; p < 2; p++) {
            const fp16* Ap = p ? Alo : Ahi;
            unsigned so = sb + (unsigned)p * A_EL * 2;
            #pragma unroll
            for (int i = 0; i < ACH; i++) {
                int chunk = tid + i * 256;
                int r = chunk >> 2, c16 = chunk & 3;
                cpasync16(so + (unsigned)(r * AST + c16 * 8) * 2,
                          Ap + (size_t)(row0 + r) * K + kt + c16 * 8);
            }
        }
        {
            unsigned so = sb + (unsigned)(2 * A_EL) * 2;
            #pragma unroll
            for (int i = 0; i < 2; i++) {
                int chunk = tid + i * 256;
                int r = chunk >> 4, cc = (chunk & 15) * 8;
                cpasync16(so + (unsigned)(r * BST + cc) * 2,
                          Bhi + (size_t)(kt + r) * N + col0 + cc);
            }
        }
    };

    int NK = K / GBK;
    load_stage(0, 0);   CP_COMMIT();
    load_stage(GBK, 1); CP_COMMIT();

    for (int it = 0; it < NK; it++) {
        CP_WAIT1();
        __syncthreads();
        int buf = it % 3;
        unsigned sb  = base + (unsigned)buf * STAGE * 2;
        unsigned aHi = sb;
        unsigned aLo = sb + A_EL * 2;
        unsigned bHi = sb + 2 * A_EL * 2;

        // 3-stage: prefetch into the buffer computed last iteration
        if (it + 2 < NK) load_stage((it + 2) * GBK, (it + 2) % 3);
        CP_COMMIT();

        #pragma unroll
        for (int k16 = 0; k16 < GBK; k16 += 16) {
            unsigned bh[2][4];
            #pragma unroll
            for (int ni = 0; ni < 2; ni++) {
                unsigned off = (unsigned)((k16 + lr) * BST + wn * 32 + ni * 16 + lc) * 2;
                ldsm4t(bh[ni], bHi + off);
            }
            #pragma unroll
            for (int mi = 0; mi < WM16; mi++) {
                unsigned ah[4], al[4];
                unsigned off = (unsigned)((wm * (TM / 2) + mi * 16 + lr) * AST + k16 + lc) * 2;
                ldsm4(ah, aHi + off);
                ldsm4(al, aLo + off);
                #pragma unroll
                for (int nj = 0; nj < 4; nj++) {
                    int ni = nj >> 1, p = nj & 1;
                    mma16816h(acc[mi][nj], ah, &bh[ni][2 * p]);
                    mma16816h(acc[mi][nj], al, &bh[ni][2 * p]);
                }
            }
        }
    }

    // ---------------- epilogue ----------------
    int rbase = row0 + wm * (TM / 2) + (lane >> 2);
    int cbase = col0 + wn * 32 + (lane & 3) * 2;
    int cnt0 = (epi == EPI_KV) ? cnts[row0 >> 11] : 0;
    #pragma unroll
    for (int mi = 0; mi < WM16; mi++) {
        #pragma unroll
        for (int nj = 0; nj < 4; nj++) {
            #pragma unroll
            for (int half = 0; half < 2; half++) {
                int r = rbase + mi * 16 + half * 8;
                int c = cbase + nj * 8;
                float v0 = acc[mi][nj][half * 2 + 0];
                float v1 = acc[mi][nj][half * 2 + 1];
                if (epi == EPI_KV) {
                    int s = r & (NN - 1);
                    if (s < cnt0) {
                        int bb = r >> 11;
                        v0 += bias[c]; v1 += bias[c + 1];
                        float* dst;
                        if (c < II)
                            dst = Kout + (((size_t)bb * HH + (c >> 6)) * SSQ + s) * DHD + (c & 63);
                        else
                            dst = Vout + (((size_t)bb * HH + ((c - II) >> 6)) * SSQ + s) * DHD + ((c - II) & 63);
                        dst[0] = v0; dst[1] = v1;
                    }
                } else if (epi == EPI_QKV) {
                    if (c < II) {
                        float* dst = C + (size_t)r * II + c;
                        dst[0] = v0; dst[1] = v1;
                    } else {
                        int c2 = c - II;
                        int bb = r / rowsPerB;
                        int s  = cnts[bb] + (r - bb * rowsPerB);
                        float* dst;
                        if (c2 < II)
                            dst = Kout + (((size_t)bb * HH + (c2 >> 6)) * SSQ + s) * DHD + (c2 & 63);
                        else
                            dst = Vout + (((size_t)bb * HH + ((c2 - II) >> 6)) * SSQ + s) * DHD + ((c2 - II) & 63);
                        dst[0] = v0; dst[1] = v1;
                    }
                } else if (epi == EPI_GELU) {
                    float h0 = 0.5f * v0 * (1.f + erff(v0 * 0.70710678118654752f));
                    float h1 = 0.5f * v1 * (1.f + erff(v1 * 0.70710678118654752f));
                    float t0 = __half2float(__float2half_rn(h0));
                    float t1 = __half2float(__float2half_rn(h1));
                    *(unsigned*)(OutHi + (size_t)r * N + c) = pack2h(h0, h1);
                    *(unsigned*)(OutLo + (size_t)r * N + c) = pack2h(h0 - t0, h1 - t1);
                } else {
                    float* dst = C + (size_t)r * N + c;
                    if (epi == EPI_ADD) { v0 += dst[0]; v1 += dst[1]; }
                    dst[0] = v0; dst[1] = v1;
                }
            }
        }
    }
}

// ---------------- fused flash attention over compacted keys ----------------
#define AT2  68
#define ATTN_SMEM (((size_t)(32 + 64 + 64 + 32) * AT2) * 4)

__global__ __launch_bounds__(256) void attn_kernel(
    const float* __restrict__ q, const float* __restrict__ kg, const float* __restrict__ vg,
    const int* __restrict__ counts, fp16* __restrict__ attHi, fp16* __restrict__ attLo)
{
    extern __shared__ float sm[];
    float* qs  = sm;
    float* kT  = sm + 32 * AT2;
    float* vs  = sm + (32 + 64) * AT2;
    float* ps  = sm + (32 + 128) * AT2;

    int blk = blockIdx.x;
    int bh = blk >> 1, half = blk & 1;
    int b = bh >> 3, h = bh & 7;
    int tid = threadIdx.x;
    int qr = tid >> 3;
    int j0 = (tid & 7) * 8;

    int Sv = counts[b] + LQ;
    int nT = (Sv + 63) >> 6;

    const float* qbase = q + ((size_t)(b * LQ) + half * 32) * II + h * DHD;
    for (int idx = tid; idx < 32 * 16; idx += 256) {
        int r = idx >> 4, d4 = (idx & 15) << 2;
        *(float4*)&qs[r * AT2 + d4] = *(const float4*)&qbase[(size_t)r * II + d4];
    }

    float acc[8];
    #pragma unroll
    for (int i = 0; i < 8; i++) acc[i] = 0.f;
    float m = -1e30f, l = 0.f;

    const float* kb = kg + ((size_t)b * HH + h) * SSQ * DHD;
    const float* vb = vg + ((size_t)b * HH + h) * SSQ * DHD;

    for (int t = 0; t < nT; t++) {
        int s0 = t * 64;
        __syncthreads();
        for (int idx = tid; idx < 64 * 16; idx += 256) {
            int r = idx >> 4, d4 = (idx & 15) << 2;
            float4 k4 = *(const float4*)&kb[(size_t)(s0 + r) * DHD + d4];
            kT[(d4 + 0) * AT2 + r] = k4.x;
            kT[(d4 + 1) * AT2 + r] = k4.y;
            kT[(d4 + 2) * AT2 + r] = k4.z;
            kT[(d4 + 3) * AT2 + r] = k4.w;
            *(float4*)&vs[r * AT2 + d4] = *(const float4*)&vb[(size_t)(s0 + r) * DHD + d4];
        }
        __syncthreads();

        float sc[8];
        #pragma unroll
        for (int j = 0; j < 8; j++) sc[j] = 0.f;
        const float* qrow = &qs[qr * AT2];
        #pragma unroll 8
        for (int d = 0; d < 64; d++) {
            float qv = qrow[d];
            float4 kA = *(const float4*)&kT[d * AT2 + j0];
            float4 kB = *(const float4*)&kT[d * AT2 + j0 + 4];
            sc[0] += qv * kA.x; sc[1] += qv * kA.y; sc[2] += qv * kA.z; sc[3] += qv * kA.w;
            sc[4] += qv * kB.x; sc[5] += qv * kB.y; sc[6] += qv * kB.z; sc[7] += qv * kB.w;
        }
        float tmax = -1e30f;
        #pragma unroll
        for (int j = 0; j < 8; j++) {
            float s = sc[j] * 0.125f;
            if (s0 + j0 + j >= Sv) s = -1e30f;
            sc[j] = s;
            tmax = fmaxf(tmax, s);
        }
        tmax = fmaxf(tmax, __shfl_xor_sync(0xffffffffu, tmax, 1));
        tmax = fmaxf(tmax, __shfl_xor_sync(0xffffffffu, tmax, 2));
        tmax = fmaxf(tmax, __shfl_xor_sync(0xffffffffu, tmax, 4));
        float mnew = fmaxf(m, tmax);
        float corr = __expf(m - mnew);
        float psum = 0.f;
        #pragma unroll
        for (int j = 0; j < 8; j++) {
            float p = __expf(sc[j] - mnew);
            ps[qr * AT2 + j0 + j] = p;
            psum += p;
        }
        psum += __shfl_xor_sync(0xffffffffu, psum, 1);
        psum += __shfl_xor_sync(0xffffffffu, psum, 2);
        psum += __shfl_xor_sync(0xffffffffu, psum, 4);
        l = l * corr + psum;
        m = mnew;
        #pragma unroll
        for (int i = 0; i < 8; i++) acc[i] *= corr;
        __syncwarp();

        #pragma unroll 4
        for (int j = 0; j < 64; j++) {
            float p = ps[qr * AT2 + j];
            float4 v0 = *(const float4*)&vs[j * AT2 + j0];
            float4 v1 = *(const float4*)&vs[j * AT2 + j0 + 4];
            acc[0] += p * v0.x; acc[1] += p * v0.y; acc[2] += p * v0.z; acc[3] += p * v0.w;
            acc[4] += p * v1.x; acc[5] += p * v1.y; acc[6] += p * v1.z; acc[7] += p * v1.w;
        }
    }

    float invl = 1.f / l;
    size_t obase = ((size_t)(b * LQ) + half * 32 + qr) * II + h * DHD + j0;
    float o[8];
    #pragma unroll
    for (int i = 0; i < 8; i++) o[i] = acc[i] * invl;
    float th[8];
    #pragma unroll
    for (int i = 0; i < 8; i++) th[i] = __half2float(__float2half_rn(o[i]));
    *(uint2*)(attHi + obase)     = make_uint2(pack2h(o[0], o[1]), pack2h(o[2], o[3]));
    *(uint2*)(attHi + obase + 4) = make_uint2(pack2h(o[4], o[5]), pack2h(o[6], o[7]));
    *(uint2*)(attLo + obase)     = make_uint2(pack2h(o[0]-th[0], o[1]-th[1]), pack2h(o[2]-th[2], o[3]-th[3]));
    *(uint2*)(attLo + obase + 4) = make_uint2(pack2h(o[4]-th[4], o[5]-th[5]), pack2h(o[6]-th[6], o[7]-th[7]));
}

// ---------------- host orchestration ----------------
#define SMEM128 ((3 * (2 * 128 * AST + GBK * BST)) * 2)
#define SMEM64  ((3 * (2 * 64  * AST + GBK * BST)) * 2)

extern "C" void kernel_launch(void* const* d_in, const int* in_sizes, int n_in,
                              void* d_out, int out_size)
{
    (void)in_sizes; (void)n_in; (void)out_size;
    const float* x        = (const float*)d_in[0];
    const int*   mask     = (const int*)  d_in[1];
    const float* latents  = (const float*)d_in[2];
    const float* ln_m_w   = (const float*)d_in[3];
    const float* ln_m_b   = (const float*)d_in[4];
    const float* ln_l_w   = (const float*)d_in[5];
    const float* ln_l_b   = (const float*)d_in[6];
    const float* Wq       = (const float*)d_in[7];
    const float* Wkv      = (const float*)d_in[8];
    const float* Wo       = (const float*)d_in[9];
    const float* ff_ln_w  = (const float*)d_in[10];
    const float* ff_ln_b  = (const float*)d_in[11];
    const float* W1       = (const float*)d_in[12];
    const float* W2       = (const float*)d_in[13];
    const float* norm_w   = (const float*)d_in[14];
    const float* norm_b   = (const float*)d_in[15];
    float* out = (float*)d_out;

    fp16 *xh, *xl, *lnlh, *lnll, *lnfh, *lnfl, *atth, *attl, *hfh, *hfl;
    fp16 *cmbh, *wkvph, *woh, *w1h, *w2h;
    float *lat, *qb, *kb, *vb, *biaskv;
    int *idxmap, *counts;
    cudaGetSymbolAddress((void**)&xh, g_xh);     cudaGetSymbolAddress((void**)&xl, g_xl);
    cudaGetSymbolAddress((void**)&lnlh, g_lnlh); cudaGetSymbolAddress((void**)&lnll, g_lnll);
    cudaGetSymbolAddress((void**)&lnfh, g_lnfh); cudaGetSymbolAddress((void**)&lnfl, g_lnfl);
    cudaGetSymbolAddress((void**)&atth, g_atth); cudaGetSymbolAddress((void**)&attl, g_attl);
    cudaGetSymbolAddress((void**)&hfh, g_hfh);   cudaGetSymbolAddress((void**)&hfl, g_hfl);
    cudaGetSymbolAddress((void**)&cmbh, g_cmbh);
    cudaGetSymbolAddress((void**)&wkvph, g_wkvph);
    cudaGetSymbolAddress((void**)&woh, g_woh);
    cudaGetSymbolAddress((void**)&w1h, g_w1h);
    cudaGetSymbolAddress((void**)&w2h, g_w2h);
    cudaGetSymbolAddress((void**)&lat, g_lat);
    cudaGetSymbolAddress((void**)&qb, g_q);
    cudaGetSymbolAddress((void**)&kb, g_k);
    cudaGetSymbolAddress((void**)&vb, g_v);
    cudaGetSymbolAddress((void**)&biaskv, g_biaskv);
    cudaGetSymbolAddress((void**)&idxmap, g_idxmap);
    cudaGetSymbolAddress((void**)&counts, g_counts);

    cudaFuncSetAttribute((const void*)gemm_fp16<128>, cudaFuncAttributeMaxDynamicSharedMemorySize, SMEM128);
    cudaFuncSetAttribute((const void*)gemm_fp16<64>,  cudaFuncAttributeMaxDynamicSharedMemorySize, SMEM64);
    cudaFuncSetAttribute((const void*)attn_kernel,    cudaFuncAttributeMaxDynamicSharedMemorySize, (int)ATTN_SMEM);

    cudaStream_t s2;
    cudaStreamCreateWithFlags(&s2, cudaStreamNonBlocking);
    cudaEvent_t evFork, evKV[NDEPTH];
    cudaEventCreateWithFlags(&evFork, cudaEventDisableTiming);
    for (int i = 0; i < NDEPTH; i++)
        cudaEventCreateWithFlags(&evKV[i], cudaEventDisableTiming);

    // ---- prologue: compaction, xhat, lat, ALL weight prep ----
    scan_mask_kernel<<<BB, 1024>>>(mask, idxmap, counts);
    ln_split_gather_kernel<<<BB * NN, 256>>>(x, idxmap, counts, xh, xl);
    init_lat_kernel<<<BB * LQ * DD / 256, 256>>>(latents, lat);

    split_wkv_all_kernel<<<dim3(1024, NDEPTH), 256>>>(Wkv, ln_m_w, wkvph, cmbh);
    split_all_kernel<<<dim3(512, NDEPTH), 256>>>(Wq, cmbh, 9, NQKV, 0,
                                                 (size_t)DD * II, (size_t)DD * NQKV);
    split_all_kernel<<<dim3(512, NDEPTH), 256>>>(Wo, woh, 10, DD, 0,
                                                 (size_t)II * DD, (size_t)II * DD);
    split_all_kernel<<<dim3(4096, NDEPTH), 256>>>(W1, w1h, 12, FFD, 0,
                                                  (size_t)DD * FFD, (size_t)DD * FFD);
    split_all_kernel<<<dim3(4096, NDEPTH), 256>>>(W2, w2h, 10, DD, 0,
                                                  (size_t)FFD * DD, (size_t)FFD * DD);
    bias_kv_all_kernel<<<dim3(128, NDEPTH), 256>>>(Wkv, ln_m_b, biaskv);

    // ---- fork: six kv-x GEMMs on side stream ----
    cudaEventRecord(evFork, 0);
    cudaStreamWaitEvent(s2, evFork, 0);
    for (int i = 0; i < NDEPTH; i++) {
        gemm_fp16<128><<<dim3(2 * II / 128, BB * NN / 128), 256, SMEM128, s2>>>(
            xh, xl, wkvph + (size_t)i * DD * 2 * II,
            nullptr, BB * NN, 2 * II, DD, EPI_KV,
            biaskv + i * 2 * II, kb + (size_t)i * KVSZ, vb + (size_t)i * KVSZ, NN, counts,
            nullptr, nullptr);
        cudaEventRecord(evKV[i], s2);
    }

    // ---- main loop: lat path ----
    for (int i = 0; i < NDEPTH; i++) {
        float* kb_i = kb + (size_t)i * KVSZ;
        float* vb_i = vb + (size_t)i * KVSZ;

        ln_split_kernel<<<BB * LQ, 256>>>(lat, lnlh, lnll, ln_l_w + i * DD, ln_l_b + i * DD);

        gemm_fp16<64><<<dim3(NQKV / 128, BB * LQ / 64), 256, SMEM64>>>(
            lnlh, lnll, cmbh + (size_t)i * DD * NQKV,
            qb, BB * LQ, NQKV, DD, EPI_QKV,
            nullptr, kb_i, vb_i, LQ, counts, nullptr, nullptr);

        cudaStreamWaitEvent(0, evKV[i], 0);
        attn_kernel<<<BB * HH * 2, 256, ATTN_SMEM>>>(qb, kb_i, vb_i, counts, atth, attl);

        gemm_fp16<64><<<dim3(DD / 128, BB * LQ / 64), 256, SMEM64>>>(
            atth, attl, woh + (size_t)i * II * DD,
            lat, BB * LQ, DD, II, EPI_ADD,
            nullptr, nullptr, nullptr, 0, counts, nullptr, nullptr);

        ln_split_kernel<<<BB * LQ, 256>>>(lat, lnfh, lnfl, ff_ln_w + i * DD, ff_ln_b + i * DD);
        gemm_fp16<64><<<dim3(FFD / 128, BB * LQ / 64), 256, SMEM64>>>(
            lnfh, lnfl, w1h + (size_t)i * DD * FFD,
            nullptr, BB * LQ, FFD, DD, EPI_GELU,
            nullptr, nullptr, nullptr, 0, counts, hfh, hfl);
        gemm_fp16<64><<<dim3(DD / 128, BB * LQ / 64), 256, SMEM64>>>(
            hfh, hfl, w2h + (size_t)i * FFD * DD,
            lat, BB * LQ, DD, FFD, EPI_ADD,
            nullptr, nullptr, nullptr, 0, counts, nullptr, nullptr);
    }

    ln_kernel<<<BB * LQ, 256>>>(lat, out, norm_w, norm_b);
}

// round 13
// speedup vs baseline: 2.0302x; 1.0133x over previous
#include <cuda_runtime.h>
#include <cuda_fp16.h>
#include <stdint.h>
#include <math.h>

// ---------------- problem constants ----------------
#define BB   16
#define NN   2048
#define DD   1024
#define HH   8
#define DHD  64
#define II   512           // H*DH
#define LQ   64
#define SSQ  2112          // N + L
#define NDEPTH 6
#define FFD  4096
#define NQKV 1536          // II + 2*II

#define KVSZ ((size_t)BB * HH * SSQ * DHD)

typedef __half fp16;

// ---------------- scratch ----------------
__device__ fp16 g_xh[(size_t)BB * NN * DD];     // compacted xhat hi
__device__ fp16 g_xl[(size_t)BB * NN * DD];     // compacted xhat lo
__device__ fp16 g_lnlh[BB * LQ * DD],  g_lnll[BB * LQ * DD];
__device__ fp16 g_lnfh[BB * LQ * DD],  g_lnfl[BB * LQ * DD];
__device__ fp16 g_atth[BB * LQ * II],  g_attl[BB * LQ * II];
__device__ fp16 g_hfh [BB * LQ * FFD], g_hfl [BB * LQ * FFD];
// per-layer weight planes (hi only — B side of every GEMM)
__device__ fp16 g_cmbh[(size_t)NDEPTH * DD * NQKV];
__device__ fp16 g_wkvph[(size_t)NDEPTH * DD * 2 * II];
__device__ fp16 g_woh [(size_t)NDEPTH * II * DD];
__device__ fp16 g_w1h [(size_t)NDEPTH * DD * FFD];
__device__ fp16 g_w2h [(size_t)NDEPTH * FFD * DD];
__device__ float g_biaskv[NDEPTH * 2 * II];
__device__ float g_lat[BB * LQ * DD];
__device__ float g_q  [BB * LQ * II];
__device__ float g_k  [(size_t)NDEPTH * KVSZ];
__device__ float g_v  [(size_t)NDEPTH * KVSZ];
__device__ int   g_idxmap[BB * NN];
__device__ int   g_counts[BB];

// ---------------- helpers ----------------
__device__ __forceinline__ unsigned pack2h(float x, float y)
{
    return (unsigned)__half_as_ushort(__float2half_rn(x))
         | ((unsigned)__half_as_ushort(__float2half_rn(y)) << 16);
}
__device__ __forceinline__ void split4h(float4 v, uint2& hi, uint2& lo)
{
    float hx = __half2float(__float2half_rn(v.x));
    float hy = __half2float(__float2half_rn(v.y));
    float hz = __half2float(__float2half_rn(v.z));
    float hw = __half2float(__float2half_rn(v.w));
    hi = make_uint2(pack2h(v.x, v.y), pack2h(v.z, v.w));
    lo = make_uint2(pack2h(v.x - hx, v.y - hy), pack2h(v.z - hz, v.w - hw));
}
__device__ __forceinline__ uint2 hi4h(float4 v)
{
    return make_uint2(pack2h(v.x, v.y), pack2h(v.z, v.w));
}

// ---------------- mask compaction: per-batch scan ----------------
__global__ __launch_bounds__(1024) void scan_mask_kernel(const int* __restrict__ mask,
                                                         int* __restrict__ idxmap,
                                                         int* __restrict__ counts)
{
    __shared__ int sh[1024];
    int b = blockIdx.x;
    int t = threadIdx.x;
    int v0 = (mask[b * NN + 2 * t]     == 0) ? 1 : 0;
    int v1 = (mask[b * NN + 2 * t + 1] == 0) ? 1 : 0;
    sh[t] = v0 + v1;
    __syncthreads();
    for (int off = 1; off < 1024; off <<= 1) {
        int x = 0;
        if (t >= off) x = sh[t - off];
        __syncthreads();
        if (t >= off) sh[t] += x;
        __syncthreads();
    }
    int incl = sh[t];
    int excl = incl - v0 - v1;
    if (v0) idxmap[b * NN + excl] = 2 * t;
    if (v1) idxmap[b * NN + excl + v0] = 2 * t + 1;
    if (t == 1023) counts[b] = incl;
}

// ---------------- LayerNorm (fp32 out, final layer) ----------------
__global__ __launch_bounds__(256) void ln_kernel(const float* __restrict__ in,
                                                 float* __restrict__ out,
                                                 const float* __restrict__ w,
                                                 const float* __restrict__ b)
{
    int row = blockIdx.x;
    int tid = threadIdx.x;
    const float4 xv = *(const float4*)(in + (size_t)row * DD + tid * 4);
    float s  = xv.x + xv.y + xv.z + xv.w;
    float ss = xv.x * xv.x + xv.y * xv.y + xv.z * xv.z + xv.w * xv.w;
    #pragma unroll
    for (int o = 16; o; o >>= 1) {
        s  += __shfl_xor_sync(0xffffffffu, s,  o);
        ss += __shfl_xor_sync(0xffffffffu, ss, o);
    }
    __shared__ float red[16];
    int wid = tid >> 5;
    if ((tid & 31) == 0) { red[wid] = s; red[wid + 8] = ss; }
    __syncthreads();
    s = 0.f; ss = 0.f;
    #pragma unroll
    for (int i = 0; i < 8; i++) { s += red[i]; ss += red[i + 8]; }
    float mu   = s * (1.f / DD);
    float var  = ss * (1.f / DD) - mu * mu;
    float rstd = rsqrtf(var + 1e-5f);
    float4 o4;
    o4.x = (xv.x - mu) * rstd; o4.y = (xv.y - mu) * rstd;
    o4.z = (xv.z - mu) * rstd; o4.w = (xv.w - mu) * rstd;
    const float4 wv = *(const float4*)(w + tid * 4);
    const float4 bv = *(const float4*)(b + tid * 4);
    o4.x = o4.x * wv.x + bv.x; o4.y = o4.y * wv.y + bv.y;
    o4.z = o4.z * wv.z + bv.z; o4.w = o4.w * wv.w + bv.w;
    *(float4*)(out + (size_t)row * DD + tid * 4) = o4;
}

// ---------------- LayerNorm -> split fp16 hi/lo ----------------
__global__ __launch_bounds__(256) void ln_split_kernel(const float* __restrict__ in,
                                                       fp16* __restrict__ hi,
                                                       fp16* __restrict__ lo,
                                                       const float* __restrict__ w,
                                                       const float* __restrict__ b)
{
    int row = blockIdx.x;
    int tid = threadIdx.x;
    const float4 xv = *(const float4*)(in + (size_t)row * DD + tid * 4);
    float s  = xv.x + xv.y + xv.z + xv.w;
    float ss = xv.x * xv.x + xv.y * xv.y + xv.z * xv.z + xv.w * xv.w;
    #pragma unroll
    for (int o = 16; o; o >>= 1) {
        s  += __shfl_xor_sync(0xffffffffu, s,  o);
        ss += __shfl_xor_sync(0xffffffffu, ss, o);
    }
    __shared__ float red[16];
    int wid = tid >> 5;
    if ((tid & 31) == 0) { red[wid] = s; red[wid + 8] = ss; }
    __syncthreads();
    s = 0.f; ss = 0.f;
    #pragma unroll
    for (int i = 0; i < 8; i++) { s += red[i]; ss += red[i + 8]; }
    float mu   = s * (1.f / DD);
    float var  = ss * (1.f / DD) - mu * mu;
    float rstd = rsqrtf(var + 1e-5f);
    float4 o4;
    o4.x = (xv.x - mu) * rstd; o4.y = (xv.y - mu) * rstd;
    o4.z = (xv.z - mu) * rstd; o4.w = (xv.w - mu) * rstd;
    const float4 wv = *(const float4*)(w + tid * 4);
    const float4 bv = *(const float4*)(b + tid * 4);
    o4.x = o4.x * wv.x + bv.x; o4.y = o4.y * wv.y + bv.y;
    o4.z = o4.z * wv.z + bv.z; o4.w = o4.w * wv.w + bv.w;
    uint2 h, l;
    split4h(o4, h, l);
    *(uint2*)(hi + (size_t)row * DD + tid * 4) = h;
    *(uint2*)(lo + (size_t)row * DD + tid * 4) = l;
}

// ---------------- compacted LN-split of x ----------------
__global__ __launch_bounds__(256) void ln_split_gather_kernel(const float* __restrict__ in,
                                                              const int* __restrict__ idxmap,
                                                              const int* __restrict__ counts,
                                                              fp16* __restrict__ hi,
                                                              fp16* __restrict__ lo)
{
    int row = blockIdx.x;
    int b   = row >> 11;
    int j   = row & (NN - 1);
    if (j >= counts[b]) return;
    int src = idxmap[row];
    int tid = threadIdx.x;
    const float4 xv = *(const float4*)(in + ((size_t)b * NN + src) * DD + tid * 4);
    float s  = xv.x + xv.y + xv.z + xv.w;
    float ss = xv.x * xv.x + xv.y * xv.y + xv.z * xv.z + xv.w * xv.w;
    #pragma unroll
    for (int o = 16; o; o >>= 1) {
        s  += __shfl_xor_sync(0xffffffffu, s,  o);
        ss += __shfl_xor_sync(0xffffffffu, ss, o);
    }
    __shared__ float red[16];
    int wid = tid >> 5;
    if ((tid & 31) == 0) { red[wid] = s; red[wid + 8] = ss; }
    __syncthreads();
    s = 0.f; ss = 0.f;
    #pragma unroll
    for (int i = 0; i < 8; i++) { s += red[i]; ss += red[i + 8]; }
    float mu   = s * (1.f / DD);
    float var  = ss * (1.f / DD) - mu * mu;
    float rstd = rsqrtf(var + 1e-5f);
    float4 o4;
    o4.x = (xv.x - mu) * rstd; o4.y = (xv.y - mu) * rstd;
    o4.z = (xv.z - mu) * rstd; o4.w = (xv.w - mu) * rstd;
    uint2 h, l;
    split4h(o4, h, l);
    *(uint2*)(hi + (size_t)row * DD + tid * 4) = h;
    *(uint2*)(lo + (size_t)row * DD + tid * 4) = l;
}

// ---------------- all-layer generic weight split (hi plane only) ----------
__global__ __launch_bounds__(256) void split_all_kernel(const float* __restrict__ in,
                                                        fp16* __restrict__ hi,
                                                        int srcColsLog2, int dstStride, int dstOff,
                                                        size_t srcLS, size_t dstLS)
{
    int layer = blockIdx.y;
    int idx = (blockIdx.x * 256 + threadIdx.x) * 4;
    float4 v = *(const float4*)(in + layer * srcLS + idx);
    int row = idx >> srcColsLog2;
    int col = idx & ((1 << srcColsLog2) - 1);
    size_t d = layer * dstLS + (size_t)row * dstStride + dstOff + col;
    *(uint2*)(hi + d) = hi4h(v);
}

// ---------------- all-layer Wkv split: folded + unfolded-into-combined ------
__global__ __launch_bounds__(256) void split_wkv_all_kernel(const float* __restrict__ Wkv,
                                                            const float* __restrict__ lwAll,
                                                            fp16* __restrict__ fh,
                                                            fp16* __restrict__ ch)
{
    int layer = blockIdx.y;
    int idx = (blockIdx.x * 256 + threadIdx.x) * 4;      // over D*1024
    float4 v = *(const float4*)(Wkv + (size_t)layer * DD * 1024 + idx);
    int row = idx >> 10;
    int col = idx & 1023;
    size_t d = (size_t)layer * DD * NQKV + (size_t)row * NQKV + II + col;
    *(uint2*)(ch + d) = hi4h(v);
    float sc = lwAll[layer * DD + row];
    v.x *= sc; v.y *= sc; v.z *= sc; v.w *= sc;
    size_t f = (size_t)layer * DD * 1024 + idx;
    *(uint2*)(fh + f) = hi4h(v);
}

// ---------------- lat init ----------------
__global__ void init_lat_kernel(const float* __restrict__ latents, float* __restrict__ lat)
{
    int idx = blockIdx.x * 256 + threadIdx.x;
    lat[idx] = latents[idx & (LQ * DD - 1)];
}

// ---------------- all-layer biaskv ----------------
__global__ __launch_bounds__(256) void bias_kv_all_kernel(const float* __restrict__ Wkv,
                                                          const float* __restrict__ lnbAll,
                                                          float* __restrict__ bias)
{
    int layer = blockIdx.y;
    const float* W = Wkv + (size_t)layer * DD * 1024;
    const float* lnb = lnbAll + layer * DD;
    int j  = blockIdx.x * 8 + (threadIdx.x & 7);
    int dc = threadIdx.x >> 3;
    float a = 0.f;
    int d0 = dc * 32;
    #pragma unroll 8
    for (int d = d0; d < d0 + 32; d++) a += lnb[d] * W[(size_t)d * 1024 + j];
    __shared__ float red[32][8];
    red[dc][threadIdx.x & 7] = a;
    __syncthreads();
    if (threadIdx.x < 8) {
        float s = 0.f;
        #pragma unroll
        for (int i = 0; i < 32; i++) s += red[i][threadIdx.x];
        bias[layer * 1024 + blockIdx.x * 8 + threadIdx.x] = s;
    }
}

// ================= fp16x2 split-precision mma.sync GEMM =================
enum { EPI_NONE = 0, EPI_ADD = 1, EPI_GELU = 2, EPI_KV = 3, EPI_QKV = 4 };

#define GBK 32
#define AST 40
#define BST 136
#define BST2 264

__device__ __forceinline__ void mma16816h(float* d, const unsigned* a, const unsigned* b)
{
    asm volatile(
        "mma.sync.aligned.m16n8k16.row.col.f32.f16.f16.f32 "
        "{%0,%1,%2,%3}, {%4,%5,%6,%7}, {%8,%9}, {%0,%1,%2,%3};\n"
        : "+f"(d[0]), "+f"(d[1]), "+f"(d[2]), "+f"(d[3])
        : "r"(a[0]), "r"(a[1]), "r"(a[2]), "r"(a[3]), "r"(b[0]), "r"(b[1]));
}
__device__ __forceinline__ void ldsm4(unsigned* r, unsigned addr)
{
    asm volatile("ldmatrix.sync.aligned.m8n8.x4.shared.b16 {%0,%1,%2,%3}, [%4];\n"
                 : "=r"(r[0]), "=r"(r[1]), "=r"(r[2]), "=r"(r[3]) : "r"(addr));
}
__device__ __forceinline__ void ldsm4t(unsigned* r, unsigned addr)
{
    asm volatile("ldmatrix.sync.aligned.m8n8.x4.trans.shared.b16 {%0,%1,%2,%3}, [%4];\n"
                 : "=r"(r[0]), "=r"(r[1]), "=r"(r[2]), "=r"(r[3]) : "r"(addr));
}
__device__ __forceinline__ void cpasync16(unsigned s, const void* g)
{
    asm volatile("cp.async.cg.shared.global [%0], [%1], 16;\n" :: "r"(s), "l"(g));
}
#define CP_COMMIT() asm volatile("cp.async.commit_group;\n")
#define CP_WAIT1()  asm volatile("cp.async.wait_group 1;\n")

// ---------- small-GEMM variant: TM x 128, 256 threads (unchanged) ----------
template<int TM>
__global__ __launch_bounds__(256, 2) void gemm_fp16(
    const fp16* __restrict__ Ahi, const fp16* __restrict__ Alo,
    const fp16* __restrict__ Bhi,
    float* __restrict__ C, int M, int N, int K, int epi,
    const float* __restrict__ bias,
    float* __restrict__ Kout, float* __restrict__ Vout, int rowsPerB,
    const int* __restrict__ cnts,
    fp16* __restrict__ OutHi, fp16* __restrict__ OutLo)
{
    constexpr int WM16   = TM / 32;
    constexpr int A_EL   = TM * AST;
    constexpr int B_EL   = GBK * BST;
    constexpr int STAGE  = 2 * A_EL + B_EL;
    extern __shared__ __align__(16) fp16 smg[];
    unsigned base = (unsigned)__cvta_generic_to_shared(smg);

    int row0 = blockIdx.y * TM;
    int col0 = blockIdx.x << 7;

    int tid  = threadIdx.x;
    int lane = tid & 31;
    int warp = tid >> 5;
    int wm = warp & 1, wn = warp >> 1;
    int lr = (lane & 7) + (((lane >> 3) & 1) << 3);
    int lc = (lane >> 4) << 3;

    float acc[WM16][4][4];
    #pragma unroll
    for (int i = 0; i < WM16; i++)
        #pragma unroll
        for (int j = 0; j < 4; j++)
            #pragma unroll
            for (int t = 0; t < 4; t++) acc[i][j][t] = 0.f;

    auto load_stage = [&](int kt, int buf) {
        unsigned sb = base + (unsigned)buf * STAGE * 2;
        constexpr int ACH = (TM * 4) / 256;
        #pragma unroll
        for (int p = 0; p < 2; p++) {
            const fp16* Ap = p ? Alo : Ahi;
            unsigned so = sb + (unsigned)p * A_EL * 2;
            #pragma unroll
            for (int i = 0; i < ACH; i++) {
                int chunk = tid + i * 256;
                int r = chunk >> 2, c16 = chunk & 3;
                cpasync16(so + (unsigned)(r * AST + c16 * 8) * 2,
                          Ap + (size_t)(row0 + r) * K + kt + c16 * 8);
            }
        }
        {
            unsigned so = sb + (unsigned)(2 * A_EL) * 2;
            #pragma unroll
            for (int i = 0; i < 2; i++) {
                int chunk = tid + i * 256;
                int r = chunk >> 4, cc = (chunk & 15) * 8;
                cpasync16(so + (unsigned)(r * BST + cc) * 2,
                          Bhi + (size_t)(kt + r) * N + col0 + cc);
            }
        }
    };

    int NK = K / GBK;
    load_stage(0, 0);   CP_COMMIT();
    load_stage(GBK, 1); CP_COMMIT();

    for (int it = 0; it < NK; it++) {
        CP_WAIT1();
        __syncthreads();
        int buf = it % 3;
        unsigned sb  = base + (unsigned)buf * STAGE * 2;
        unsigned aHi = sb;
        unsigned aLo = sb + A_EL * 2;
        unsigned bHi = sb + 2 * A_EL * 2;

        if (it + 2 < NK) load_stage((it + 2) * GBK, (it + 2) % 3);
        CP_COMMIT();

        #pragma unroll
        for (int k16 = 0; k16 < GBK; k16 += 16) {
            unsigned bh[2][4];
            #pragma unroll
            for (int ni = 0; ni < 2; ni++) {
                unsigned off = (unsigned)((k16 + lr) * BST + wn * 32 + ni * 16 + lc) * 2;
                ldsm4t(bh[ni], bHi + off);
            }
            #pragma unroll
            for (int mi = 0; mi < WM16; mi++) {
                unsigned ah[4], al[4];
                unsigned off = (unsigned)((wm * (TM / 2) + mi * 16 + lr) * AST + k16 + lc) * 2;
                ldsm4(ah, aHi + off);
                ldsm4(al, aLo + off);
                #pragma unroll
                for (int nj = 0; nj < 4; nj++) {
                    int ni = nj >> 1, p = nj & 1;
                    mma16816h(acc[mi][nj], ah, &bh[ni][2 * p]);
                    mma16816h(acc[mi][nj], al, &bh[ni][2 * p]);
                }
            }
        }
    }

    int rbase = row0 + wm * (TM / 2) + (lane >> 2);
    int cbase = col0 + wn * 32 + (lane & 3) * 2;
    #pragma unroll
    for (int mi = 0; mi < WM16; mi++) {
        #pragma unroll
        for (int nj = 0; nj < 4; nj++) {
            #pragma unroll
            for (int half = 0; half < 2; half++) {
                int r = rbase + mi * 16 + half * 8;
                int c = cbase + nj * 8;
                float v0 = acc[mi][nj][half * 2 + 0];
                float v1 = acc[mi][nj][half * 2 + 1];
                if (epi == EPI_QKV) {
                    if (c < II) {
                        float* dst = C + (size_t)r * II + c;
                        dst[0] = v0; dst[1] = v1;
                    } else {
                        int c2 = c - II;
                        int bb = r / rowsPerB;
                        int s  = cnts[bb] + (r - bb * rowsPerB);
                        float* dst;
                        if (c2 < II)
                            dst = Kout + (((size_t)bb * HH + (c2 >> 6)) * SSQ + s) * DHD + (c2 & 63);
                        else
                            dst = Vout + (((size_t)bb * HH + ((c2 - II) >> 6)) * SSQ + s) * DHD + ((c2 - II) & 63);
                        dst[0] = v0; dst[1] = v1;
                    }
                } else if (epi == EPI_GELU) {
                    float h0 = 0.5f * v0 * (1.f + erff(v0 * 0.70710678118654752f));
                    float h1 = 0.5f * v1 * (1.f + erff(v1 * 0.70710678118654752f));
                    float t0 = __half2float(__float2half_rn(h0));
                    float t1 = __half2float(__float2half_rn(h1));
                    *(unsigned*)(OutHi + (size_t)r * N + c) = pack2h(h0, h1);
                    *(unsigned*)(OutLo + (size_t)r * N + c) = pack2h(h0 - t0, h1 - t1);
                } else {
                    float* dst = C + (size_t)r * N + c;
                    if (epi == EPI_ADD) { v0 += dst[0]; v1 += dst[1]; }
                    dst[0] = v0; dst[1] = v1;
                }
            }
        }
    }
}

// ---------- kv-x GEMM: 128 x 256 tile, 512 threads, high arithmetic intensity ----------
#define KV_A_EL (128 * AST)
#define KV_B_EL (GBK * BST2)
#define KV_STAGE (2 * KV_A_EL + KV_B_EL)
#define SMEMKV (3 * KV_STAGE * 2)

__global__ __launch_bounds__(512, 1) void gemm_kv256(
    const fp16* __restrict__ Ahi, const fp16* __restrict__ Alo,
    const fp16* __restrict__ Bhi,
    const float* __restrict__ bias,
    float* __restrict__ Kout, float* __restrict__ Vout,
    const int* __restrict__ cnts)
{
    extern __shared__ __align__(16) fp16 smg[];
    unsigned base = (unsigned)__cvta_generic_to_shared(smg);

    int row0 = blockIdx.y * 128;
    int col0 = blockIdx.x * 256;       // N = 1024

    int bb = row0 >> 11;
    int cnt0 = cnts[bb];
    if ((row0 & (NN - 1)) >= cnt0) return;

    int tid  = threadIdx.x;
    int lane = tid & 31;
    int warp = tid >> 5;               // 0..15
    int wm = warp & 3, wn = warp >> 2; // 4 x 4 warps; warp tile 32 x 64
    int lr = (lane & 7) + (((lane >> 3) & 1) << 3);
    int lc = (lane >> 4) << 3;

    float acc[2][8][4];
    #pragma unroll
    for (int i = 0; i < 2; i++)
        #pragma unroll
        for (int j = 0; j < 8; j++)
            #pragma unroll
            for (int t = 0; t < 4; t++) acc[i][j][t] = 0.f;

    auto load_stage = [&](int kt, int buf) {
        unsigned sb = base + (unsigned)buf * KV_STAGE * 2;
        #pragma unroll
        for (int p = 0; p < 2; p++) {
            const fp16* Ap = p ? Alo : Ahi;
            unsigned so = sb + (unsigned)p * KV_A_EL * 2;
            int r = tid >> 2, c16 = tid & 3;           // 512 chunks, 1/thread
            cpasync16(so + (unsigned)(r * AST + c16 * 8) * 2,
                      Ap + (size_t)(row0 + r) * DD + kt + c16 * 8);
        }
        {
            unsigned so = sb + (unsigned)(2 * KV_A_EL) * 2;
            #pragma unroll
            for (int i = 0; i < 2; i++) {
                int chunk = tid + i * 512;             // 1024 chunks
                int r = chunk >> 5, cc = (chunk & 31) * 8;
                cpasync16(so + (unsigned)(r * BST2 + cc) * 2,
                          Bhi + (size_t)(kt + r) * 1024 + col0 + cc);
            }
        }
    };

    const int NK = DD / GBK;           // 32
    load_stage(0, 0);   CP_COMMIT();
    load_stage(GBK, 1); CP_COMMIT();

    for (int it = 0; it < NK; it++) {
        CP_WAIT1();
        __syncthreads();
        int buf = it % 3;
        unsigned sb  = base + (unsigned)buf * KV_STAGE * 2;
        unsigned aHi = sb;
        unsigned aLo = sb + KV_A_EL * 2;
        unsigned bHi = sb + 2 * KV_A_EL * 2;

        if (it + 2 < NK) load_stage((it + 2) * GBK, (it + 2) % 3);
        CP_COMMIT();

        #pragma unroll
        for (int k16 = 0; k16 < GBK; k16 += 16) {
            unsigned bh[4][4];
            #pragma unroll
            for (int ni = 0; ni < 4; ni++) {
                unsigned off = (unsigned)((k16 + lr) * BST2 + wn * 64 + ni * 16 + lc) * 2;
                ldsm4t(bh[ni], bHi + off);
            }
            #pragma unroll
            for (int mi = 0; mi < 2; mi++) {
                unsigned ah[4], al[4];
                unsigned off = (unsigned)((wm * 32 + mi * 16 + lr) * AST + k16 + lc) * 2;
                ldsm4(ah, aHi + off);
                ldsm4(al, aLo + off);
                #pragma unroll
                for (int nj = 0; nj < 8; nj++) {
                    int ni = nj >> 1, p = nj & 1;
                    mma16816h(acc[mi][nj], ah, &bh[ni][2 * p]);
                    mma16816h(acc[mi][nj], al, &bh[ni][2 * p]);
                }
            }
        }
    }

    // epilogue: bias + scatter into K/V
    int rbase = row0 + wm * 32 + (lane >> 2);
    int cbase = col0 + wn * 64 + (lane & 3) * 2;
    #pragma unroll
    for (int mi = 0; mi < 2; mi++) {
        #pragma unroll
        for (int nj = 0; nj < 8; nj++) {
            #pragma unroll
            for (int half = 0; half < 2; half++) {
                int r = rbase + mi * 16 + half * 8;
                int s = r & (NN - 1);
                if (s < cnt0) {
                    int c = cbase + nj * 8;
                    float v0 = acc[mi][nj][half * 2 + 0] + bias[c];
                    float v1 = acc[mi][nj][half * 2 + 1] + bias[c + 1];
                    float* dst;
                    if (c < II)
                        dst = Kout + (((size_t)bb * HH + (c >> 6)) * SSQ + s) * DHD + (c & 63);
                    else {
                        int c2 = c - II;
                        dst = Vout + (((size_t)bb * HH + (c2 >> 6)) * SSQ + s) * DHD + (c2 & 63);
                    }
                    dst[0] = v0; dst[1] = v1;
                }
            }
        }
    }
}

// ---------------- fused flash attention over compacted keys ----------------
#define AT2  68
#define ATTN_SMEM (((size_t)(32 + 64 + 64 + 32) * AT2) * 4)

__global__ __launch_bounds__(256) void attn_kernel(
    const float* __restrict__ q, const float* __restrict__ kg, const float* __restrict__ vg,
    const int* __restrict__ counts, fp16* __restrict__ attHi, fp16* __restrict__ attLo)
{
    extern __shared__ float sm[];
    float* qs  = sm;
    float* kT  = sm + 32 * AT2;
    float* vs  = sm + (32 + 64) * AT2;
    float* ps  = sm + (32 + 128) * AT2;

    int blk = blockIdx.x;
    int bh = blk >> 1, half = blk & 1;
    int b = bh >> 3, h = bh & 7;
    int tid = threadIdx.x;
    int qr = tid >> 3;
    int j0 = (tid & 7) * 8;

    int Sv = counts[b] + LQ;
    int nT = (Sv + 63) >> 6;

    const float* qbase = q + ((size_t)(b * LQ) + half * 32) * II + h * DHD;
    for (int idx = tid; idx < 32 * 16; idx += 256) {
        int r = idx >> 4, d4 = (idx & 15) << 2;
        *(float4*)&qs[r * AT2 + d4] = *(const float4*)&qbase[(size_t)r * II + d4];
    }

    float acc[8];
    #pragma unroll
    for (int i = 0; i < 8; i++) acc[i] = 0.f;
    float m = -1e30f, l = 0.f;

    const float* kb = kg + ((size_t)b * HH + h) * SSQ * DHD;
    const float* vb = vg + ((size_t)b * HH + h) * SSQ * DHD;

    for (int t = 0; t < nT; t++) {
        int s0 = t * 64;
        __syncthreads();
        for (int idx = tid; idx < 64 * 16; idx += 256) {
            int r = idx >> 4, d4 = (idx & 15) << 2;
            float4 k4 = *(const float4*)&kb[(size_t)(s0 + r) * DHD + d4];
            kT[(d4 + 0) * AT2 + r] = k4.x;
            kT[(d4 + 1) * AT2 + r] = k4.y;
            kT[(d4 + 2) * AT2 + r] = k4.z;
            kT[(d4 + 3) * AT2 + r] = k4.w;
            *(float4*)&vs[r * AT2 + d4] = *(const float4*)&vb[(size_t)(s0 + r) * DHD + d4];
        }
        __syncthreads();

        float sc[8];
        #pragma unroll
        for (int j = 0; j < 8; j++) sc[j] = 0.f;
        const float* qrow = &qs[qr * AT2];
        #pragma unroll 8
        for (int d = 0; d < 64; d++) {
            float qv = qrow[d];
            float4 kA = *(const float4*)&kT[d * AT2 + j0];
            float4 kB = *(const float4*)&kT[d * AT2 + j0 + 4];
            sc[0] += qv * kA.x; sc[1] += qv * kA.y; sc[2] += qv * kA.z; sc[3] += qv * kA.w;
            sc[4] += qv * kB.x; sc[5] += qv * kB.y; sc[6] += qv * kB.z; sc[7] += qv * kB.w;
        }
        float tmax = -1e30f;
        #pragma unroll
        for (int j = 0; j < 8; j++) {
            float s = sc[j] * 0.125f;
            if (s0 + j0 + j >= Sv) s = -1e30f;
            sc[j] = s;
            tmax = fmaxf(tmax, s);
        }
        tmax = fmaxf(tmax, __shfl_xor_sync(0xffffffffu, tmax, 1));
        tmax = fmaxf(tmax, __shfl_xor_sync(0xffffffffu, tmax, 2));
        tmax = fmaxf(tmax, __shfl_xor_sync(0xffffffffu, tmax, 4));
        float mnew = fmaxf(m, tmax);
        float corr = __expf(m - mnew);
        float psum = 0.f;
        #pragma unroll
        for (int j = 0; j < 8; j++) {
            float p = __expf(sc[j] - mnew);
            ps[qr * AT2 + j0 + j] = p;
            psum += p;
        }
        psum += __shfl_xor_sync(0xffffffffu, psum, 1);
        psum += __shfl_xor_sync(0xffffffffu, psum, 2);
        psum += __shfl_xor_sync(0xffffffffu, psum, 4);
        l = l * corr + psum;
        m = mnew;
        #pragma unroll
        for (int i = 0; i < 8; i++) acc[i] *= corr;
        __syncwarp();

        #pragma unroll 4
        for (int j = 0; j < 64; j++) {
            float p = ps[qr * AT2 + j];
            float4 v0 = *(const float4*)&vs[j * AT2 + j0];
            float4 v1 = *(const float4*)&vs[j * AT2 + j0 + 4];
            acc[0] += p * v0.x; acc[1] += p * v0.y; acc[2] += p * v0.z; acc[3] += p * v0.w;
            acc[4] += p * v1.x; acc[5] += p * v1.y; acc[6] += p * v1.z; acc[7] += p * v1.w;
        }
    }

    float invl = 1.f / l;
    size_t obase = ((size_t)(b * LQ) + half * 32 + qr) * II + h * DHD + j0;
    float o[8];
    #pragma unroll
    for (int i = 0; i < 8; i++) o[i] = acc[i] * invl;
    float th[8];
    #pragma unroll
    for (int i = 0; i < 8; i++) th[i] = __half2float(__float2half_rn(o[i]));
    *(uint2*)(attHi + obase)     = make_uint2(pack2h(o[0], o[1]), pack2h(o[2], o[3]));
    *(uint2*)(attHi + obase + 4) = make_uint2(pack2h(o[4], o[5]), pack2h(o[6], o[7]));
    *(uint2*)(attLo + obase)     = make_uint2(pack2h(o[0]-th[0], o[1]-th[1]), pack2h(o[2]-th[2], o[3]-th[3]));
    *(uint2*)(attLo + obase + 4) = make_uint2(pack2h(o[4]-th[4], o[5]-th[5]), pack2h(o[6]-th[6], o[7]-th[7]));
}

// ---------------- host orchestration ----------------
#define SMEM64  ((3 * (2 * 64 * AST + GBK * BST)) * 2)

extern "C" void kernel_launch(void* const* d_in, const int* in_sizes, int n_in,
                              void* d_out, int out_size)
{
    (void)in_sizes; (void)n_in; (void)out_size;
    const float* x        = (const float*)d_in[0];
    const int*   mask     = (const int*)  d_in[1];
    const float* latents  = (const float*)d_in[2];
    const float* ln_m_w   = (const float*)d_in[3];
    const float* ln_m_b   = (const float*)d_in[4];
    const float* ln_l_w   = (const float*)d_in[5];
    const float* ln_l_b   = (const float*)d_in[6];
    const float* Wq       = (const float*)d_in[7];
    const float* Wkv      = (const float*)d_in[8];
    const float* Wo       = (const float*)d_in[9];
    const float* ff_ln_w  = (const float*)d_in[10];
    const float* ff_ln_b  = (const float*)d_in[11];
    const float* W1       = (const float*)d_in[12];
    const float* W2       = (const float*)d_in[13];
    const float* norm_w   = (const float*)d_in[14];
    const float* norm_b   = (const float*)d_in[15];
    float* out = (float*)d_out;

    fp16 *xh, *xl, *lnlh, *lnll, *lnfh, *lnfl, *atth, *attl, *hfh, *hfl;
    fp16 *cmbh, *wkvph, *woh, *w1h, *w2h;
    float *lat, *qb, *kb, *vb, *biaskv;
    int *idxmap, *counts;
    cudaGetSymbolAddress((void**)&xh, g_xh);     cudaGetSymbolAddress((void**)&xl, g_xl);
    cudaGetSymbolAddress((void**)&lnlh, g_lnlh); cudaGetSymbolAddress((void**)&lnll, g_lnll);
    cudaGetSymbolAddress((void**)&lnfh, g_lnfh); cudaGetSymbolAddress((void**)&lnfl, g_lnfl);
    cudaGetSymbolAddress((void**)&atth, g_atth); cudaGetSymbolAddress((void**)&attl, g_attl);
    cudaGetSymbolAddress((void**)&hfh, g_hfh);   cudaGetSymbolAddress((void**)&hfl, g_hfl);
    cudaGetSymbolAddress((void**)&cmbh, g_cmbh);
    cudaGetSymbolAddress((void**)&wkvph, g_wkvph);
    cudaGetSymbolAddress((void**)&woh, g_woh);
    cudaGetSymbolAddress((void**)&w1h, g_w1h);
    cudaGetSymbolAddress((void**)&w2h, g_w2h);
    cudaGetSymbolAddress((void**)&lat, g_lat);
    cudaGetSymbolAddress((void**)&qb, g_q);
    cudaGetSymbolAddress((void**)&kb, g_k);
    cudaGetSymbolAddress((void**)&vb, g_v);
    cudaGetSymbolAddress((void**)&biaskv, g_biaskv);
    cudaGetSymbolAddress((void**)&idxmap, g_idxmap);
    cudaGetSymbolAddress((void**)&counts, g_counts);

    cudaFuncSetAttribute((const void*)gemm_kv256,     cudaFuncAttributeMaxDynamicSharedMemorySize, SMEMKV);
    cudaFuncSetAttribute((const void*)gemm_fp16<64>,  cudaFuncAttributeMaxDynamicSharedMemorySize, SMEM64);
    cudaFuncSetAttribute((const void*)attn_kernel,    cudaFuncAttributeMaxDynamicSharedMemorySize, (int)ATTN_SMEM);

    cudaStream_t s2;
    cudaStreamCreateWithFlags(&s2, cudaStreamNonBlocking);
    cudaEvent_t evFork, evKV[NDEPTH];
    cudaEventCreateWithFlags(&evFork, cudaEventDisableTiming);
    for (int i = 0; i < NDEPTH; i++)
        cudaEventCreateWithFlags(&evKV[i], cudaEventDisableTiming);

    // ---- prologue: compaction, xhat, lat, ALL weight prep ----
    scan_mask_kernel<<<BB, 1024>>>(mask, idxmap, counts);
    ln_split_gather_kernel<<<BB * NN, 256>>>(x, idxmap, counts, xh, xl);
    init_lat_kernel<<<BB * LQ * DD / 256, 256>>>(latents, lat);

    split_wkv_all_kernel<<<dim3(1024, NDEPTH), 256>>>(Wkv, ln_m_w, wkvph, cmbh);
    split_all_kernel<<<dim3(512, NDEPTH), 256>>>(Wq, cmbh, 9, NQKV, 0,
                                                 (size_t)DD * II, (size_t)DD * NQKV);
    split_all_kernel<<<dim3(512, NDEPTH), 256>>>(Wo, woh, 10, DD, 0,
                                                 (size_t)II * DD, (size_t)II * DD);
    split_all_kernel<<<dim3(4096, NDEPTH), 256>>>(W1, w1h, 12, FFD, 0,
                                                  (size_t)DD * FFD, (size_t)DD * FFD);
    split_all_kernel<<<dim3(4096, NDEPTH), 256>>>(W2, w2h, 10, DD, 0,
                                                  (size_t)FFD * DD, (size_t)FFD * DD);
    bias_kv_all_kernel<<<dim3(128, NDEPTH), 256>>>(Wkv, ln_m_b, biaskv);

    // ---- fork: six kv-x GEMMs (128x256 tiles) on side stream ----
    cudaEventRecord(evFork, 0);
    cudaStreamWaitEvent(s2, evFork, 0);
    for (int i = 0; i < NDEPTH; i++) {
        gemm_kv256<<<dim3(2 * II / 256, BB * NN / 128), 512, SMEMKV, s2>>>(
            xh, xl, wkvph + (size_t)i * DD * 2 * II,
            biaskv + i * 2 * II, kb + (size_t)i * KVSZ, vb + (size_t)i * KVSZ, counts);
        cudaEventRecord(evKV[i], s2);
    }

    // ---- main loop: lat path ----
    for (int i = 0; i < NDEPTH; i++) {
        float* kb_i = kb + (size_t)i * KVSZ;
        float* vb_i = vb + (size_t)i * KVSZ;

        ln_split_kernel<<<BB * LQ, 256>>>(lat, lnlh, lnll, ln_l_w + i * DD, ln_l_b + i * DD);

        gemm_fp16<64><<<dim3(NQKV / 128, BB * LQ / 64), 256, SMEM64>>>(
            lnlh, lnll, cmbh + (size_t)i * DD * NQKV,
            qb, BB * LQ, NQKV, DD, EPI_QKV,
            nullptr, kb_i, vb_i, LQ, counts, nullptr, nullptr);

        cudaStreamWaitEvent(0, evKV[i], 0);
        attn_kernel<<<BB * HH * 2, 256, ATTN_SMEM>>>(qb, kb_i, vb_i, counts, atth, attl);

        gemm_fp16<64><<<dim3(DD / 128, BB * LQ / 64), 256, SMEM64>>>(
            atth, attl, woh + (size_t)i * II * DD,
            lat, BB * LQ, DD, II, EPI_ADD,
            nullptr, nullptr, nullptr, 0, counts, nullptr, nullptr);

        ln_split_kernel<<<BB * LQ, 256>>>(lat, lnfh, lnfl, ff_ln_w + i * DD, ff_ln_b + i * DD);
        gemm_fp16<64><<<dim3(FFD / 128, BB * LQ / 64), 256, SMEM64>>>(
            lnfh, lnfl, w1h + (size_t)i * DD * FFD,
            nullptr, BB * LQ, FFD, DD, EPI_GELU,
            nullptr, nullptr, nullptr, 0, counts, hfh, hfl);
        gemm_fp16<64><<<dim3(DD / 128, BB * LQ / 64), 256, SMEM64>>>(
            hfh, hfl, w2h + (size_t)i * FFD * DD,
            lat, BB * LQ, DD, FFD, EPI_ADD,
            nullptr, nullptr, nullptr, 0, counts, nullptr, nullptr);
    }

    ln_kernel<<<BB * LQ, 256>>>(lat, out, norm_w, norm_b);
}

// round 14
// speedup vs baseline: 3.6078x; 1.7770x over previous
#include <cuda_runtime.h>
#include <cuda_fp16.h>
#include <stdint.h>
#include <math.h>

// ---------------- problem constants ----------------
#define BB   16
#define NN   2048
#define DD   1024
#define HH   8
#define DHD  64
#define II   512           // H*DH
#define LQ   64
#define SSQ  2112          // N + L
#define NDEPTH 6
#define FFD  4096
#define NQKV 1536          // II + 2*II

#define KVSZ ((size_t)BB * HH * SSQ * DHD)

typedef __half fp16;

// ---------------- scratch ----------------
__device__ fp16 g_xh[(size_t)BB * NN * DD];     // compacted xhat hi
__device__ fp16 g_xl[(size_t)BB * NN * DD];     // compacted xhat lo
__device__ fp16 g_lnlh[BB * LQ * DD],  g_lnll[BB * LQ * DD];
__device__ fp16 g_lnfh[BB * LQ * DD],  g_lnfl[BB * LQ * DD];
__device__ fp16 g_atth[BB * LQ * II],  g_attl[BB * LQ * II];
__device__ fp16 g_hfh [BB * LQ * FFD], g_hfl [BB * LQ * FFD];
// per-layer weight planes (hi only — B side of every GEMM)
__device__ fp16 g_cmbh[(size_t)NDEPTH * DD * NQKV];
__device__ fp16 g_wkvph[(size_t)NDEPTH * DD * 2 * II];
__device__ fp16 g_woh [(size_t)NDEPTH * II * DD];
__device__ fp16 g_w1h [(size_t)NDEPTH * DD * FFD];
__device__ fp16 g_w2h [(size_t)NDEPTH * FFD * DD];
__device__ float g_biaskv[NDEPTH * 2 * II];
__device__ float g_lat[BB * LQ * DD];
__device__ fp16  g_q  [BB * LQ * II];
__device__ fp16  g_k  [(size_t)NDEPTH * KVSZ];
__device__ fp16  g_v  [(size_t)NDEPTH * KVSZ];
__device__ int   g_idxmap[BB * NN];
__device__ int   g_counts[BB];

// ---------------- helpers ----------------
__device__ __forceinline__ unsigned pack2h(float x, float y)
{
    return (unsigned)__half_as_ushort(__float2half_rn(x))
         | ((unsigned)__half_as_ushort(__float2half_rn(y)) << 16);
}
__device__ __forceinline__ void split4h(float4 v, uint2& hi, uint2& lo)
{
    float hx = __half2float(__float2half_rn(v.x));
    float hy = __half2float(__float2half_rn(v.y));
    float hz = __half2float(__float2half_rn(v.z));
    float hw = __half2float(__float2half_rn(v.w));
    hi = make_uint2(pack2h(v.x, v.y), pack2h(v.z, v.w));
    lo = make_uint2(pack2h(v.x - hx, v.y - hy), pack2h(v.z - hz, v.w - hw));
}
__device__ __forceinline__ uint2 hi4h(float4 v)
{
    return make_uint2(pack2h(v.x, v.y), pack2h(v.z, v.w));
}

// ---------------- mask compaction: per-batch scan ----------------
__global__ __launch_bounds__(1024) void scan_mask_kernel(const int* __restrict__ mask,
                                                         int* __restrict__ idxmap,
                                                         int* __restrict__ counts)
{
    __shared__ int sh[1024];
    int b = blockIdx.x;
    int t = threadIdx.x;
    int v0 = (mask[b * NN + 2 * t]     == 0) ? 1 : 0;
    int v1 = (mask[b * NN + 2 * t + 1] == 0) ? 1 : 0;
    sh[t] = v0 + v1;
    __syncthreads();
    for (int off = 1; off < 1024; off <<= 1) {
        int x = 0;
        if (t >= off) x = sh[t - off];
        __syncthreads();
        if (t >= off) sh[t] += x;
        __syncthreads();
    }
    int incl = sh[t];
    int excl = incl - v0 - v1;
    if (v0) idxmap[b * NN + excl] = 2 * t;
    if (v1) idxmap[b * NN + excl + v0] = 2 * t + 1;
    if (t == 1023) counts[b] = incl;
}

// ---------------- LayerNorm (fp32 out, final layer) ----------------
__global__ __launch_bounds__(256) void ln_kernel(const float* __restrict__ in,
                                                 float* __restrict__ out,
                                                 const float* __restrict__ w,
                                                 const float* __restrict__ b)
{
    int row = blockIdx.x;
    int tid = threadIdx.x;
    const float4 xv = *(const float4*)(in + (size_t)row * DD + tid * 4);
    float s  = xv.x + xv.y + xv.z + xv.w;
    float ss = xv.x * xv.x + xv.y * xv.y + xv.z * xv.z + xv.w * xv.w;
    #pragma unroll
    for (int o = 16; o; o >>= 1) {
        s  += __shfl_xor_sync(0xffffffffu, s,  o);
        ss += __shfl_xor_sync(0xffffffffu, ss, o);
    }
    __shared__ float red[16];
    int wid = tid >> 5;
    if ((tid & 31) == 0) { red[wid] = s; red[wid + 8] = ss; }
    __syncthreads();
    s = 0.f; ss = 0.f;
    #pragma unroll
    for (int i = 0; i < 8; i++) { s += red[i]; ss += red[i + 8]; }
    float mu   = s * (1.f / DD);
    float var  = ss * (1.f / DD) - mu * mu;
    float rstd = rsqrtf(var + 1e-5f);
    float4 o4;
    o4.x = (xv.x - mu) * rstd; o4.y = (xv.y - mu) * rstd;
    o4.z = (xv.z - mu) * rstd; o4.w = (xv.w - mu) * rstd;
    const float4 wv = *(const float4*)(w + tid * 4);
    const float4 bv = *(const float4*)(b + tid * 4);
    o4.x = o4.x * wv.x + bv.x; o4.y = o4.y * wv.y + bv.y;
    o4.z = o4.z * wv.z + bv.z; o4.w = o4.w * wv.w + bv.w;
    *(float4*)(out + (size_t)row * DD + tid * 4) = o4;
}

// ---------------- LayerNorm -> split fp16 hi/lo ----------------
__global__ __launch_bounds__(256) void ln_split_kernel(const float* __restrict__ in,
                                                       fp16* __restrict__ hi,
                                                       fp16* __restrict__ lo,
                                                       const float* __restrict__ w,
                                                       const float* __restrict__ b)
{
    int row = blockIdx.x;
    int tid = threadIdx.x;
    const float4 xv = *(const float4*)(in + (size_t)row * DD + tid * 4);
    float s  = xv.x + xv.y + xv.z + xv.w;
    float ss = xv.x * xv.x + xv.y * xv.y + xv.z * xv.z + xv.w * xv.w;
    #pragma unroll
    for (int o = 16; o; o >>= 1) {
        s  += __shfl_xor_sync(0xffffffffu, s,  o);
        ss += __shfl_xor_sync(0xffffffffu, ss, o);
    }
    __shared__ float red[16];
    int wid = tid >> 5;
    if ((tid & 31) == 0) { red[wid] = s; red[wid + 8] = ss; }
    __syncthreads();
    s = 0.f; ss = 0.f;
    #pragma unroll
    for (int i = 0; i < 8; i++) { s += red[i]; ss += red[i + 8]; }
    float mu   = s * (1.f / DD);
    float var  = ss * (1.f / DD) - mu * mu;
    float rstd = rsqrtf(var + 1e-5f);
    float4 o4;
    o4.x = (xv.x - mu) * rstd; o4.y = (xv.y - mu) * rstd;
    o4.z = (xv.z - mu) * rstd; o4.w = (xv.w - mu) * rstd;
    const float4 wv = *(const float4*)(w + tid * 4);
    const float4 bv = *(const float4*)(b + tid * 4);
    o4.x = o4.x * wv.x + bv.x; o4.y = o4.y * wv.y + bv.y;
    o4.z = o4.z * wv.z + bv.z; o4.w = o4.w * wv.w + bv.w;
    uint2 h, l;
    split4h(o4, h, l);
    *(uint2*)(hi + (size_t)row * DD + tid * 4) = h;
    *(uint2*)(lo + (size_t)row * DD + tid * 4) = l;
}

// ---------------- compacted LN-split of x ----------------
__global__ __launch_bounds__(256) void ln_split_gather_kernel(const float* __restrict__ in,
                                                              const int* __restrict__ idxmap,
                                                              const int* __restrict__ counts,
                                                              fp16* __restrict__ hi,
                                                              fp16* __restrict__ lo)
{
    int row = blockIdx.x;
    int b   = row >> 11;
    int j   = row & (NN - 1);
    if (j >= counts[b]) return;
    int src = idxmap[row];
    int tid = threadIdx.x;
    const float4 xv = *(const float4*)(in + ((size_t)b * NN + src) * DD + tid * 4);
    float s  = xv.x + xv.y + xv.z + xv.w;
    float ss = xv.x * xv.x + xv.y * xv.y + xv.z * xv.z + xv.w * xv.w;
    #pragma unroll
    for (int o = 16; o; o >>= 1) {
        s  += __shfl_xor_sync(0xffffffffu, s,  o);
        ss += __shfl_xor_sync(0xffffffffu, ss, o);
    }
    __shared__ float red[16];
    int wid = tid >> 5;
    if ((tid & 31) == 0) { red[wid] = s; red[wid + 8] = ss; }
    __syncthreads();
    s = 0.f; ss = 0.f;
    #pragma unroll
    for (int i = 0; i < 8; i++) { s += red[i]; ss += red[i + 8]; }
    float mu   = s * (1.f / DD);
    float var  = ss * (1.f / DD) - mu * mu;
    float rstd = rsqrtf(var + 1e-5f);
    float4 o4;
    o4.x = (xv.x - mu) * rstd; o4.y = (xv.y - mu) * rstd;
    o4.z = (xv.z - mu) * rstd; o4.w = (xv.w - mu) * rstd;
    uint2 h, l;
    split4h(o4, h, l);
    *(uint2*)(hi + (size_t)row * DD + tid * 4) = h;
    *(uint2*)(lo + (size_t)row * DD + tid * 4) = l;
}

// ---------------- all-layer generic weight split (hi plane only) ----------
__global__ __launch_bounds__(256) void split_all_kernel(const float* __restrict__ in,
                                                        fp16* __restrict__ hi,
                                                        int srcColsLog2, int dstStride, int dstOff,
                                                        size_t srcLS, size_t dstLS)
{
    int layer = blockIdx.y;
    int idx = (blockIdx.x * 256 + threadIdx.x) * 4;
    float4 v = *(const float4*)(in + layer * srcLS + idx);
    int row = idx >> srcColsLog2;
    int col = idx & ((1 << srcColsLog2) - 1);
    size_t d = layer * dstLS + (size_t)row * dstStride + dstOff + col;
    *(uint2*)(hi + d) = hi4h(v);
}

// ---------------- all-layer Wkv split ----------------
__global__ __launch_bounds__(256) void split_wkv_all_kernel(const float* __restrict__ Wkv,
                                                            const float* __restrict__ lwAll,
                                                            fp16* __restrict__ fh,
                                                            fp16* __restrict__ ch)
{
    int layer = blockIdx.y;
    int idx = (blockIdx.x * 256 + threadIdx.x) * 4;
    float4 v = *(const float4*)(Wkv + (size_t)layer * DD * 1024 + idx);
    int row = idx >> 10;
    int col = idx & 1023;
    size_t d = (size_t)layer * DD * NQKV + (size_t)row * NQKV + II + col;
    *(uint2*)(ch + d) = hi4h(v);
    float sc = lwAll[layer * DD + row];
    v.x *= sc; v.y *= sc; v.z *= sc; v.w *= sc;
    size_t f = (size_t)layer * DD * 1024 + idx;
    *(uint2*)(fh + f) = hi4h(v);
}

// ---------------- lat init ----------------
__global__ void init_lat_kernel(const float* __restrict__ latents, float* __restrict__ lat)
{
    int idx = blockIdx.x * 256 + threadIdx.x;
    lat[idx] = latents[idx & (LQ * DD - 1)];
}

// ---------------- all-layer biaskv ----------------
__global__ __launch_bounds__(256) void bias_kv_all_kernel(const float* __restrict__ Wkv,
                                                          const float* __restrict__ lnbAll,
                                                          float* __restrict__ bias)
{
    int layer = blockIdx.y;
    const float* W = Wkv + (size_t)layer * DD * 1024;
    const float* lnb = lnbAll + layer * DD;
    int j  = blockIdx.x * 8 + (threadIdx.x & 7);
    int dc = threadIdx.x >> 3;
    float a = 0.f;
    int d0 = dc * 32;
    #pragma unroll 8
    for (int d = d0; d < d0 + 32; d++) a += lnb[d] * W[(size_t)d * 1024 + j];
    __shared__ float red[32][8];
    red[dc][threadIdx.x & 7] = a;
    __syncthreads();
    if (threadIdx.x < 8) {
        float s = 0.f;
        #pragma unroll
        for (int i = 0; i < 32; i++) s += red[i][threadIdx.x];
        bias[layer * 1024 + blockIdx.x * 8 + threadIdx.x] = s;
    }
}

// ================= fp16x2 split-precision mma.sync GEMM =================
enum { EPI_NONE = 0, EPI_ADD = 1, EPI_GELU = 2, EPI_KV = 3, EPI_QKV = 4 };

#define GBK 32
#define AST 40
#define BST 136
#define BST2 264

__device__ __forceinline__ void mma16816h(float* d, const unsigned* a, const unsigned* b)
{
    asm volatile(
        "mma.sync.aligned.m16n8k16.row.col.f32.f16.f16.f32 "
        "{%0,%1,%2,%3}, {%4,%5,%6,%7}, {%8,%9}, {%0,%1,%2,%3};\n"
        : "+f"(d[0]), "+f"(d[1]), "+f"(d[2]), "+f"(d[3])
        : "r"(a[0]), "r"(a[1]), "r"(a[2]), "r"(a[3]), "r"(b[0]), "r"(b[1]));
}
__device__ __forceinline__ void mma16816h2(float* d, const unsigned* a, unsigned b0, unsigned b1)
{
    asm volatile(
        "mma.sync.aligned.m16n8k16.row.col.f32.f16.f16.f32 "
        "{%0,%1,%2,%3}, {%4,%5,%6,%7}, {%8,%9}, {%0,%1,%2,%3};\n"
        : "+f"(d[0]), "+f"(d[1]), "+f"(d[2]), "+f"(d[3])
        : "r"(a[0]), "r"(a[1]), "r"(a[2]), "r"(a[3]), "r"(b0), "r"(b1));
}
__device__ __forceinline__ void ldsm4(unsigned* r, unsigned addr)
{
    asm volatile("ldmatrix.sync.aligned.m8n8.x4.shared.b16 {%0,%1,%2,%3}, [%4];\n"
                 : "=r"(r[0]), "=r"(r[1]), "=r"(r[2]), "=r"(r[3]) : "r"(addr));
}
__device__ __forceinline__ void ldsm4t(unsigned* r, unsigned addr)
{
    asm volatile("ldmatrix.sync.aligned.m8n8.x4.trans.shared.b16 {%0,%1,%2,%3}, [%4];\n"
                 : "=r"(r[0]), "=r"(r[1]), "=r"(r[2]), "=r"(r[3]) : "r"(addr));
}
__device__ __forceinline__ void cpasync16(unsigned s, const void* g)
{
    asm volatile("cp.async.cg.shared.global [%0], [%1], 16;\n" :: "r"(s), "l"(g));
}
#define CP_COMMIT() asm volatile("cp.async.commit_group;\n")
#define CP_WAIT1()  asm volatile("cp.async.wait_group 1;\n")

// ---------- small-GEMM variant: TM x 128, 256 threads ----------
template<int TM>
__global__ __launch_bounds__(256, 2) void gemm_fp16(
    const fp16* __restrict__ Ahi, const fp16* __restrict__ Alo,
    const fp16* __restrict__ Bhi,
    float* __restrict__ C, int M, int N, int K, int epi,
    const float* __restrict__ bias,
    fp16* __restrict__ Kout, fp16* __restrict__ Vout, int rowsPerB,
    const int* __restrict__ cnts,
    fp16* __restrict__ OutHi, fp16* __restrict__ OutLo)
{
    constexpr int WM16   = TM / 32;
    constexpr int A_EL   = TM * AST;
    constexpr int B_EL   = GBK * BST;
    constexpr int STAGE  = 2 * A_EL + B_EL;
    extern __shared__ __align__(16) fp16 smg[];
    unsigned base = (unsigned)__cvta_generic_to_shared(smg);

    int row0 = blockIdx.y * TM;
    int col0 = blockIdx.x << 7;

    int tid  = threadIdx.x;
    int lane = tid & 31;
    int warp = tid >> 5;
    int wm = warp & 1, wn = warp >> 1;
    int lr = (lane & 7) + (((lane >> 3) & 1) << 3);
    int lc = (lane >> 4) << 3;

    float acc[WM16][4][4];
    #pragma unroll
    for (int i = 0; i < WM16; i++)
        #pragma unroll
        for (int j = 0; j < 4; j++)
            #pragma unroll
            for (int t = 0; t < 4; t++) acc[i][j][t] = 0.f;

    auto load_stage = [&](int kt, int buf) {
        unsigned sb = base + (unsigned)buf * STAGE * 2;
        constexpr int ACH = (TM * 4) / 256;
        #pragma unroll
        for (int p = 0; p < 2; p++) {
            const fp16* Ap = p ? Alo : Ahi;
            unsigned so = sb + (unsigned)p * A_EL * 2;
            #pragma unroll
            for (int i = 0; i < ACH; i++) {
                int chunk = tid + i * 256;
                int r = chunk >> 2, c16 = chunk & 3;
                cpasync16(so + (unsigned)(r * AST + c16 * 8) * 2,
                          Ap + (size_t)(row0 + r) * K + kt + c16 * 8);
            }
        }
        {
            unsigned so = sb + (unsigned)(2 * A_EL) * 2;
            #pragma unroll
            for (int i = 0; i < 2; i++) {
                int chunk = tid + i * 256;
                int r = chunk >> 4, cc = (chunk & 15) * 8;
                cpasync16(so + (unsigned)(r * BST + cc) * 2,
                          Bhi + (size_t)(kt + r) * N + col0 + cc);
            }
        }
    };

    int NK = K / GBK;
    load_stage(0, 0);   CP_COMMIT();
    load_stage(GBK, 1); CP_COMMIT();

    for (int it = 0; it < NK; it++) {
        CP_WAIT1();
        __syncthreads();
        int buf = it % 3;
        unsigned sb  = base + (unsigned)buf * STAGE * 2;
        unsigned aHi = sb;
        unsigned aLo = sb + A_EL * 2;
        unsigned bHi = sb + 2 * A_EL * 2;

        if (it + 2 < NK) load_stage((it + 2) * GBK, (it + 2) % 3);
        CP_COMMIT();

        #pragma unroll
        for (int k16 = 0; k16 < GBK; k16 += 16) {
            unsigned bh[2][4];
            #pragma unroll
            for (int ni = 0; ni < 2; ni++) {
                unsigned off = (unsigned)((k16 + lr) * BST + wn * 32 + ni * 16 + lc) * 2;
                ldsm4t(bh[ni], bHi + off);
            }
            #pragma unroll
            for (int mi = 0; mi < WM16; mi++) {
                unsigned ah[4], al[4];
                unsigned off = (unsigned)((wm * (TM / 2) + mi * 16 + lr) * AST + k16 + lc) * 2;
                ldsm4(ah, aHi + off);
                ldsm4(al, aLo + off);
                #pragma unroll
                for (int nj = 0; nj < 4; nj++) {
                    int ni = nj >> 1, p = nj & 1;
                    mma16816h(acc[mi][nj], ah, &bh[ni][2 * p]);
                    mma16816h(acc[mi][nj], al, &bh[ni][2 * p]);
                }
            }
        }
    }

    int rbase = row0 + wm * (TM / 2) + (lane >> 2);
    int cbase = col0 + wn * 32 + (lane & 3) * 2;
    #pragma unroll
    for (int mi = 0; mi < WM16; mi++) {
        #pragma unroll
        for (int nj = 0; nj < 4; nj++) {
            #pragma unroll
            for (int half = 0; half < 2; half++) {
                int r = rbase + mi * 16 + half * 8;
                int c = cbase + nj * 8;
                float v0 = acc[mi][nj][half * 2 + 0];
                float v1 = acc[mi][nj][half * 2 + 1];
                if (epi == EPI_QKV) {
                    if (c < II) {
                        // q -> fp16 (OutHi used as q buffer)
                        *(unsigned*)(OutHi + (size_t)r * II + c) = pack2h(v0, v1);
                    } else {
                        int c2 = c - II;
                        int bb = r / rowsPerB;
                        int s  = cnts[bb] + (r - bb * rowsPerB);
                        fp16* dst;
                        if (c2 < II)
                            dst = Kout + (((size_t)bb * HH + (c2 >> 6)) * SSQ + s) * DHD + (c2 & 63);
                        else
                            dst = Vout + (((size_t)bb * HH + ((c2 - II) >> 6)) * SSQ + s) * DHD + ((c2 - II) & 63);
                        *(unsigned*)dst = pack2h(v0, v1);
                    }
                } else if (epi == EPI_GELU) {
                    float h0 = 0.5f * v0 * (1.f + erff(v0 * 0.70710678118654752f));
                    float h1 = 0.5f * v1 * (1.f + erff(v1 * 0.70710678118654752f));
                    float t0 = __half2float(__float2half_rn(h0));
                    float t1 = __half2float(__float2half_rn(h1));
                    *(unsigned*)(OutHi + (size_t)r * N + c) = pack2h(h0, h1);
                    *(unsigned*)(OutLo + (size_t)r * N + c) = pack2h(h0 - t0, h1 - t1);
                } else {
                    float* dst = C + (size_t)r * N + c;
                    if (epi == EPI_ADD) { v0 += dst[0]; v1 += dst[1]; }
                    dst[0] = v0; dst[1] = v1;
                }
            }
        }
    }
}

// ---------- kv-x GEMM: 128 x 256 tile, 512 threads ----------
#define KV_A_EL (128 * AST)
#define KV_B_EL (GBK * BST2)
#define KV_STAGE (2 * KV_A_EL + KV_B_EL)
#define SMEMKV (3 * KV_STAGE * 2)

__global__ __launch_bounds__(512, 1) void gemm_kv256(
    const fp16* __restrict__ Ahi, const fp16* __restrict__ Alo,
    const fp16* __restrict__ Bhi,
    const float* __restrict__ bias,
    fp16* __restrict__ Kout, fp16* __restrict__ Vout,
    const int* __restrict__ cnts)
{
    extern __shared__ __align__(16) fp16 smg[];
    unsigned base = (unsigned)__cvta_generic_to_shared(smg);

    int row0 = blockIdx.y * 128;
    int col0 = blockIdx.x * 256;

    int bb = row0 >> 11;
    int cnt0 = cnts[bb];
    if ((row0 & (NN - 1)) >= cnt0) return;

    int tid  = threadIdx.x;
    int lane = tid & 31;
    int warp = tid >> 5;
    int wm = warp & 3, wn = warp >> 2;
    int lr = (lane & 7) + (((lane >> 3) & 1) << 3);
    int lc = (lane >> 4) << 3;

    float acc[2][8][4];
    #pragma unroll
    for (int i = 0; i < 2; i++)
        #pragma unroll
        for (int j = 0; j < 8; j++)
            #pragma unroll
            for (int t = 0; t < 4; t++) acc[i][j][t] = 0.f;

    auto load_stage = [&](int kt, int buf) {
        unsigned sb = base + (unsigned)buf * KV_STAGE * 2;
        #pragma unroll
        for (int p = 0; p < 2; p++) {
            const fp16* Ap = p ? Alo : Ahi;
            unsigned so = sb + (unsigned)p * KV_A_EL * 2;
            int r = tid >> 2, c16 = tid & 3;
            cpasync16(so + (unsigned)(r * AST + c16 * 8) * 2,
                      Ap + (size_t)(row0 + r) * DD + kt + c16 * 8);
        }
        {
            unsigned so = sb + (unsigned)(2 * KV_A_EL) * 2;
            #pragma unroll
            for (int i = 0; i < 2; i++) {
                int chunk = tid + i * 512;
                int r = chunk >> 5, cc = (chunk & 31) * 8;
                cpasync16(so + (unsigned)(r * BST2 + cc) * 2,
                          Bhi + (size_t)(kt + r) * 1024 + col0 + cc);
            }
        }
    };

    const int NK = DD / GBK;
    load_stage(0, 0);   CP_COMMIT();
    load_stage(GBK, 1); CP_COMMIT();

    for (int it = 0; it < NK; it++) {
        CP_WAIT1();
        __syncthreads();
        int buf = it % 3;
        unsigned sb  = base + (unsigned)buf * KV_STAGE * 2;
        unsigned aHi = sb;
        unsigned aLo = sb + KV_A_EL * 2;
        unsigned bHi = sb + 2 * KV_A_EL * 2;

        if (it + 2 < NK) load_stage((it + 2) * GBK, (it + 2) % 3);
        CP_COMMIT();

        #pragma unroll
        for (int k16 = 0; k16 < GBK; k16 += 16) {
            unsigned bh[4][4];
            #pragma unroll
            for (int ni = 0; ni < 4; ni++) {
                unsigned off = (unsigned)((k16 + lr) * BST2 + wn * 64 + ni * 16 + lc) * 2;
                ldsm4t(bh[ni], bHi + off);
            }
            #pragma unroll
            for (int mi = 0; mi < 2; mi++) {
                unsigned ah[4], al[4];
                unsigned off = (unsigned)((wm * 32 + mi * 16 + lr) * AST + k16 + lc) * 2;
                ldsm4(ah, aHi + off);
                ldsm4(al, aLo + off);
                #pragma unroll
                for (int nj = 0; nj < 8; nj++) {
                    int ni = nj >> 1, p = nj & 1;
                    mma16816h(acc[mi][nj], ah, &bh[ni][2 * p]);
                    mma16816h(acc[mi][nj], al, &bh[ni][2 * p]);
                }
            }
        }
    }

    int rbase = row0 + wm * 32 + (lane >> 2);
    int cbase = col0 + wn * 64 + (lane & 3) * 2;
    #pragma unroll
    for (int mi = 0; mi < 2; mi++) {
        #pragma unroll
        for (int nj = 0; nj < 8; nj++) {
            #pragma unroll
            for (int half = 0; half < 2; half++) {
                int r = rbase + mi * 16 + half * 8;
                int s = r & (NN - 1);
                if (s < cnt0) {
                    int c = cbase + nj * 8;
                    float v0 = acc[mi][nj][half * 2 + 0] + bias[c];
                    float v1 = acc[mi][nj][half * 2 + 1] + bias[c + 1];
                    fp16* dst;
                    if (c < II)
                        dst = Kout + (((size_t)bb * HH + (c >> 6)) * SSQ + s) * DHD + (c & 63);
                    else {
                        int c2 = c - II;
                        dst = Vout + (((size_t)bb * HH + (c2 >> 6)) * SSQ + s) * DHD + (c2 & 63);
                    }
                    *(unsigned*)dst = pack2h(v0, v1);
                }
            }
        }
    }
}

// ---------------- tensor-core flash attention ----------------
// 1 CTA per (b,h); 4 warps x 16 q rows. K [s][d] fp16 is col-major [k][n]
// for the QK B operand -> plain ldsm4; V via ldsm4t.
#define ATS 72

__global__ __launch_bounds__(128) void attn_mma_kernel(
    const fp16* __restrict__ q, const fp16* __restrict__ kg, const fp16* __restrict__ vg,
    const int* __restrict__ counts, fp16* __restrict__ attHi, fp16* __restrict__ attLo)
{
    __shared__ __align__(16) fp16 qs[64 * ATS];
    __shared__ __align__(16) fp16 ks[64 * ATS];
    __shared__ __align__(16) fp16 vs[64 * ATS];

    int bh = blockIdx.x, b = bh >> 3;
    int tid = threadIdx.x, lane = tid & 31, warp = tid >> 5;
    int lr = (lane & 7) + (((lane >> 3) & 1) << 3);
    int lc = (lane >> 4) << 3;

    unsigned qsb = (unsigned)__cvta_generic_to_shared(qs);
    unsigned ksb = (unsigned)__cvta_generic_to_shared(ks);
    unsigned vsb = (unsigned)__cvta_generic_to_shared(vs);

    int Sv = counts[b] + LQ;
    int nT = (Sv + 63) >> 6;

    // load Q tile (64 q rows x 64 dh); q layout [b*LQ + r][II] at col h*64
    {
        const fp16* qgp = q + (size_t)(b * LQ) * II + (bh & 7) * DHD;
        #pragma unroll
        for (int i = 0; i < 4; i++) {
            int ch = tid + i * 128;
            int r = ch >> 3, d8 = (ch & 7) * 8;
            *(uint4*)&qs[r * ATS + d8] = *(const uint4*)&qgp[(size_t)r * II + d8];
        }
    }

    const fp16* kb = kg + (size_t)bh * SSQ * DHD;
    const fp16* vb = vg + (size_t)bh * SSQ * DHD;

    float accO[8][4];
    #pragma unroll
    for (int n = 0; n < 8; n++)
        #pragma unroll
        for (int c = 0; c < 4; c++) accO[n][c] = 0.f;
    float m0 = -1e30f, m1 = -1e30f, l0 = 0.f, l1 = 0.f;

    for (int t = 0; t < nT; t++) {
        int s0 = t * 64;
        __syncthreads();
        #pragma unroll
        for (int i = 0; i < 4; i++) {
            int ch = tid + i * 128;
            int s = ch >> 3, d8 = (ch & 7) * 8;
            int sg = s0 + s;
            uint4 kk, vv;
            if (sg < Sv) {
                kk = *(const uint4*)&kb[(size_t)sg * DHD + d8];
                vv = *(const uint4*)&vb[(size_t)sg * DHD + d8];
            } else {
                kk = make_uint4(0, 0, 0, 0);
                vv = make_uint4(0, 0, 0, 0);
            }
            *(uint4*)&ks[s * ATS + d8] = kk;
            *(uint4*)&vs[s * ATS + d8] = vv;
        }
        __syncthreads();

        // S = Q @ K^T  (accS[n8][4], n = s-cols)
        float accS[8][4];
        #pragma unroll
        for (int n = 0; n < 8; n++)
            #pragma unroll
            for (int c = 0; c < 4; c++) accS[n][c] = 0.f;

        #pragma unroll
        for (int k16 = 0; k16 < 64; k16 += 16) {
            unsigned aq[4];
            ldsm4(aq, qsb + (unsigned)((warp * 16 + lr) * ATS + k16 + lc) * 2);
            #pragma unroll
            for (int ni = 0; ni < 4; ni++) {
                unsigned bk[4];
                // non-trans load from K [n=s][k=d] memory
                ldsm4(bk, ksb + (unsigned)((ni * 16 + lr) * ATS + k16 + lc) * 2);
                mma16816h2(accS[2 * ni + 0], aq, bk[0], bk[2]);
                mma16816h2(accS[2 * ni + 1], aq, bk[1], bk[3]);
            }
        }

        // scale + tail mask + row maxes (rows: r0 = lane>>2, r1 = r0+8)
        float mx0 = -1e30f, mx1 = -1e30f;
        #pragma unroll
        for (int n = 0; n < 8; n++) {
            int colb = s0 + n * 8 + (lane & 3) * 2;
            #pragma unroll
            for (int c = 0; c < 2; c++) {
                bool ok = (colb + c) < Sv;
                accS[n][c]     = ok ? accS[n][c]     * 0.125f : -1e30f;
                accS[n][c + 2] = ok ? accS[n][c + 2] * 0.125f : -1e30f;
                mx0 = fmaxf(mx0, accS[n][c]);
                mx1 = fmaxf(mx1, accS[n][c + 2]);
            }
        }
        mx0 = fmaxf(mx0, __shfl_xor_sync(0xffffffffu, mx0, 1));
        mx0 = fmaxf(mx0, __shfl_xor_sync(0xffffffffu, mx0, 2));
        mx1 = fmaxf(mx1, __shfl_xor_sync(0xffffffffu, mx1, 1));
        mx1 = fmaxf(mx1, __shfl_xor_sync(0xffffffffu, mx1, 2));

        float mn0 = fmaxf(m0, mx0), mn1 = fmaxf(m1, mx1);
        float cor0 = __expf(m0 - mn0), cor1 = __expf(m1 - mn1);
        float ps0 = 0.f, ps1 = 0.f;
        unsigned aP[4][4];
        #pragma unroll
        for (int n = 0; n < 8; n++) {
            float p0 = __expf(accS[n][0] - mn0);
            float p1 = __expf(accS[n][1] - mn0);
            float p2 = __expf(accS[n][2] - mn1);
            float p3 = __expf(accS[n][3] - mn1);
            ps0 += p0 + p1; ps1 += p2 + p3;
            int j = n >> 1;
            if ((n & 1) == 0) {
                aP[j][0] = pack2h(p0, p1);
                aP[j][1] = pack2h(p2, p3);
            } else {
                aP[j][2] = pack2h(p0, p1);
                aP[j][3] = pack2h(p2, p3);
            }
        }
        ps0 += __shfl_xor_sync(0xffffffffu, ps0, 1);
        ps0 += __shfl_xor_sync(0xffffffffu, ps0, 2);
        ps1 += __shfl_xor_sync(0xffffffffu, ps1, 1);
        ps1 += __shfl_xor_sync(0xffffffffu, ps1, 2);
        l0 = l0 * cor0 + ps0;
        l1 = l1 * cor1 + ps1;
        m0 = mn0; m1 = mn1;

        #pragma unroll
        for (int n = 0; n < 8; n++) {
            accO[n][0] *= cor0; accO[n][1] *= cor0;
            accO[n][2] *= cor1; accO[n][3] *= cor1;
        }

        // O += P @ V   (V [k=s][n=d] row-major -> ldsm4t)
        #pragma unroll
        for (int j = 0; j < 4; j++) {
            #pragma unroll
            for (int ni = 0; ni < 4; ni++) {
                unsigned bv[4];
                ldsm4t(bv, vsb + (unsigned)((j * 16 + lr) * ATS + ni * 16 + lc) * 2);
                mma16816h(accO[2 * ni + 0], aP[j], &bv[0]);
                mma16816h(accO[2 * ni + 1], aP[j], &bv[2]);
            }
        }
    }

    float inv0 = 1.f / l0, inv1 = 1.f / l1;
    int r0 = b * LQ + warp * 16 + (lane >> 2);
    int r1 = r0 + 8;
    int cb = (bh & 7) * DHD + (lane & 3) * 2;
    #pragma unroll
    for (int n = 0; n < 8; n++) {
        int c = cb + n * 8;
        float o0 = accO[n][0] * inv0, o1 = accO[n][1] * inv0;
        float o2 = accO[n][2] * inv1, o3 = accO[n][3] * inv1;
        float t0 = __half2float(__float2half_rn(o0));
        float t1 = __half2float(__float2half_rn(o1));
        float t2 = __half2float(__float2half_rn(o2));
        float t3 = __half2float(__float2half_rn(o3));
        *(unsigned*)(attHi + (size_t)r0 * II + c) = pack2h(o0, o1);
        *(unsigned*)(attLo + (size_t)r0 * II + c) = pack2h(o0 - t0, o1 - t1);
        *(unsigned*)(attHi + (size_t)r1 * II + c) = pack2h(o2, o3);
        *(unsigned*)(attLo + (size_t)r1 * II + c) = pack2h(o2 - t2, o3 - t3);
    }
}

// ---------------- host orchestration ----------------
#define SMEM64  ((3 * (2 * 64 * AST + GBK * BST)) * 2)

extern "C" void kernel_launch(void* const* d_in, const int* in_sizes, int n_in,
                              void* d_out, int out_size)
{
    (void)in_sizes; (void)n_in; (void)out_size;
    const float* x        = (const float*)d_in[0];
    const int*   mask     = (const int*)  d_in[1];
    const float* latents  = (const float*)d_in[2];
    const float* ln_m_w   = (const float*)d_in[3];
    const float* ln_m_b   = (const float*)d_in[4];
    const float* ln_l_w   = (const float*)d_in[5];
    const float* ln_l_b   = (const float*)d_in[6];
    const float* Wq       = (const float*)d_in[7];
    const float* Wkv      = (const float*)d_in[8];
    const float* Wo       = (const float*)d_in[9];
    const float* ff_ln_w  = (const float*)d_in[10];
    const float* ff_ln_b  = (const float*)d_in[11];
    const float* W1       = (const float*)d_in[12];
    const float* W2       = (const float*)d_in[13];
    const float* norm_w   = (const float*)d_in[14];
    const float* norm_b   = (const float*)d_in[15];
    float* out = (float*)d_out;

    fp16 *xh, *xl, *lnlh, *lnll, *lnfh, *lnfl, *atth, *attl, *hfh, *hfl;
    fp16 *cmbh, *wkvph, *woh, *w1h, *w2h, *qb, *kb, *vb;
    float *lat, *biaskv;
    int *idxmap, *counts;
    cudaGetSymbolAddress((void**)&xh, g_xh);     cudaGetSymbolAddress((void**)&xl, g_xl);
    cudaGetSymbolAddress((void**)&lnlh, g_lnlh); cudaGetSymbolAddress((void**)&lnll, g_lnll);
    cudaGetSymbolAddress((void**)&lnfh, g_lnfh); cudaGetSymbolAddress((void**)&lnfl, g_lnfl);
    cudaGetSymbolAddress((void**)&atth, g_atth); cudaGetSymbolAddress((void**)&attl, g_attl);
    cudaGetSymbolAddress((void**)&hfh, g_hfh);   cudaGetSymbolAddress((void**)&hfl, g_hfl);
    cudaGetSymbolAddress((void**)&cmbh, g_cmbh);
    cudaGetSymbolAddress((void**)&wkvph, g_wkvph);
    cudaGetSymbolAddress((void**)&woh, g_woh);
    cudaGetSymbolAddress((void**)&w1h, g_w1h);
    cudaGetSymbolAddress((void**)&w2h, g_w2h);
    cudaGetSymbolAddress((void**)&lat, g_lat);
    cudaGetSymbolAddress((void**)&qb, g_q);
    cudaGetSymbolAddress((void**)&kb, g_k);
    cudaGetSymbolAddress((void**)&vb, g_v);
    cudaGetSymbolAddress((void**)&biaskv, g_biaskv);
    cudaGetSymbolAddress((void**)&idxmap, g_idxmap);
    cudaGetSymbolAddress((void**)&counts, g_counts);

    cudaFuncSetAttribute((const void*)gemm_kv256,     cudaFuncAttributeMaxDynamicSharedMemorySize, SMEMKV);
    cudaFuncSetAttribute((const void*)gemm_fp16<64>,  cudaFuncAttributeMaxDynamicSharedMemorySize, SMEM64);

    cudaStream_t s2;
    cudaStreamCreateWithFlags(&s2, cudaStreamNonBlocking);
    cudaEvent_t evFork, evKV[NDEPTH];
    cudaEventCreateWithFlags(&evFork, cudaEventDisableTiming);
    for (int i = 0; i < NDEPTH; i++)
        cudaEventCreateWithFlags(&evKV[i], cudaEventDisableTiming);

    // ---- prologue: compaction, xhat, lat, ALL weight prep ----
    scan_mask_kernel<<<BB, 1024>>>(mask, idxmap, counts);
    ln_split_gather_kernel<<<BB * NN, 256>>>(x, idxmap, counts, xh, xl);
    init_lat_kernel<<<BB * LQ * DD / 256, 256>>>(latents, lat);

    split_wkv_all_kernel<<<dim3(1024, NDEPTH), 256>>>(Wkv, ln_m_w, wkvph, cmbh);
    split_all_kernel<<<dim3(512, NDEPTH), 256>>>(Wq, cmbh, 9, NQKV, 0,
                                                 (size_t)DD * II, (size_t)DD * NQKV);
    split_all_kernel<<<dim3(512, NDEPTH), 256>>>(Wo, woh, 10, DD, 0,
                                                 (size_t)II * DD, (size_t)II * DD);
    split_all_kernel<<<dim3(4096, NDEPTH), 256>>>(W1, w1h, 12, FFD, 0,
                                                  (size_t)DD * FFD, (size_t)DD * FFD);
    split_all_kernel<<<dim3(4096, NDEPTH), 256>>>(W2, w2h, 10, DD, 0,
                                                  (size_t)FFD * DD, (size_t)FFD * DD);
    bias_kv_all_kernel<<<dim3(128, NDEPTH), 256>>>(Wkv, ln_m_b, biaskv);

    // ---- fork: six kv-x GEMMs on side stream ----
    cudaEventRecord(evFork, 0);
    cudaStreamWaitEvent(s2, evFork, 0);
    for (int i = 0; i < NDEPTH; i++) {
        gemm_kv256<<<dim3(2 * II / 256, BB * NN / 128), 512, SMEMKV, s2>>>(
            xh, xl, wkvph + (size_t)i * DD * 2 * II,
            biaskv + i * 2 * II, kb + (size_t)i * KVSZ, vb + (size_t)i * KVSZ, counts);
        cudaEventRecord(evKV[i], s2);
    }

    // ---- main loop: lat path ----
    for (int i = 0; i < NDEPTH; i++) {
        fp16* kb_i = kb + (size_t)i * KVSZ;
        fp16* vb_i = vb + (size_t)i * KVSZ;

        ln_split_kernel<<<BB * LQ, 256>>>(lat, lnlh, lnll, ln_l_w + i * DD, ln_l_b + i * DD);

        gemm_fp16<64><<<dim3(NQKV / 128, BB * LQ / 64), 256, SMEM64>>>(
            lnlh, lnll, cmbh + (size_t)i * DD * NQKV,
            nullptr, BB * LQ, NQKV, DD, EPI_QKV,
            nullptr, kb_i, vb_i, LQ, counts, qb, nullptr);

        cudaStreamWaitEvent(0, evKV[i], 0);
        attn_mma_kernel<<<BB * HH, 128>>>(qb, kb_i, vb_i, counts, atth, attl);

        gemm_fp16<64><<<dim3(DD / 128, BB * LQ / 64), 256, SMEM64>>>(
            atth, attl, woh + (size_t)i * II * DD,
            lat, BB * LQ, DD, II, EPI_ADD,
            nullptr, nullptr, nullptr, 0, counts, nullptr, nullptr);

        ln_split_kernel<<<BB * LQ, 256>>>(lat, lnfh, lnfl, ff_ln_w + i * DD, ff_ln_b + i * DD);
        gemm_fp16<64><<<dim3(FFD / 128, BB * LQ / 64), 256, SMEM64>>>(
            lnfh, lnfl, w1h + (size_t)i * DD * FFD,
            nullptr, BB * LQ, FFD, DD, EPI_GELU,
            nullptr, nullptr, nullptr, 0, counts, hfh, hfl);
        gemm_fp16<64><<<dim3(DD / 128, BB * LQ / 64), 256, SMEM64>>>(
            hfh, hfl, w2h + (size_t)i * FFD * DD,
            lat, BB * LQ, DD, FFD, EPI_ADD,
            nullptr, nullptr, nullptr, 0, counts, nullptr, nullptr);
    }

    ln_kernel<<<BB * LQ, 256>>>(lat, out, norm_w, norm_b);
}

// round 15
// speedup vs baseline: 4.3534x; 1.2066x over previous
#include <cuda_runtime.h>
#include <cuda_fp16.h>
#include <stdint.h>
#include <math.h>

// ---------------- problem constants ----------------
#define BB   16
#define NN   2048
#define DD   1024
#define HH   8
#define DHD  64
#define II   512           // H*DH
#define LQ   64
#define SSQ  2112          // N + L
#define NDEPTH 6
#define FFD  4096
#define NQKV 1536          // II + 2*II

#define KVSZ ((size_t)BB * HH * SSQ * DHD)

typedef __half fp16;

// ---------------- scratch ----------------
__device__ fp16 g_xh[(size_t)BB * NN * DD];     // compacted xhat (single plane)
__device__ fp16 g_lnlh[BB * LQ * DD];
__device__ fp16 g_lnfh[BB * LQ * DD],  g_lnfl[BB * LQ * DD];
__device__ fp16 g_atth[BB * LQ * II],  g_attl[BB * LQ * II];
__device__ fp16 g_hfh [BB * LQ * FFD], g_hfl [BB * LQ * FFD];
// per-layer weight planes (hi only — B side of every GEMM)
__device__ fp16 g_cmbh[(size_t)NDEPTH * DD * NQKV];
__device__ fp16 g_wkvph[(size_t)NDEPTH * DD * 2 * II];
__device__ fp16 g_woh [(size_t)NDEPTH * II * DD];
__device__ fp16 g_w1h [(size_t)NDEPTH * DD * FFD];
__device__ fp16 g_w2h [(size_t)NDEPTH * FFD * DD];
__device__ float g_biaskv[NDEPTH * 2 * II];
__device__ float g_lat[BB * LQ * DD];
__device__ fp16  g_q  [BB * LQ * II];
__device__ fp16  g_k  [(size_t)NDEPTH * KVSZ];
__device__ fp16  g_v  [(size_t)NDEPTH * KVSZ];
__device__ int   g_idxmap[BB * NN];
__device__ int   g_counts[BB];

// ---------------- helpers ----------------
__device__ __forceinline__ unsigned pack2h(float x, float y)
{
    return (unsigned)__half_as_ushort(__float2half_rn(x))
         | ((unsigned)__half_as_ushort(__float2half_rn(y)) << 16);
}
__device__ __forceinline__ void split4h(float4 v, uint2& hi, uint2& lo)
{
    float hx = __half2float(__float2half_rn(v.x));
    float hy = __half2float(__float2half_rn(v.y));
    float hz = __half2float(__float2half_rn(v.z));
    float hw = __half2float(__float2half_rn(v.w));
    hi = make_uint2(pack2h(v.x, v.y), pack2h(v.z, v.w));
    lo = make_uint2(pack2h(v.x - hx, v.y - hy), pack2h(v.z - hz, v.w - hw));
}
__device__ __forceinline__ uint2 hi4h(float4 v)
{
    return make_uint2(pack2h(v.x, v.y), pack2h(v.z, v.w));
}

// ---------------- mask compaction: per-batch scan ----------------
__global__ __launch_bounds__(1024) void scan_mask_kernel(const int* __restrict__ mask,
                                                         int* __restrict__ idxmap,
                                                         int* __restrict__ counts)
{
    __shared__ int sh[1024];
    int b = blockIdx.x;
    int t = threadIdx.x;
    int v0 = (mask[b * NN + 2 * t]     == 0) ? 1 : 0;
    int v1 = (mask[b * NN + 2 * t + 1] == 0) ? 1 : 0;
    sh[t] = v0 + v1;
    __syncthreads();
    for (int off = 1; off < 1024; off <<= 1) {
        int x = 0;
        if (t >= off) x = sh[t - off];
        __syncthreads();
        if (t >= off) sh[t] += x;
        __syncthreads();
    }
    int incl = sh[t];
    int excl = incl - v0 - v1;
    if (v0) idxmap[b * NN + excl] = 2 * t;
    if (v1) idxmap[b * NN + excl + v0] = 2 * t + 1;
    if (t == 1023) counts[b] = incl;
}

// ---------------- LayerNorm (fp32 out, final layer) ----------------
__global__ __launch_bounds__(256) void ln_kernel(const float* __restrict__ in,
                                                 float* __restrict__ out,
                                                 const float* __restrict__ w,
                                                 const float* __restrict__ b)
{
    int row = blockIdx.x;
    int tid = threadIdx.x;
    const float4 xv = *(const float4*)(in + (size_t)row * DD + tid * 4);
    float s  = xv.x + xv.y + xv.z + xv.w;
    float ss = xv.x * xv.x + xv.y * xv.y + xv.z * xv.z + xv.w * xv.w;
    #pragma unroll
    for (int o = 16; o; o >>= 1) {
        s  += __shfl_xor_sync(0xffffffffu, s,  o);
        ss += __shfl_xor_sync(0xffffffffu, ss, o);
    }
    __shared__ float red[16];
    int wid = tid >> 5;
    if ((tid & 31) == 0) { red[wid] = s; red[wid + 8] = ss; }
    __syncthreads();
    s = 0.f; ss = 0.f;
    #pragma unroll
    for (int i = 0; i < 8; i++) { s += red[i]; ss += red[i + 8]; }
    float mu   = s * (1.f / DD);
    float var  = ss * (1.f / DD) - mu * mu;
    float rstd = rsqrtf(var + 1e-5f);
    float4 o4;
    o4.x = (xv.x - mu) * rstd; o4.y = (xv.y - mu) * rstd;
    o4.z = (xv.z - mu) * rstd; o4.w = (xv.w - mu) * rstd;
    const float4 wv = *(const float4*)(w + tid * 4);
    const float4 bv = *(const float4*)(b + tid * 4);
    o4.x = o4.x * wv.x + bv.x; o4.y = o4.y * wv.y + bv.y;
    o4.z = o4.z * wv.z + bv.z; o4.w = o4.w * wv.w + bv.w;
    *(float4*)(out + (size_t)row * DD + tid * 4) = o4;
}

// ---------------- LayerNorm -> split fp16 hi (+optional lo) ----------------
__global__ __launch_bounds__(256) void ln_split_kernel(const float* __restrict__ in,
                                                       fp16* __restrict__ hi,
                                                       fp16* __restrict__ lo,
                                                       const float* __restrict__ w,
                                                       const float* __restrict__ b)
{
    int row = blockIdx.x;
    int tid = threadIdx.x;
    const float4 xv = *(const float4*)(in + (size_t)row * DD + tid * 4);
    float s  = xv.x + xv.y + xv.z + xv.w;
    float ss = xv.x * xv.x + xv.y * xv.y + xv.z * xv.z + xv.w * xv.w;
    #pragma unroll
    for (int o = 16; o; o >>= 1) {
        s  += __shfl_xor_sync(0xffffffffu, s,  o);
        ss += __shfl_xor_sync(0xffffffffu, ss, o);
    }
    __shared__ float red[16];
    int wid = tid >> 5;
    if ((tid & 31) == 0) { red[wid] = s; red[wid + 8] = ss; }
    __syncthreads();
    s = 0.f; ss = 0.f;
    #pragma unroll
    for (int i = 0; i < 8; i++) { s += red[i]; ss += red[i + 8]; }
    float mu   = s * (1.f / DD);
    float var  = ss * (1.f / DD) - mu * mu;
    float rstd = rsqrtf(var + 1e-5f);
    float4 o4;
    o4.x = (xv.x - mu) * rstd; o4.y = (xv.y - mu) * rstd;
    o4.z = (xv.z - mu) * rstd; o4.w = (xv.w - mu) * rstd;
    const float4 wv = *(const float4*)(w + tid * 4);
    const float4 bv = *(const float4*)(b + tid * 4);
    o4.x = o4.x * wv.x + bv.x; o4.y = o4.y * wv.y + bv.y;
    o4.z = o4.z * wv.z + bv.z; o4.w = o4.w * wv.w + bv.w;
    uint2 h, l;
    split4h(o4, h, l);
    *(uint2*)(hi + (size_t)row * DD + tid * 4) = h;
    if (lo) *(uint2*)(lo + (size_t)row * DD + tid * 4) = l;
}

// ---------------- compacted LN of x -> fp16 (single plane) ----------------
__global__ __launch_bounds__(256) void ln_gather_kernel(const float* __restrict__ in,
                                                        const int* __restrict__ idxmap,
                                                        const int* __restrict__ counts,
                                                        fp16* __restrict__ hi)
{
    int row = blockIdx.x;
    int b   = row >> 11;
    int j   = row & (NN - 1);
    if (j >= counts[b]) return;
    int src = idxmap[row];
    int tid = threadIdx.x;
    const float4 xv = *(const float4*)(in + ((size_t)b * NN + src) * DD + tid * 4);
    float s  = xv.x + xv.y + xv.z + xv.w;
    float ss = xv.x * xv.x + xv.y * xv.y + xv.z * xv.z + xv.w * xv.w;
    #pragma unroll
    for (int o = 16; o; o >>= 1) {
        s  += __shfl_xor_sync(0xffffffffu, s,  o);
        ss += __shfl_xor_sync(0xffffffffu, ss, o);
    }
    __shared__ float red[16];
    int wid = tid >> 5;
    if ((tid & 31) == 0) { red[wid] = s; red[wid + 8] = ss; }
    __syncthreads();
    s = 0.f; ss = 0.f;
    #pragma unroll
    for (int i = 0; i < 8; i++) { s += red[i]; ss += red[i + 8]; }
    float mu   = s * (1.f / DD);
    float var  = ss * (1.f / DD) - mu * mu;
    float rstd = rsqrtf(var + 1e-5f);
    float4 o4;
    o4.x = (xv.x - mu) * rstd; o4.y = (xv.y - mu) * rstd;
    o4.z = (xv.z - mu) * rstd; o4.w = (xv.w - mu) * rstd;
    *(uint2*)(hi + (size_t)row * DD + tid * 4) = hi4h(o4);
}

// ---------------- all-layer generic weight split (hi plane only) ----------
__global__ __launch_bounds__(256) void split_all_kernel(const float* __restrict__ in,
                                                        fp16* __restrict__ hi,
                                                        int srcColsLog2, int dstStride, int dstOff,
                                                        size_t srcLS, size_t dstLS)
{
    int layer = blockIdx.y;
    int idx = (blockIdx.x * 256 + threadIdx.x) * 4;
    float4 v = *(const float4*)(in + layer * srcLS + idx);
    int row = idx >> srcColsLog2;
    int col = idx & ((1 << srcColsLog2) - 1);
    size_t d = layer * dstLS + (size_t)row * dstStride + dstOff + col;
    *(uint2*)(hi + d) = hi4h(v);
}

// ---------------- all-layer Wkv split ----------------
__global__ __launch_bounds__(256) void split_wkv_all_kernel(const float* __restrict__ Wkv,
                                                            const float* __restrict__ lwAll,
                                                            fp16* __restrict__ fh,
                                                            fp16* __restrict__ ch)
{
    int layer = blockIdx.y;
    int idx = (blockIdx.x * 256 + threadIdx.x) * 4;
    float4 v = *(const float4*)(Wkv + (size_t)layer * DD * 1024 + idx);
    int row = idx >> 10;
    int col = idx & 1023;
    size_t d = (size_t)layer * DD * NQKV + (size_t)row * NQKV + II + col;
    *(uint2*)(ch + d) = hi4h(v);
    float sc = lwAll[layer * DD + row];
    v.x *= sc; v.y *= sc; v.z *= sc; v.w *= sc;
    size_t f = (size_t)layer * DD * 1024 + idx;
    *(uint2*)(fh + f) = hi4h(v);
}

// ---------------- lat init ----------------
__global__ void init_lat_kernel(const float* __restrict__ latents, float* __restrict__ lat)
{
    int idx = blockIdx.x * 256 + threadIdx.x;
    lat[idx] = latents[idx & (LQ * DD - 1)];
}

// ---------------- all-layer biaskv ----------------
__global__ __launch_bounds__(256) void bias_kv_all_kernel(const float* __restrict__ Wkv,
                                                          const float* __restrict__ lnbAll,
                                                          float* __restrict__ bias)
{
    int layer = blockIdx.y;
    const float* W = Wkv + (size_t)layer * DD * 1024;
    const float* lnb = lnbAll + layer * DD;
    int j  = blockIdx.x * 8 + (threadIdx.x & 7);
    int dc = threadIdx.x >> 3;
    float a = 0.f;
    int d0 = dc * 32;
    #pragma unroll 8
    for (int d = d0; d < d0 + 32; d++) a += lnb[d] * W[(size_t)d * 1024 + j];
    __shared__ float red[32][8];
    red[dc][threadIdx.x & 7] = a;
    __syncthreads();
    if (threadIdx.x < 8) {
        float s = 0.f;
        #pragma unroll
        for (int i = 0; i < 32; i++) s += red[i][threadIdx.x];
        bias[layer * 1024 + blockIdx.x * 8 + threadIdx.x] = s;
    }
}

// ================= fp16 split-precision mma.sync GEMM =================
enum { EPI_NONE = 0, EPI_ADD = 1, EPI_GELU = 2, EPI_KV = 3, EPI_QKV = 4 };

#define GBK 32
#define AST 40
#define BST 136
#define BST2 264

__device__ __forceinline__ void mma16816h(float* d, const unsigned* a, const unsigned* b)
{
    asm volatile(
        "mma.sync.aligned.m16n8k16.row.col.f32.f16.f16.f32 "
        "{%0,%1,%2,%3}, {%4,%5,%6,%7}, {%8,%9}, {%0,%1,%2,%3};\n"
        : "+f"(d[0]), "+f"(d[1]), "+f"(d[2]), "+f"(d[3])
        : "r"(a[0]), "r"(a[1]), "r"(a[2]), "r"(a[3]), "r"(b[0]), "r"(b[1]));
}
__device__ __forceinline__ void mma16816h2(float* d, const unsigned* a, unsigned b0, unsigned b1)
{
    asm volatile(
        "mma.sync.aligned.m16n8k16.row.col.f32.f16.f16.f32 "
        "{%0,%1,%2,%3}, {%4,%5,%6,%7}, {%8,%9}, {%0,%1,%2,%3};\n"
        : "+f"(d[0]), "+f"(d[1]), "+f"(d[2]), "+f"(d[3])
        : "r"(a[0]), "r"(a[1]), "r"(a[2]), "r"(a[3]), "r"(b0), "r"(b1));
}
__device__ __forceinline__ void ldsm4(unsigned* r, unsigned addr)
{
    asm volatile("ldmatrix.sync.aligned.m8n8.x4.shared.b16 {%0,%1,%2,%3}, [%4];\n"
                 : "=r"(r[0]), "=r"(r[1]), "=r"(r[2]), "=r"(r[3]) : "r"(addr));
}
__device__ __forceinline__ void ldsm4t(unsigned* r, unsigned addr)
{
    asm volatile("ldmatrix.sync.aligned.m8n8.x4.trans.shared.b16 {%0,%1,%2,%3}, [%4];\n"
                 : "=r"(r[0]), "=r"(r[1]), "=r"(r[2]), "=r"(r[3]) : "r"(addr));
}
__device__ __forceinline__ void cpasync16(unsigned s, const void* g)
{
    asm volatile("cp.async.cg.shared.global [%0], [%1], 16;\n" :: "r"(s), "l"(g));
}
#define CP_COMMIT() asm volatile("cp.async.commit_group;\n")
#define CP_WAIT1()  asm volatile("cp.async.wait_group 1;\n")

// ---------- small-GEMM variant: TM x 128, 256 threads ----------
// DUAL: A = Ahi + Alo (2 MMAs); else single plane.
template<int TM, bool DUAL>
__global__ __launch_bounds__(256, 2) void gemm_fp16(
    const fp16* __restrict__ Ahi, const fp16* __restrict__ Alo,
    const fp16* __restrict__ Bhi,
    float* __restrict__ C, int M, int N, int K, int epi,
    fp16* __restrict__ Kout, fp16* __restrict__ Vout, int rowsPerB,
    const int* __restrict__ cnts,
    fp16* __restrict__ OutHi, fp16* __restrict__ OutLo)
{
    constexpr int WM16   = TM / 32;
    constexpr int A_EL   = TM * AST;
    constexpr int B_EL   = GBK * BST;
    constexpr int STAGE  = (DUAL ? 2 : 1) * A_EL + B_EL;
    extern __shared__ __align__(16) fp16 smg[];
    unsigned base = (unsigned)__cvta_generic_to_shared(smg);

    int row0 = blockIdx.y * TM;
    int col0 = blockIdx.x << 7;

    int tid  = threadIdx.x;
    int lane = tid & 31;
    int warp = tid >> 5;
    int wm = warp & 1, wn = warp >> 1;
    int lr = (lane & 7) + (((lane >> 3) & 1) << 3);
    int lc = (lane >> 4) << 3;

    float acc[WM16][4][4];
    #pragma unroll
    for (int i = 0; i < WM16; i++)
        #pragma unroll
        for (int j = 0; j < 4; j++)
            #pragma unroll
            for (int t = 0; t < 4; t++) acc[i][j][t] = 0.f;

    auto load_stage = [&](int kt, int buf) {
        unsigned sb = base + (unsigned)buf * STAGE * 2;
        constexpr int ACH = (TM * 4) / 256;
        constexpr int NP = DUAL ? 2 : 1;
        #pragma unroll
        for (int p = 0; p < NP; p++) {
            const fp16* Ap = p ? Alo : Ahi;
            unsigned so = sb + (unsigned)p * A_EL * 2;
            #pragma unroll
            for (int i = 0; i < ACH; i++) {
                int chunk = tid + i * 256;
                int r = chunk >> 2, c16 = chunk & 3;
                cpasync16(so + (unsigned)(r * AST + c16 * 8) * 2,
                          Ap + (size_t)(row0 + r) * K + kt + c16 * 8);
            }
        }
        {
            unsigned so = sb + (unsigned)(NP * A_EL) * 2;
            #pragma unroll
            for (int i = 0; i < 2; i++) {
                int chunk = tid + i * 256;
                int r = chunk >> 4, cc = (chunk & 15) * 8;
                cpasync16(so + (unsigned)(r * BST + cc) * 2,
                          Bhi + (size_t)(kt + r) * N + col0 + cc);
            }
        }
    };

    int NK = K / GBK;
    load_stage(0, 0);   CP_COMMIT();
    load_stage(GBK, 1); CP_COMMIT();

    for (int it = 0; it < NK; it++) {
        CP_WAIT1();
        __syncthreads();
        int buf = it % 3;
        unsigned sb  = base + (unsigned)buf * STAGE * 2;
        unsigned aHi = sb;
        unsigned aLo = sb + A_EL * 2;
        unsigned bHi = sb + (unsigned)((DUAL ? 2 : 1) * A_EL) * 2;

        if (it + 2 < NK) load_stage((it + 2) * GBK, (it + 2) % 3);
        CP_COMMIT();

        #pragma unroll
        for (int k16 = 0; k16 < GBK; k16 += 16) {
            unsigned bh[2][4];
            #pragma unroll
            for (int ni = 0; ni < 2; ni++) {
                unsigned off = (unsigned)((k16 + lr) * BST + wn * 32 + ni * 16 + lc) * 2;
                ldsm4t(bh[ni], bHi + off);
            }
            #pragma unroll
            for (int mi = 0; mi < WM16; mi++) {
                unsigned ah[4], al[4];
                unsigned off = (unsigned)((wm * (TM / 2) + mi * 16 + lr) * AST + k16 + lc) * 2;
                ldsm4(ah, aHi + off);
                if (DUAL) ldsm4(al, aLo + off);
                #pragma unroll
                for (int nj = 0; nj < 4; nj++) {
                    int ni = nj >> 1, p = nj & 1;
                    mma16816h(acc[mi][nj], ah, &bh[ni][2 * p]);
                    if (DUAL) mma16816h(acc[mi][nj], al, &bh[ni][2 * p]);
                }
            }
        }
    }

    int rbase = row0 + wm * (TM / 2) + (lane >> 2);
    int cbase = col0 + wn * 32 + (lane & 3) * 2;
    #pragma unroll
    for (int mi = 0; mi < WM16; mi++) {
        #pragma unroll
        for (int nj = 0; nj < 4; nj++) {
            #pragma unroll
            for (int half = 0; half < 2; half++) {
                int r = rbase + mi * 16 + half * 8;
                int c = cbase + nj * 8;
                float v0 = acc[mi][nj][half * 2 + 0];
                float v1 = acc[mi][nj][half * 2 + 1];
                if (epi == EPI_QKV) {
                    if (c < II) {
                        *(unsigned*)(OutHi + (size_t)r * II + c) = pack2h(v0, v1);
                    } else {
                        int c2 = c - II;
                        int bb = r / rowsPerB;
                        int s  = cnts[bb] + (r - bb * rowsPerB);
                        fp16* dst;
                        if (c2 < II)
                            dst = Kout + (((size_t)bb * HH + (c2 >> 6)) * SSQ + s) * DHD + (c2 & 63);
                        else
                            dst = Vout + (((size_t)bb * HH + ((c2 - II) >> 6)) * SSQ + s) * DHD + ((c2 - II) & 63);
                        *(unsigned*)dst = pack2h(v0, v1);
                    }
                } else if (epi == EPI_GELU) {
                    float h0 = 0.5f * v0 * (1.f + erff(v0 * 0.70710678118654752f));
                    float h1 = 0.5f * v1 * (1.f + erff(v1 * 0.70710678118654752f));
                    float t0 = __half2float(__float2half_rn(h0));
                    float t1 = __half2float(__float2half_rn(h1));
                    *(unsigned*)(OutHi + (size_t)r * N + c) = pack2h(h0, h1);
                    *(unsigned*)(OutLo + (size_t)r * N + c) = pack2h(h0 - t0, h1 - t1);
                } else {
                    float* dst = C + (size_t)r * N + c;
                    if (epi == EPI_ADD) { v0 += dst[0]; v1 += dst[1]; }
                    dst[0] = v0; dst[1] = v1;
                }
            }
        }
    }
}

// ---------- kv-x GEMM: 128 x 256 tile, 512 threads, single A plane ----------
#define KV_A_EL (128 * AST)
#define KV_B_EL (GBK * BST2)
#define KV_STAGE (KV_A_EL + KV_B_EL)
#define SMEMKV (3 * KV_STAGE * 2)

__global__ __launch_bounds__(512, 1) void gemm_kv256(
    const fp16* __restrict__ Ahi,
    const fp16* __restrict__ Bhi,
    const float* __restrict__ bias,
    fp16* __restrict__ Kout, fp16* __restrict__ Vout,
    const int* __restrict__ cnts)
{
    extern __shared__ __align__(16) fp16 smg[];
    unsigned base = (unsigned)__cvta_generic_to_shared(smg);

    int row0 = blockIdx.y * 128;
    int col0 = blockIdx.x * 256;

    int bb = row0 >> 11;
    int cnt0 = cnts[bb];
    if ((row0 & (NN - 1)) >= cnt0) return;

    int tid  = threadIdx.x;
    int lane = tid & 31;
    int warp = tid >> 5;
    int wm = warp & 3, wn = warp >> 2;
    int lr = (lane & 7) + (((lane >> 3) & 1) << 3);
    int lc = (lane >> 4) << 3;

    float acc[2][8][4];
    #pragma unroll
    for (int i = 0; i < 2; i++)
        #pragma unroll
        for (int j = 0; j < 8; j++)
            #pragma unroll
            for (int t = 0; t < 4; t++) acc[i][j][t] = 0.f;

    auto load_stage = [&](int kt, int buf) {
        unsigned sb = base + (unsigned)buf * KV_STAGE * 2;
        {
            int r = tid >> 2, c16 = tid & 3;
            cpasync16(sb + (unsigned)(r * AST + c16 * 8) * 2,
                      Ahi + (size_t)(row0 + r) * DD + kt + c16 * 8);
        }
        {
            unsigned so = sb + (unsigned)KV_A_EL * 2;
            #pragma unroll
            for (int i = 0; i < 2; i++) {
                int chunk = tid + i * 512;
                int r = chunk >> 5, cc = (chunk & 31) * 8;
                cpasync16(so + (unsigned)(r * BST2 + cc) * 2,
                          Bhi + (size_t)(kt + r) * 1024 + col0 + cc);
            }
        }
    };

    const int NK = DD / GBK;
    load_stage(0, 0);   CP_COMMIT();
    load_stage(GBK, 1); CP_COMMIT();

    for (int it = 0; it < NK; it++) {
        CP_WAIT1();
        __syncthreads();
        int buf = it % 3;
        unsigned sb  = base + (unsigned)buf * KV_STAGE * 2;
        unsigned aHi = sb;
        unsigned bHi = sb + (unsigned)KV_A_EL * 2;

        if (it + 2 < NK) load_stage((it + 2) * GBK, (it + 2) % 3);
        CP_COMMIT();

        #pragma unroll
        for (int k16 = 0; k16 < GBK; k16 += 16) {
            unsigned bh[4][4];
            #pragma unroll
            for (int ni = 0; ni < 4; ni++) {
                unsigned off = (unsigned)((k16 + lr) * BST2 + wn * 64 + ni * 16 + lc) * 2;
                ldsm4t(bh[ni], bHi + off);
            }
            #pragma unroll
            for (int mi = 0; mi < 2; mi++) {
                unsigned ah[4];
                unsigned off = (unsigned)((wm * 32 + mi * 16 + lr) * AST + k16 + lc) * 2;
                ldsm4(ah, aHi + off);
                #pragma unroll
                for (int nj = 0; nj < 8; nj++) {
                    int ni = nj >> 1, p = nj & 1;
                    mma16816h(acc[mi][nj], ah, &bh[ni][2 * p]);
                }
            }
        }
    }

    int rbase = row0 + wm * 32 + (lane >> 2);
    int cbase = col0 + wn * 64 + (lane & 3) * 2;
    #pragma unroll
    for (int mi = 0; mi < 2; mi++) {
        #pragma unroll
        for (int nj = 0; nj < 8; nj++) {
            #pragma unroll
            for (int half = 0; half < 2; half++) {
                int r = rbase + mi * 16 + half * 8;
                int s = r & (NN - 1);
                if (s < cnt0) {
                    int c = cbase + nj * 8;
                    float v0 = acc[mi][nj][half * 2 + 0] + bias[c];
                    float v1 = acc[mi][nj][half * 2 + 1] + bias[c + 1];
                    fp16* dst;
                    if (c < II)
                        dst = Kout + (((size_t)bb * HH + (c >> 6)) * SSQ + s) * DHD + (c & 63);
                    else {
                        int c2 = c - II;
                        dst = Vout + (((size_t)bb * HH + (c2 >> 6)) * SSQ + s) * DHD + (c2 & 63);
                    }
                    *(unsigned*)dst = pack2h(v0, v1);
                }
            }
        }
    }
}

// ---------------- tensor-core flash attention ----------------
#define ATS 72

__global__ __launch_bounds__(128) void attn_mma_kernel(
    const fp16* __restrict__ q, const fp16* __restrict__ kg, const fp16* __restrict__ vg,
    const int* __restrict__ counts, fp16* __restrict__ attHi, fp16* __restrict__ attLo)
{
    __shared__ __align__(16) fp16 qs[64 * ATS];
    __shared__ __align__(16) fp16 ks[64 * ATS];
    __shared__ __align__(16) fp16 vs[64 * ATS];

    int bh = blockIdx.x, b = bh >> 3;
    int tid = threadIdx.x, lane = tid & 31, warp = tid >> 5;
    int lr = (lane & 7) + (((lane >> 3) & 1) << 3);
    int lc = (lane >> 4) << 3;

    unsigned qsb = (unsigned)__cvta_generic_to_shared(qs);
    unsigned ksb = (unsigned)__cvta_generic_to_shared(ks);
    unsigned vsb = (unsigned)__cvta_generic_to_shared(vs);

    int Sv = counts[b] + LQ;
    int nT = (Sv + 63) >> 6;

    {
        const fp16* qgp = q + (size_t)(b * LQ) * II + (bh & 7) * DHD;
        #pragma unroll
        for (int i = 0; i < 4; i++) {
            int ch = tid + i * 128;
            int r = ch >> 3, d8 = (ch & 7) * 8;
            *(uint4*)&qs[r * ATS + d8] = *(const uint4*)&qgp[(size_t)r * II + d8];
        }
    }

    const fp16* kb = kg + (size_t)bh * SSQ * DHD;
    const fp16* vb = vg + (size_t)bh * SSQ * DHD;

    float accO[8][4];
    #pragma unroll
    for (int n = 0; n < 8; n++)
        #pragma unroll
        for (int c = 0; c < 4; c++) accO[n][c] = 0.f;
    float m0 = -1e30f, m1 = -1e30f, l0 = 0.f, l1 = 0.f;

    for (int t = 0; t < nT; t++) {
        int s0 = t * 64;
        __syncthreads();
        #pragma unroll
        for (int i = 0; i < 4; i++) {
            int ch = tid + i * 128;
            int s = ch >> 3, d8 = (ch & 7) * 8;
            int sg = s0 + s;
            uint4 kk, vv;
            if (sg < Sv) {
                kk = *(const uint4*)&kb[(size_t)sg * DHD + d8];
                vv = *(const uint4*)&vb[(size_t)sg * DHD + d8];
            } else {
                kk = make_uint4(0, 0, 0, 0);
                vv = make_uint4(0, 0, 0, 0);
            }
            *(uint4*)&ks[s * ATS + d8] = kk;
            *(uint4*)&vs[s * ATS + d8] = vv;
        }
        __syncthreads();

        float accS[8][4];
        #pragma unroll
        for (int n = 0; n < 8; n++)
            #pragma unroll
            for (int c = 0; c < 4; c++) accS[n][c] = 0.f;

        #pragma unroll
        for (int k16 = 0; k16 < 64; k16 += 16) {
            unsigned aq[4];
            ldsm4(aq, qsb + (unsigned)((warp * 16 + lr) * ATS + k16 + lc) * 2);
            #pragma unroll
            for (int ni = 0; ni < 4; ni++) {
                unsigned bk[4];
                ldsm4(bk, ksb + (unsigned)((ni * 16 + lr) * ATS + k16 + lc) * 2);
                mma16816h2(accS[2 * ni + 0], aq, bk[0], bk[2]);
                mma16816h2(accS[2 * ni + 1], aq, bk[1], bk[3]);
            }
        }

        float mx0 = -1e30f, mx1 = -1e30f;
        #pragma unroll
        for (int n = 0; n < 8; n++) {
            int colb = s0 + n * 8 + (lane & 3) * 2;
            #pragma unroll
            for (int c = 0; c < 2; c++) {
                bool ok = (colb + c) < Sv;
                accS[n][c]     = ok ? accS[n][c]     * 0.125f : -1e30f;
                accS[n][c + 2] = ok ? accS[n][c + 2] * 0.125f : -1e30f;
                mx0 = fmaxf(mx0, accS[n][c]);
                mx1 = fmaxf(mx1, accS[n][c + 2]);
            }
        }
        mx0 = fmaxf(mx0, __shfl_xor_sync(0xffffffffu, mx0, 1));
        mx0 = fmaxf(mx0, __shfl_xor_sync(0xffffffffu, mx0, 2));
        mx1 = fmaxf(mx1, __shfl_xor_sync(0xffffffffu, mx1, 1));
        mx1 = fmaxf(mx1, __shfl_xor_sync(0xffffffffu, mx1, 2));

        float mn0 = fmaxf(m0, mx0), mn1 = fmaxf(m1, mx1);
        float cor0 = __expf(m0 - mn0), cor1 = __expf(m1 - mn1);
        float ps0 = 0.f, ps1 = 0.f;
        unsigned aP[4][4];
        #pragma unroll
        for (int n = 0; n < 8; n++) {
            float p0 = __expf(accS[n][0] - mn0);
            float p1 = __expf(accS[n][1] - mn0);
            float p2 = __expf(accS[n][2] - mn1);
            float p3 = __expf(accS[n][3] - mn1);
            ps0 += p0 + p1; ps1 += p2 + p3;
            int j = n >> 1;
            if ((n & 1) == 0) {
                aP[j][0] = pack2h(p0, p1);
                aP[j][1] = pack2h(p2, p3);
            } else {
                aP[j][2] = pack2h(p0, p1);
                aP[j][3] = pack2h(p2, p3);
            }
        }
        ps0 += __shfl_xor_sync(0xffffffffu, ps0, 1);
        ps0 += __shfl_xor_sync(0xffffffffu, ps0, 2);
        ps1 += __shfl_xor_sync(0xffffffffu, ps1, 1);
        ps1 += __shfl_xor_sync(0xffffffffu, ps1, 2);
        l0 = l0 * cor0 + ps0;
        l1 = l1 * cor1 + ps1;
        m0 = mn0; m1 = mn1;

        #pragma unroll
        for (int n = 0; n < 8; n++) {
            accO[n][0] *= cor0; accO[n][1] *= cor0;
            accO[n][2] *= cor1; accO[n][3] *= cor1;
        }

        #pragma unroll
        for (int j = 0; j < 4; j++) {
            #pragma unroll
            for (int ni = 0; ni < 4; ni++) {
                unsigned bv[4];
                ldsm4t(bv, vsb + (unsigned)((j * 16 + lr) * ATS + ni * 16 + lc) * 2);
                mma16816h(accO[2 * ni + 0], aP[j], &bv[0]);
                mma16816h(accO[2 * ni + 1], aP[j], &bv[2]);
            }
        }
    }

    float inv0 = 1.f / l0, inv1 = 1.f / l1;
    int r0 = b * LQ + warp * 16 + (lane >> 2);
    int r1 = r0 + 8;
    int cb = (bh & 7) * DHD + (lane & 3) * 2;
    #pragma unroll
    for (int n = 0; n < 8; n++) {
        int c = cb + n * 8;
        float o0 = accO[n][0] * inv0, o1 = accO[n][1] * inv0;
        float o2 = accO[n][2] * inv1, o3 = accO[n][3] * inv1;
        float t0 = __half2float(__float2half_rn(o0));
        float t1 = __half2float(__float2half_rn(o1));
        float t2 = __half2float(__float2half_rn(o2));
        float t3 = __half2float(__float2half_rn(o3));
        *(unsigned*)(attHi + (size_t)r0 * II + c) = pack2h(o0, o1);
        *(unsigned*)(attLo + (size_t)r0 * II + c) = pack2h(o0 - t0, o1 - t1);
        *(unsigned*)(attHi + (size_t)r1 * II + c) = pack2h(o2, o3);
        *(unsigned*)(attLo + (size_t)r1 * II + c) = pack2h(o2 - t2, o3 - t3);
    }
}

// ---------------- host orchestration ----------------
#define SMEM64D ((3 * (2 * 64 * AST + GBK * BST)) * 2)
#define SMEM64S ((3 * (1 * 64 * AST + GBK * BST)) * 2)

extern "C" void kernel_launch(void* const* d_in, const int* in_sizes, int n_in,
                              void* d_out, int out_size)
{
    (void)in_sizes; (void)n_in; (void)out_size;
    const float* x        = (const float*)d_in[0];
    const int*   mask     = (const int*)  d_in[1];
    const float* latents  = (const float*)d_in[2];
    const float* ln_m_w   = (const float*)d_in[3];
    const float* ln_m_b   = (const float*)d_in[4];
    const float* ln_l_w   = (const float*)d_in[5];
    const float* ln_l_b   = (const float*)d_in[6];
    const float* Wq       = (const float*)d_in[7];
    const float* Wkv      = (const float*)d_in[8];
    const float* Wo       = (const float*)d_in[9];
    const float* ff_ln_w  = (const float*)d_in[10];
    const float* ff_ln_b  = (const float*)d_in[11];
    const float* W1       = (const float*)d_in[12];
    const float* W2       = (const float*)d_in[13];
    const float* norm_w   = (const float*)d_in[14];
    const float* norm_b   = (const float*)d_in[15];
    float* out = (float*)d_out;

    fp16 *xh, *lnlh, *lnfh, *lnfl, *atth, *attl, *hfh, *hfl;
    fp16 *cmbh, *wkvph, *woh, *w1h, *w2h, *qb, *kb, *vb;
    float *lat, *biaskv;
    int *idxmap, *counts;
    cudaGetSymbolAddress((void**)&xh, g_xh);
    cudaGetSymbolAddress((void**)&lnlh, g_lnlh);
    cudaGetSymbolAddress((void**)&lnfh, g_lnfh); cudaGetSymbolAddress((void**)&lnfl, g_lnfl);
    cudaGetSymbolAddress((void**)&atth, g_atth); cudaGetSymbolAddress((void**)&attl, g_attl);
    cudaGetSymbolAddress((void**)&hfh, g_hfh);   cudaGetSymbolAddress((void**)&hfl, g_hfl);
    cudaGetSymbolAddress((void**)&cmbh, g_cmbh);
    cudaGetSymbolAddress((void**)&wkvph, g_wkvph);
    cudaGetSymbolAddress((void**)&woh, g_woh);
    cudaGetSymbolAddress((void**)&w1h, g_w1h);
    cudaGetSymbolAddress((void**)&w2h, g_w2h);
    cudaGetSymbolAddress((void**)&lat, g_lat);
    cudaGetSymbolAddress((void**)&qb, g_q);
    cudaGetSymbolAddress((void**)&kb, g_k);
    cudaGetSymbolAddress((void**)&vb, g_v);
    cudaGetSymbolAddress((void**)&biaskv, g_biaskv);
    cudaGetSymbolAddress((void**)&idxmap, g_idxmap);
    cudaGetSymbolAddress((void**)&counts, g_counts);

    cudaFuncSetAttribute((const void*)gemm_kv256,          cudaFuncAttributeMaxDynamicSharedMemorySize, SMEMKV);
    cudaFuncSetAttribute((const void*)gemm_fp16<64,true>,  cudaFuncAttributeMaxDynamicSharedMemorySize, SMEM64D);
    cudaFuncSetAttribute((const void*)gemm_fp16<64,false>, cudaFuncAttributeMaxDynamicSharedMemorySize, SMEM64S);

    cudaStream_t s2;
    cudaStreamCreateWithFlags(&s2, cudaStreamNonBlocking);
    cudaEvent_t evFork, evKV[NDEPTH];
    cudaEventCreateWithFlags(&evFork, cudaEventDisableTiming);
    for (int i = 0; i < NDEPTH; i++)
        cudaEventCreateWithFlags(&evKV[i], cudaEventDisableTiming);

    // ---- prologue: compaction, xhat, lat, ALL weight prep ----
    scan_mask_kernel<<<BB, 1024>>>(mask, idxmap, counts);
    ln_gather_kernel<<<BB * NN, 256>>>(x, idxmap, counts, xh);
    init_lat_kernel<<<BB * LQ * DD / 256, 256>>>(latents, lat);

    split_wkv_all_kernel<<<dim3(1024, NDEPTH), 256>>>(Wkv, ln_m_w, wkvph, cmbh);
    split_all_kernel<<<dim3(512, NDEPTH), 256>>>(Wq, cmbh, 9, NQKV, 0,
                                                 (size_t)DD * II, (size_t)DD * NQKV);
    split_all_kernel<<<dim3(512, NDEPTH), 256>>>(Wo, woh, 10, DD, 0,
                                                 (size_t)II * DD, (size_t)II * DD);
    split_all_kernel<<<dim3(4096, NDEPTH), 256>>>(W1, w1h, 12, FFD, 0,
                                                  (size_t)DD * FFD, (size_t)DD * FFD);
    split_all_kernel<<<dim3(4096, NDEPTH), 256>>>(W2, w2h, 10, DD, 0,
                                                  (size_t)FFD * DD, (size_t)FFD * DD);
    bias_kv_all_kernel<<<dim3(128, NDEPTH), 256>>>(Wkv, ln_m_b, biaskv);

    // ---- fork: six kv-x GEMMs on side stream (single A plane) ----
    cudaEventRecord(evFork, 0);
    cudaStreamWaitEvent(s2, evFork, 0);
    for (int i = 0; i < NDEPTH; i++) {
        gemm_kv256<<<dim3(2 * II / 256, BB * NN / 128), 512, SMEMKV, s2>>>(
            xh, wkvph + (size_t)i * DD * 2 * II,
            biaskv + i * 2 * II, kb + (size_t)i * KVSZ, vb + (size_t)i * KVSZ, counts);
        cudaEventRecord(evKV[i], s2);
    }

    // ---- main loop: lat path ----
    for (int i = 0; i < NDEPTH; i++) {
        fp16* kb_i = kb + (size_t)i * KVSZ;
        fp16* vb_i = vb + (size_t)i * KVSZ;

        ln_split_kernel<<<BB * LQ, 256>>>(lat, lnlh, nullptr, ln_l_w + i * DD, ln_l_b + i * DD);

        gemm_fp16<64,false><<<dim3(NQKV / 128, BB * LQ / 64), 256, SMEM64S>>>(
            lnlh, nullptr, cmbh + (size_t)i * DD * NQKV,
            nullptr, BB * LQ, NQKV, DD, EPI_QKV,
            kb_i, vb_i, LQ, counts, qb, nullptr);

        cudaStreamWaitEvent(0, evKV[i], 0);
        attn_mma_kernel<<<BB * HH, 128>>>(qb, kb_i, vb_i, counts, atth, attl);

        gemm_fp16<64,true><<<dim3(DD / 128, BB * LQ / 64), 256, SMEM64D>>>(
            atth, attl, woh + (size_t)i * II * DD,
            lat, BB * LQ, DD, II, EPI_ADD,
            nullptr, nullptr, 0, counts, nullptr, nullptr);

        ln_split_kernel<<<BB * LQ, 256>>>(lat, lnfh, lnfl, ff_ln_w + i * DD, ff_ln_b + i * DD);
        gemm_fp16<64,true><<<dim3(FFD / 128, BB * LQ / 64), 256, SMEM64D>>>(
            lnfh, lnfl, w1h + (size_t)i * DD * FFD,
            nullptr, BB * LQ, FFD, DD, EPI_GELU,
            nullptr, nullptr, 0, counts, hfh, hfl);
        gemm_fp16<64,true><<<dim3(DD / 128, BB * LQ / 64), 256, SMEM64D>>>(
            hfh, hfl, w2h + (size_t)i * FFD * DD,
            lat, BB * LQ, DD, FFD, EPI_ADD,
            nullptr, nullptr, 0, counts, nullptr, nullptr);
    }

    ln_kernel<<<BB * LQ, 256>>>(lat, out, norm_w, norm_b);
}

// round 16
// speedup vs baseline: 5.0418x; 1.1581x over previous
#include <cuda_runtime.h>
#include <cuda_fp16.h>
#include <stdint.h>
#include <math.h>

// ---------------- problem constants ----------------
#define BB   16
#define NN   2048
#define DD   1024
#define HH   8
#define DHD  64
#define II   512           // H*DH
#define LQ   64
#define SSQ  2112          // N + L
#define NDEPTH 6
#define FFD  4096
#define NQKV 1536          // II + 2*II

#define KVSZ ((size_t)BB * HH * SSQ * DHD)

typedef __half fp16;

// ---------------- scratch ----------------
__device__ fp16 g_xh[(size_t)BB * NN * DD];     // compacted xhat
__device__ fp16 g_lnlh[BB * LQ * DD];
__device__ fp16 g_lnfh[BB * LQ * DD];
__device__ fp16 g_atth[BB * LQ * II];
__device__ fp16 g_hfh [BB * LQ * FFD];
// per-layer weight planes
__device__ fp16 g_cmbh[(size_t)NDEPTH * DD * NQKV];
__device__ fp16 g_wkvph[(size_t)NDEPTH * DD * 2 * II];
__device__ fp16 g_woh [(size_t)NDEPTH * II * DD];
__device__ fp16 g_w1h [(size_t)NDEPTH * DD * FFD];
__device__ fp16 g_w2h [(size_t)NDEPTH * FFD * DD];
__device__ float g_biaskv[NDEPTH * 2 * II];
__device__ float g_lat[BB * LQ * DD];
__device__ fp16  g_q  [BB * LQ * II];
__device__ fp16  g_k  [(size_t)NDEPTH * KVSZ];
__device__ fp16  g_v  [(size_t)NDEPTH * KVSZ];
__device__ int   g_idxmap[BB * NN];
__device__ int   g_counts[BB];

// ---------------- helpers ----------------
__device__ __forceinline__ unsigned pack2h(float x, float y)
{
    return (unsigned)__half_as_ushort(__float2half_rn(x))
         | ((unsigned)__half_as_ushort(__float2half_rn(y)) << 16);
}
__device__ __forceinline__ uint2 hi4h(float4 v)
{
    return make_uint2(pack2h(v.x, v.y), pack2h(v.z, v.w));
}

// ---------------- mask compaction: per-batch scan ----------------
__global__ __launch_bounds__(1024) void scan_mask_kernel(const int* __restrict__ mask,
                                                         int* __restrict__ idxmap,
                                                         int* __restrict__ counts)
{
    __shared__ int sh[1024];
    int b = blockIdx.x;
    int t = threadIdx.x;
    int v0 = (mask[b * NN + 2 * t]     == 0) ? 1 : 0;
    int v1 = (mask[b * NN + 2 * t + 1] == 0) ? 1 : 0;
    sh[t] = v0 + v1;
    __syncthreads();
    for (int off = 1; off < 1024; off <<= 1) {
        int x = 0;
        if (t >= off) x = sh[t - off];
        __syncthreads();
        if (t >= off) sh[t] += x;
        __syncthreads();
    }
    int incl = sh[t];
    int excl = incl - v0 - v1;
    if (v0) idxmap[b * NN + excl] = 2 * t;
    if (v1) idxmap[b * NN + excl + v0] = 2 * t + 1;
    if (t == 1023) counts[b] = incl;
}

// ---------------- LayerNorm (fp32 out, final layer) ----------------
__global__ __launch_bounds__(256) void ln_kernel(const float* __restrict__ in,
                                                 float* __restrict__ out,
                                                 const float* __restrict__ w,
                                                 const float* __restrict__ b)
{
    int row = blockIdx.x;
    int tid = threadIdx.x;
    const float4 xv = *(const float4*)(in + (size_t)row * DD + tid * 4);
    float s  = xv.x + xv.y + xv.z + xv.w;
    float ss = xv.x * xv.x + xv.y * xv.y + xv.z * xv.z + xv.w * xv.w;
    #pragma unroll
    for (int o = 16; o; o >>= 1) {
        s  += __shfl_xor_sync(0xffffffffu, s,  o);
        ss += __shfl_xor_sync(0xffffffffu, ss, o);
    }
    __shared__ float red[16];
    int wid = tid >> 5;
    if ((tid & 31) == 0) { red[wid] = s; red[wid + 8] = ss; }
    __syncthreads();
    s = 0.f; ss = 0.f;
    #pragma unroll
    for (int i = 0; i < 8; i++) { s += red[i]; ss += red[i + 8]; }
    float mu   = s * (1.f / DD);
    float var  = ss * (1.f / DD) - mu * mu;
    float rstd = rsqrtf(var + 1e-5f);
    float4 o4;
    o4.x = (xv.x - mu) * rstd; o4.y = (xv.y - mu) * rstd;
    o4.z = (xv.z - mu) * rstd; o4.w = (xv.w - mu) * rstd;
    const float4 wv = *(const float4*)(w + tid * 4);
    const float4 bv = *(const float4*)(b + tid * 4);
    o4.x = o4.x * wv.x + bv.x; o4.y = o4.y * wv.y + bv.y;
    o4.z = o4.z * wv.z + bv.z; o4.w = o4.w * wv.w + bv.w;
    *(float4*)(out + (size_t)row * DD + tid * 4) = o4;
}

// ---------------- LayerNorm -> fp16 ----------------
__global__ __launch_bounds__(256) void ln_h_kernel(const float* __restrict__ in,
                                                   fp16* __restrict__ hi,
                                                   const float* __restrict__ w,
                                                   const float* __restrict__ b)
{
    int row = blockIdx.x;
    int tid = threadIdx.x;
    const float4 xv = *(const float4*)(in + (size_t)row * DD + tid * 4);
    float s  = xv.x + xv.y + xv.z + xv.w;
    float ss = xv.x * xv.x + xv.y * xv.y + xv.z * xv.z + xv.w * xv.w;
    #pragma unroll
    for (int o = 16; o; o >>= 1) {
        s  += __shfl_xor_sync(0xffffffffu, s,  o);
        ss += __shfl_xor_sync(0xffffffffu, ss, o);
    }
    __shared__ float red[16];
    int wid = tid >> 5;
    if ((tid & 31) == 0) { red[wid] = s; red[wid + 8] = ss; }
    __syncthreads();
    s = 0.f; ss = 0.f;
    #pragma unroll
    for (int i = 0; i < 8; i++) { s += red[i]; ss += red[i + 8]; }
    float mu   = s * (1.f / DD);
    float var  = ss * (1.f / DD) - mu * mu;
    float rstd = rsqrtf(var + 1e-5f);
    float4 o4;
    o4.x = (xv.x - mu) * rstd; o4.y = (xv.y - mu) * rstd;
    o4.z = (xv.z - mu) * rstd; o4.w = (xv.w - mu) * rstd;
    const float4 wv = *(const float4*)(w + tid * 4);
    const float4 bv = *(const float4*)(b + tid * 4);
    o4.x = o4.x * wv.x + bv.x; o4.y = o4.y * wv.y + bv.y;
    o4.z = o4.z * wv.z + bv.z; o4.w = o4.w * wv.w + bv.w;
    *(uint2*)(hi + (size_t)row * DD + tid * 4) = hi4h(o4);
}

// ---------------- compacted LN of x -> fp16 ----------------
__global__ __launch_bounds__(256) void ln_gather_kernel(const float* __restrict__ in,
                                                        const int* __restrict__ idxmap,
                                                        const int* __restrict__ counts,
                                                        fp16* __restrict__ hi)
{
    int row = blockIdx.x;
    int b   = row >> 11;
    int j   = row & (NN - 1);
    if (j >= counts[b]) return;
    int src = idxmap[row];
    int tid = threadIdx.x;
    const float4 xv = *(const float4*)(in + ((size_t)b * NN + src) * DD + tid * 4);
    float s  = xv.x + xv.y + xv.z + xv.w;
    float ss = xv.x * xv.x + xv.y * xv.y + xv.z * xv.z + xv.w * xv.w;
    #pragma unroll
    for (int o = 16; o; o >>= 1) {
        s  += __shfl_xor_sync(0xffffffffu, s,  o);
        ss += __shfl_xor_sync(0xffffffffu, ss, o);
    }
    __shared__ float red[16];
    int wid = tid >> 5;
    if ((tid & 31) == 0) { red[wid] = s; red[wid + 8] = ss; }
    __syncthreads();
    s = 0.f; ss = 0.f;
    #pragma unroll
    for (int i = 0; i < 8; i++) { s += red[i]; ss += red[i + 8]; }
    float mu   = s * (1.f / DD);
    float var  = ss * (1.f / DD) - mu * mu;
    float rstd = rsqrtf(var + 1e-5f);
    float4 o4;
    o4.x = (xv.x - mu) * rstd; o4.y = (xv.y - mu) * rstd;
    o4.z = (xv.z - mu) * rstd; o4.w = (xv.w - mu) * rstd;
    *(uint2*)(hi + (size_t)row * DD + tid * 4) = hi4h(o4);
}

// ---------------- all-layer generic weight split ----------
__global__ __launch_bounds__(256) void split_all_kernel(const float* __restrict__ in,
                                                        fp16* __restrict__ hi,
                                                        int srcColsLog2, int dstStride, int dstOff,
                                                        size_t srcLS, size_t dstLS)
{
    int layer = blockIdx.y;
    int idx = (blockIdx.x * 256 + threadIdx.x) * 4;
    float4 v = *(const float4*)(in + layer * srcLS + idx);
    int row = idx >> srcColsLog2;
    int col = idx & ((1 << srcColsLog2) - 1);
    size_t d = layer * dstLS + (size_t)row * dstStride + dstOff + col;
    *(uint2*)(hi + d) = hi4h(v);
}

// ---------------- all-layer Wkv split ----------------
__global__ __launch_bounds__(256) void split_wkv_all_kernel(const float* __restrict__ Wkv,
                                                            const float* __restrict__ lwAll,
                                                            fp16* __restrict__ fh,
                                                            fp16* __restrict__ ch)
{
    int layer = blockIdx.y;
    int idx = (blockIdx.x * 256 + threadIdx.x) * 4;
    float4 v = *(const float4*)(Wkv + (size_t)layer * DD * 1024 + idx);
    int row = idx >> 10;
    int col = idx & 1023;
    size_t d = (size_t)layer * DD * NQKV + (size_t)row * NQKV + II + col;
    *(uint2*)(ch + d) = hi4h(v);
    float sc = lwAll[layer * DD + row];
    v.x *= sc; v.y *= sc; v.z *= sc; v.w *= sc;
    size_t f = (size_t)layer * DD * 1024 + idx;
    *(uint2*)(fh + f) = hi4h(v);
}

// ---------------- lat init ----------------
__global__ void init_lat_kernel(const float* __restrict__ latents, float* __restrict__ lat)
{
    int idx = blockIdx.x * 256 + threadIdx.x;
    lat[idx] = latents[idx & (LQ * DD - 1)];
}

// ---------------- all-layer biaskv ----------------
__global__ __launch_bounds__(256) void bias_kv_all_kernel(const float* __restrict__ Wkv,
                                                          const float* __restrict__ lnbAll,
                                                          float* __restrict__ bias)
{
    int layer = blockIdx.y;
    const float* W = Wkv + (size_t)layer * DD * 1024;
    const float* lnb = lnbAll + layer * DD;
    int j  = blockIdx.x * 8 + (threadIdx.x & 7);
    int dc = threadIdx.x >> 3;
    float a = 0.f;
    int d0 = dc * 32;
    #pragma unroll 8
    for (int d = d0; d < d0 + 32; d++) a += lnb[d] * W[(size_t)d * 1024 + j];
    __shared__ float red[32][8];
    red[dc][threadIdx.x & 7] = a;
    __syncthreads();
    if (threadIdx.x < 8) {
        float s = 0.f;
        #pragma unroll
        for (int i = 0; i < 32; i++) s += red[i][threadIdx.x];
        bias[layer * 1024 + blockIdx.x * 8 + threadIdx.x] = s;
    }
}

// ================= fp16 mma.sync GEMM =================
enum { EPI_NONE = 0, EPI_ADD = 1, EPI_GELU = 2, EPI_KV = 3, EPI_QKV = 4 };

#define GBK 32
#define AST 40
#define BST 136
#define BST2 264

__device__ __forceinline__ void mma16816h(float* d, const unsigned* a, const unsigned* b)
{
    asm volatile(
        "mma.sync.aligned.m16n8k16.row.col.f32.f16.f16.f32 "
        "{%0,%1,%2,%3}, {%4,%5,%6,%7}, {%8,%9}, {%0,%1,%2,%3};\n"
        : "+f"(d[0]), "+f"(d[1]), "+f"(d[2]), "+f"(d[3])
        : "r"(a[0]), "r"(a[1]), "r"(a[2]), "r"(a[3]), "r"(b[0]), "r"(b[1]));
}
__device__ __forceinline__ void mma16816h2(float* d, const unsigned* a, unsigned b0, unsigned b1)
{
    asm volatile(
        "mma.sync.aligned.m16n8k16.row.col.f32.f16.f16.f32 "
        "{%0,%1,%2,%3}, {%4,%5,%6,%7}, {%8,%9}, {%0,%1,%2,%3};\n"
        : "+f"(d[0]), "+f"(d[1]), "+f"(d[2]), "+f"(d[3])
        : "r"(a[0]), "r"(a[1]), "r"(a[2]), "r"(a[3]), "r"(b0), "r"(b1));
}
__device__ __forceinline__ void ldsm4(unsigned* r, unsigned addr)
{
    asm volatile("ldmatrix.sync.aligned.m8n8.x4.shared.b16 {%0,%1,%2,%3}, [%4];\n"
                 : "=r"(r[0]), "=r"(r[1]), "=r"(r[2]), "=r"(r[3]) : "r"(addr));
}
__device__ __forceinline__ void ldsm4t(unsigned* r, unsigned addr)
{
    asm volatile("ldmatrix.sync.aligned.m8n8.x4.trans.shared.b16 {%0,%1,%2,%3}, [%4];\n"
                 : "=r"(r[0]), "=r"(r[1]), "=r"(r[2]), "=r"(r[3]) : "r"(addr));
}
__device__ __forceinline__ void cpasync16(unsigned s, const void* g)
{
    asm volatile("cp.async.cg.shared.global [%0], [%1], 16;\n" :: "r"(s), "l"(g));
}
#define CP_COMMIT() asm volatile("cp.async.commit_group;\n")
#define CP_WAIT1()  asm volatile("cp.async.wait_group 1;\n")

// ---------- small-GEMM variant: 64 x 128 tiles, 256 threads, single A plane ----------
__global__ __launch_bounds__(256, 2) void gemm_fp16(
    const fp16* __restrict__ Ahi,
    const fp16* __restrict__ Bhi,
    float* __restrict__ C, int M, int N, int K, int epi,
    fp16* __restrict__ Kout, fp16* __restrict__ Vout, int rowsPerB,
    const int* __restrict__ cnts,
    fp16* __restrict__ OutHi)
{
    constexpr int TM     = 64;
    constexpr int WM16   = TM / 32;
    constexpr int A_EL   = TM * AST;
    constexpr int B_EL   = GBK * BST;
    constexpr int STAGE  = A_EL + B_EL;
    extern __shared__ __align__(16) fp16 smg[];
    unsigned base = (unsigned)__cvta_generic_to_shared(smg);

    int row0 = blockIdx.y * TM;
    int col0 = blockIdx.x << 7;

    int tid  = threadIdx.x;
    int lane = tid & 31;
    int warp = tid >> 5;
    int wm = warp & 1, wn = warp >> 1;
    int lr = (lane & 7) + (((lane >> 3) & 1) << 3);
    int lc = (lane >> 4) << 3;

    float acc[WM16][4][4];
    #pragma unroll
    for (int i = 0; i < WM16; i++)
        #pragma unroll
        for (int j = 0; j < 4; j++)
            #pragma unroll
            for (int t = 0; t < 4; t++) acc[i][j][t] = 0.f;

    auto load_stage = [&](int kt, int buf) {
        unsigned sb = base + (unsigned)buf * STAGE * 2;
        {
            int r = tid >> 2, c16 = tid & 3;
            cpasync16(sb + (unsigned)(r * AST + c16 * 8) * 2,
                      Ahi + (size_t)(row0 + r) * K + kt + c16 * 8);
        }
        {
            unsigned so = sb + (unsigned)A_EL * 2;
            #pragma unroll
            for (int i = 0; i < 2; i++) {
                int chunk = tid + i * 256;
                int r = chunk >> 4, cc = (chunk & 15) * 8;
                cpasync16(so + (unsigned)(r * BST + cc) * 2,
                          Bhi + (size_t)(kt + r) * N + col0 + cc);
            }
        }
    };

    int NK = K / GBK;
    load_stage(0, 0);   CP_COMMIT();
    load_stage(GBK, 1); CP_COMMIT();

    for (int it = 0; it < NK; it++) {
        CP_WAIT1();
        __syncthreads();
        int buf = it % 3;
        unsigned sb  = base + (unsigned)buf * STAGE * 2;
        unsigned aHi = sb;
        unsigned bHi = sb + (unsigned)A_EL * 2;

        if (it + 2 < NK) load_stage((it + 2) * GBK, (it + 2) % 3);
        CP_COMMIT();

        #pragma unroll
        for (int k16 = 0; k16 < GBK; k16 += 16) {
            unsigned bh[2][4];
            #pragma unroll
            for (int ni = 0; ni < 2; ni++) {
                unsigned off = (unsigned)((k16 + lr) * BST + wn * 32 + ni * 16 + lc) * 2;
                ldsm4t(bh[ni], bHi + off);
            }
            #pragma unroll
            for (int mi = 0; mi < WM16; mi++) {
                unsigned ah[4];
                unsigned off = (unsigned)((wm * (TM / 2) + mi * 16 + lr) * AST + k16 + lc) * 2;
                ldsm4(ah, aHi + off);
                #pragma unroll
                for (int nj = 0; nj < 4; nj++) {
                    int ni = nj >> 1, p = nj & 1;
                    mma16816h(acc[mi][nj], ah, &bh[ni][2 * p]);
                }
            }
        }
    }

    int rbase = row0 + wm * (TM / 2) + (lane >> 2);
    int cbase = col0 + wn * 32 + (lane & 3) * 2;
    #pragma unroll
    for (int mi = 0; mi < WM16; mi++) {
        #pragma unroll
        for (int nj = 0; nj < 4; nj++) {
            #pragma unroll
            for (int half = 0; half < 2; half++) {
                int r = rbase + mi * 16 + half * 8;
                int c = cbase + nj * 8;
                float v0 = acc[mi][nj][half * 2 + 0];
                float v1 = acc[mi][nj][half * 2 + 1];
                if (epi == EPI_QKV) {
                    if (c < II) {
                        *(unsigned*)(OutHi + (size_t)r * II + c) = pack2h(v0, v1);
                    } else {
                        int c2 = c - II;
                        int bb = r / rowsPerB;
                        int s  = cnts[bb] + (r - bb * rowsPerB);
                        fp16* dst;
                        if (c2 < II)
                            dst = Kout + (((size_t)bb * HH + (c2 >> 6)) * SSQ + s) * DHD + (c2 & 63);
                        else
                            dst = Vout + (((size_t)bb * HH + ((c2 - II) >> 6)) * SSQ + s) * DHD + ((c2 - II) & 63);
                        *(unsigned*)dst = pack2h(v0, v1);
                    }
                } else if (epi == EPI_GELU) {
                    float h0 = 0.5f * v0 * (1.f + erff(v0 * 0.70710678118654752f));
                    float h1 = 0.5f * v1 * (1.f + erff(v1 * 0.70710678118654752f));
                    *(unsigned*)(OutHi + (size_t)r * N + c) = pack2h(h0, h1);
                } else {
                    float* dst = C + (size_t)r * N + c;
                    if (epi == EPI_ADD) { v0 += dst[0]; v1 += dst[1]; }
                    dst[0] = v0; dst[1] = v1;
                }
            }
        }
    }
}

// ---------- kv-x GEMM: 128 x 256 tile, 512 threads, single A plane ----------
#define KV_A_EL (128 * AST)
#define KV_B_EL (GBK * BST2)
#define KV_STAGE (KV_A_EL + KV_B_EL)
#define SMEMKV (3 * KV_STAGE * 2)

__global__ __launch_bounds__(512, 1) void gemm_kv256(
    const fp16* __restrict__ Ahi,
    const fp16* __restrict__ Bhi,
    const float* __restrict__ bias,
    fp16* __restrict__ Kout, fp16* __restrict__ Vout,
    const int* __restrict__ cnts)
{
    extern __shared__ __align__(16) fp16 smg[];
    unsigned base = (unsigned)__cvta_generic_to_shared(smg);

    int row0 = blockIdx.y * 128;
    int col0 = blockIdx.x * 256;

    int bb = row0 >> 11;
    int cnt0 = cnts[bb];
    if ((row0 & (NN - 1)) >= cnt0) return;

    int tid  = threadIdx.x;
    int lane = tid & 31;
    int warp = tid >> 5;
    int wm = warp & 3, wn = warp >> 2;
    int lr = (lane & 7) + (((lane >> 3) & 1) << 3);
    int lc = (lane >> 4) << 3;

    float acc[2][8][4];
    #pragma unroll
    for (int i = 0; i < 2; i++)
        #pragma unroll
        for (int j = 0; j < 8; j++)
            #pragma unroll
            for (int t = 0; t < 4; t++) acc[i][j][t] = 0.f;

    auto load_stage = [&](int kt, int buf) {
        unsigned sb = base + (unsigned)buf * KV_STAGE * 2;
        {
            int r = tid >> 2, c16 = tid & 3;
            cpasync16(sb + (unsigned)(r * AST + c16 * 8) * 2,
                      Ahi + (size_t)(row0 + r) * DD + kt + c16 * 8);
        }
        {
            unsigned so = sb + (unsigned)KV_A_EL * 2;
            #pragma unroll
            for (int i = 0; i < 2; i++) {
                int chunk = tid + i * 512;
                int r = chunk >> 5, cc = (chunk & 31) * 8;
                cpasync16(so + (unsigned)(r * BST2 + cc) * 2,
                          Bhi + (size_t)(kt + r) * 1024 + col0 + cc);
            }
        }
    };

    const int NK = DD / GBK;
    load_stage(0, 0);   CP_COMMIT();
    load_stage(GBK, 1); CP_COMMIT();

    for (int it = 0; it < NK; it++) {
        CP_WAIT1();
        __syncthreads();
        int buf = it % 3;
        unsigned sb  = base + (unsigned)buf * KV_STAGE * 2;
        unsigned aHi = sb;
        unsigned bHi = sb + (unsigned)KV_A_EL * 2;

        if (it + 2 < NK) load_stage((it + 2) * GBK, (it + 2) % 3);
        CP_COMMIT();

        #pragma unroll
        for (int k16 = 0; k16 < GBK; k16 += 16) {
            unsigned bh[4][4];
            #pragma unroll
            for (int ni = 0; ni < 4; ni++) {
                unsigned off = (unsigned)((k16 + lr) * BST2 + wn * 64 + ni * 16 + lc) * 2;
                ldsm4t(bh[ni], bHi + off);
            }
            #pragma unroll
            for (int mi = 0; mi < 2; mi++) {
                unsigned ah[4];
                unsigned off = (unsigned)((wm * 32 + mi * 16 + lr) * AST + k16 + lc) * 2;
                ldsm4(ah, aHi + off);
                #pragma unroll
                for (int nj = 0; nj < 8; nj++) {
                    int ni = nj >> 1, p = nj & 1;
                    mma16816h(acc[mi][nj], ah, &bh[ni][2 * p]);
                }
            }
        }
    }

    int rbase = row0 + wm * 32 + (lane >> 2);
    int cbase = col0 + wn * 64 + (lane & 3) * 2;
    #pragma unroll
    for (int mi = 0; mi < 2; mi++) {
        #pragma unroll
        for (int nj = 0; nj < 8; nj++) {
            #pragma unroll
            for (int half = 0; half < 2; half++) {
                int r = rbase + mi * 16 + half * 8;
                int s = r & (NN - 1);
                if (s < cnt0) {
                    int c = cbase + nj * 8;
                    float v0 = acc[mi][nj][half * 2 + 0] + bias[c];
                    float v1 = acc[mi][nj][half * 2 + 1] + bias[c + 1];
                    fp16* dst;
                    if (c < II)
                        dst = Kout + (((size_t)bb * HH + (c >> 6)) * SSQ + s) * DHD + (c & 63);
                    else {
                        int c2 = c - II;
                        dst = Vout + (((size_t)bb * HH + (c2 >> 6)) * SSQ + s) * DHD + (c2 & 63);
                    }
                    *(unsigned*)dst = pack2h(v0, v1);
                }
            }
        }
    }
}

// ---------------- tensor-core flash attention ----------------
#define ATS 72

__global__ __launch_bounds__(128) void attn_mma_kernel(
    const fp16* __restrict__ q, const fp16* __restrict__ kg, const fp16* __restrict__ vg,
    const int* __restrict__ counts, fp16* __restrict__ attHi)
{
    __shared__ __align__(16) fp16 qs[64 * ATS];
    __shared__ __align__(16) fp16 ks[64 * ATS];
    __shared__ __align__(16) fp16 vs[64 * ATS];

    int bh = blockIdx.x, b = bh >> 3;
    int tid = threadIdx.x, lane = tid & 31, warp = tid >> 5;
    int lr = (lane & 7) + (((lane >> 3) & 1) << 3);
    int lc = (lane >> 4) << 3;

    unsigned qsb = (unsigned)__cvta_generic_to_shared(qs);
    unsigned ksb = (unsigned)__cvta_generic_to_shared(ks);
    unsigned vsb = (unsigned)__cvta_generic_to_shared(vs);

    int Sv = counts[b] + LQ;
    int nT = (Sv + 63) >> 6;

    {
        const fp16* qgp = q + (size_t)(b * LQ) * II + (bh & 7) * DHD;
        #pragma unroll
        for (int i = 0; i < 4; i++) {
            int ch = tid + i * 128;
            int r = ch >> 3, d8 = (ch & 7) * 8;
            *(uint4*)&qs[r * ATS + d8] = *(const uint4*)&qgp[(size_t)r * II + d8];
        }
    }

    const fp16* kb = kg + (size_t)bh * SSQ * DHD;
    const fp16* vb = vg + (size_t)bh * SSQ * DHD;

    float accO[8][4];
    #pragma unroll
    for (int n = 0; n < 8; n++)
        #pragma unroll
        for (int c = 0; c < 4; c++) accO[n][c] = 0.f;
    float m0 = -1e30f, m1 = -1e30f, l0 = 0.f, l1 = 0.f;

    for (int t = 0; t < nT; t++) {
        int s0 = t * 64;
        __syncthreads();
        #pragma unroll
        for (int i = 0; i < 4; i++) {
            int ch = tid + i * 128;
            int s = ch >> 3, d8 = (ch & 7) * 8;
            int sg = s0 + s;
            uint4 kk, vv;
            if (sg < Sv) {
                kk = *(const uint4*)&kb[(size_t)sg * DHD + d8];
                vv = *(const uint4*)&vb[(size_t)sg * DHD + d8];
            } else {
                kk = make_uint4(0, 0, 0, 0);
                vv = make_uint4(0, 0, 0, 0);
            }
            *(uint4*)&ks[s * ATS + d8] = kk;
            *(uint4*)&vs[s * ATS + d8] = vv;
        }
        __syncthreads();

        float accS[8][4];
        #pragma unroll
        for (int n = 0; n < 8; n++)
            #pragma unroll
            for (int c = 0; c < 4; c++) accS[n][c] = 0.f;

        #pragma unroll
        for (int k16 = 0; k16 < 64; k16 += 16) {
            unsigned aq[4];
            ldsm4(aq, qsb + (unsigned)((warp * 16 + lr) * ATS + k16 + lc) * 2);
            #pragma unroll
            for (int ni = 0; ni < 4; ni++) {
                unsigned bk[4];
                ldsm4(bk, ksb + (unsigned)((ni * 16 + lr) * ATS + k16 + lc) * 2);
                mma16816h2(accS[2 * ni + 0], aq, bk[0], bk[2]);
                mma16816h2(accS[2 * ni + 1], aq, bk[1], bk[3]);
            }
        }

        float mx0 = -1e30f, mx1 = -1e30f;
        #pragma unroll
        for (int n = 0; n < 8; n++) {
            int colb = s0 + n * 8 + (lane & 3) * 2;
            #pragma unroll
            for (int c = 0; c < 2; c++) {
                bool ok = (colb + c) < Sv;
                accS[n][c]     = ok ? accS[n][c]     * 0.125f : -1e30f;
                accS[n][c + 2] = ok ? accS[n][c + 2] * 0.125f : -1e30f;
                mx0 = fmaxf(mx0, accS[n][c]);
                mx1 = fmaxf(mx1, accS[n][c + 2]);
            }
        }
        mx0 = fmaxf(mx0, __shfl_xor_sync(0xffffffffu, mx0, 1));
        mx0 = fmaxf(mx0, __shfl_xor_sync(0xffffffffu, mx0, 2));
        mx1 = fmaxf(mx1, __shfl_xor_sync(0xffffffffu, mx1, 1));
        mx1 = fmaxf(mx1, __shfl_xor_sync(0xffffffffu, mx1, 2));

        float mn0 = fmaxf(m0, mx0), mn1 = fmaxf(m1, mx1);
        float cor0 = __expf(m0 - mn0), cor1 = __expf(m1 - mn1);
        float ps0 = 0.f, ps1 = 0.f;
        unsigned aP[4][4];
        #pragma unroll
        for (int n = 0; n < 8; n++) {
            float p0 = __expf(accS[n][0] - mn0);
            float p1 = __expf(accS[n][1] - mn0);
            float p2 = __expf(accS[n][2] - mn1);
            float p3 = __expf(accS[n][3] - mn1);
            ps0 += p0 + p1; ps1 += p2 + p3;
            int j = n >> 1;
            if ((n & 1) == 0) {
                aP[j][0] = pack2h(p0, p1);
                aP[j][1] = pack2h(p2, p3);
            } else {
                aP[j][2] = pack2h(p0, p1);
                aP[j][3] = pack2h(p2, p3);
            }
        }
        ps0 += __shfl_xor_sync(0xffffffffu, ps0, 1);
        ps0 += __shfl_xor_sync(0xffffffffu, ps0, 2);
        ps1 += __shfl_xor_sync(0xffffffffu, ps1, 1);
        ps1 += __shfl_xor_sync(0xffffffffu, ps1, 2);
        l0 = l0 * cor0 + ps0;
        l1 = l1 * cor1 + ps1;
        m0 = mn0; m1 = mn1;

        #pragma unroll
        for (int n = 0; n < 8; n++) {
            accO[n][0] *= cor0; accO[n][1] *= cor0;
            accO[n][2] *= cor1; accO[n][3] *= cor1;
        }

        #pragma unroll
        for (int j = 0; j < 4; j++) {
            #pragma unroll
            for (int ni = 0; ni < 4; ni++) {
                unsigned bv[4];
                ldsm4t(bv, vsb + (unsigned)((j * 16 + lr) * ATS + ni * 16 + lc) * 2);
                mma16816h(accO[2 * ni + 0], aP[j], &bv[0]);
                mma16816h(accO[2 * ni + 1], aP[j], &bv[2]);
            }
        }
    }

    float inv0 = 1.f / l0, inv1 = 1.f / l1;
    int r0 = b * LQ + warp * 16 + (lane >> 2);
    int r1 = r0 + 8;
    int cb = (bh & 7) * DHD + (lane & 3) * 2;
    #pragma unroll
    for (int n = 0; n < 8; n++) {
        int c = cb + n * 8;
        *(unsigned*)(attHi + (size_t)r0 * II + c) = pack2h(accO[n][0] * inv0, accO[n][1] * inv0);
        *(unsigned*)(attHi + (size_t)r1 * II + c) = pack2h(accO[n][2] * inv1, accO[n][3] * inv1);
    }
}

// ---------------- host orchestration ----------------
#define SMEM64 ((3 * (64 * AST + GBK * BST)) * 2)

extern "C" void kernel_launch(void* const* d_in, const int* in_sizes, int n_in,
                              void* d_out, int out_size)
{
    (void)in_sizes; (void)n_in; (void)out_size;
    const float* x        = (const float*)d_in[0];
    const int*   mask     = (const int*)  d_in[1];
    const float* latents  = (const float*)d_in[2];
    const float* ln_m_w   = (const float*)d_in[3];
    const float* ln_m_b   = (const float*)d_in[4];
    const float* ln_l_w   = (const float*)d_in[5];
    const float* ln_l_b   = (const float*)d_in[6];
    const float* Wq       = (const float*)d_in[7];
    const float* Wkv      = (const float*)d_in[8];
    const float* Wo       = (const float*)d_in[9];
    const float* ff_ln_w  = (const float*)d_in[10];
    const float* ff_ln_b  = (const float*)d_in[11];
    const float* W1       = (const float*)d_in[12];
    const float* W2       = (const float*)d_in[13];
    const float* norm_w   = (const float*)d_in[14];
    const float* norm_b   = (const float*)d_in[15];
    float* out = (float*)d_out;

    fp16 *xh, *lnlh, *lnfh, *atth, *hfh;
    fp16 *cmbh, *wkvph, *woh, *w1h, *w2h, *qb, *kb, *vb;
    float *lat, *biaskv;
    int *idxmap, *counts;
    cudaGetSymbolAddress((void**)&xh, g_xh);
    cudaGetSymbolAddress((void**)&lnlh, g_lnlh);
    cudaGetSymbolAddress((void**)&lnfh, g_lnfh);
    cudaGetSymbolAddress((void**)&atth, g_atth);
    cudaGetSymbolAddress((void**)&hfh, g_hfh);
    cudaGetSymbolAddress((void**)&cmbh, g_cmbh);
    cudaGetSymbolAddress((void**)&wkvph, g_wkvph);
    cudaGetSymbolAddress((void**)&woh, g_woh);
    cudaGetSymbolAddress((void**)&w1h, g_w1h);
    cudaGetSymbolAddress((void**)&w2h, g_w2h);
    cudaGetSymbolAddress((void**)&lat, g_lat);
    cudaGetSymbolAddress((void**)&qb, g_q);
    cudaGetSymbolAddress((void**)&kb, g_k);
    cudaGetSymbolAddress((void**)&vb, g_v);
    cudaGetSymbolAddress((void**)&biaskv, g_biaskv);
    cudaGetSymbolAddress((void**)&idxmap, g_idxmap);
    cudaGetSymbolAddress((void**)&counts, g_counts);

    cudaFuncSetAttribute((const void*)gemm_kv256, cudaFuncAttributeMaxDynamicSharedMemorySize, SMEMKV);
    cudaFuncSetAttribute((const void*)gemm_fp16,  cudaFuncAttributeMaxDynamicSharedMemorySize, SMEM64);

    cudaStream_t s2;
    cudaStreamCreateWithFlags(&s2, cudaStreamNonBlocking);
    cudaEvent_t evFork, evKV[NDEPTH];
    cudaEventCreateWithFlags(&evFork, cudaEventDisableTiming);
    for (int i = 0; i < NDEPTH; i++)
        cudaEventCreateWithFlags(&evKV[i], cudaEventDisableTiming);

    // ---- prologue: compaction, xhat, lat, ALL weight prep ----
    scan_mask_kernel<<<BB, 1024>>>(mask, idxmap, counts);
    ln_gather_kernel<<<BB * NN, 256>>>(x, idxmap, counts, xh);
    init_lat_kernel<<<BB * LQ * DD / 256, 256>>>(latents, lat);

    split_wkv_all_kernel<<<dim3(1024, NDEPTH), 256>>>(Wkv, ln_m_w, wkvph, cmbh);
    split_all_kernel<<<dim3(512, NDEPTH), 256>>>(Wq, cmbh, 9, NQKV, 0,
                                                 (size_t)DD * II, (size_t)DD * NQKV);
    split_all_kernel<<<dim3(512, NDEPTH), 256>>>(Wo, woh, 10, DD, 0,
                                                 (size_t)II * DD, (size_t)II * DD);
    split_all_kernel<<<dim3(4096, NDEPTH), 256>>>(W1, w1h, 12, FFD, 0,
                                                  (size_t)DD * FFD, (size_t)DD * FFD);
    split_all_kernel<<<dim3(4096, NDEPTH), 256>>>(W2, w2h, 10, DD, 0,
                                                  (size_t)FFD * DD, (size_t)FFD * DD);
    bias_kv_all_kernel<<<dim3(128, NDEPTH), 256>>>(Wkv, ln_m_b, biaskv);

    // ---- fork: six kv-x GEMMs on side stream ----
    cudaEventRecord(evFork, 0);
    cudaStreamWaitEvent(s2, evFork, 0);
    for (int i = 0; i < NDEPTH; i++) {
        gemm_kv256<<<dim3(2 * II / 256, BB * NN / 128), 512, SMEMKV, s2>>>(
            xh, wkvph + (size_t)i * DD * 2 * II,
            biaskv + i * 2 * II, kb + (size_t)i * KVSZ, vb + (size_t)i * KVSZ, counts);
        cudaEventRecord(evKV[i], s2);
    }

    // ---- main loop: lat path ----
    for (int i = 0; i < NDEPTH; i++) {
        fp16* kb_i = kb + (size_t)i * KVSZ;
        fp16* vb_i = vb + (size_t)i * KVSZ;

        ln_h_kernel<<<BB * LQ, 256>>>(lat, lnlh, ln_l_w + i * DD, ln_l_b + i * DD);

        gemm_fp16<<<dim3(NQKV / 128, BB * LQ / 64), 256, SMEM64>>>(
            lnlh, cmbh + (size_t)i * DD * NQKV,
            nullptr, BB * LQ, NQKV, DD, EPI_QKV,
            kb_i, vb_i, LQ, counts, qb);

        cudaStreamWaitEvent(0, evKV[i], 0);
        attn_mma_kernel<<<BB * HH, 128>>>(qb, kb_i, vb_i, counts, atth);

        gemm_fp16<<<dim3(DD / 128, BB * LQ / 64), 256, SMEM64>>>(
            atth, woh + (size_t)i * II * DD,
            lat, BB * LQ, DD, II, EPI_ADD,
            nullptr, nullptr, 0, counts, nullptr);

        ln_h_kernel<<<BB * LQ, 256>>>(lat, lnfh, ff_ln_w + i * DD, ff_ln_b + i * DD);
        gemm_fp16<<<dim3(FFD / 128, BB * LQ / 64), 256, SMEM64>>>(
            lnfh, w1h + (size_t)i * DD * FFD,
            nullptr, BB * LQ, FFD, DD, EPI_GELU,
            nullptr, nullptr, 0, counts, hfh);
        gemm_fp16<<<dim3(DD / 128, BB * LQ / 64), 256, SMEM64>>>(
            hfh, w2h + (size_t)i * FFD * DD,
            lat, BB * LQ, DD, FFD, EPI_ADD,
            nullptr, nullptr, 0, counts, nullptr);
    }

    ln_kernel<<<BB * LQ, 256>>>(lat, out, norm_w, norm_b);
}